// round 1
// baseline (speedup 1.0000x reference)
#include <cuda_runtime.h>
#include <cuda_bf16.h>
#include <math.h>

// Problem constants
#define BB 4
#define LL 1024
#define DD 512
#define HH 8
#define HD 64
#define QKVD 1536
#define ML (BB*LL)          // 4096 rows
#define KTOP 716            // int(1024*0.7)
#define THRESH 0.05f
#define SCALE 0.125f        // 64^-0.5
#define QB 4                // query rows per attention block
#define NEG_INF __int_as_float(0xff800000)

// Scratch (device globals; no allocations allowed)
__device__ float g_qkv[ML * QKVD];   // (B*L, 3*D)
__device__ float g_attn[ML * DD];    // attention output in (B,L,D) layout
__device__ float g_pw[BB * 3];       // pattern weights per batch

// ---------------------------------------------------------------------------
// Generic SGEMM: C[M,N] = A[M,K] @ B[N,K]^T (+ bias[n]).  64x64x16 tiles.
// ---------------------------------------------------------------------------
__global__ void gemm_nt(const float* __restrict__ A, const float* __restrict__ Bw,
                        const float* __restrict__ bias, float* __restrict__ C,
                        int M, int N, int K)
{
    __shared__ float As[16][65];
    __shared__ float Bs[16][65];
    int tid = threadIdx.x;
    int tx = tid & 15, ty = tid >> 4;
    int m0 = blockIdx.y * 64, n0 = blockIdx.x * 64;

    float acc[4][4];
#pragma unroll
    for (int i = 0; i < 4; i++)
#pragma unroll
        for (int j = 0; j < 4; j++) acc[i][j] = 0.f;

    for (int k0 = 0; k0 < K; k0 += 16) {
#pragma unroll
        for (int i = 0; i < 4; i++) {
            int idx = tid + i * 256;       // 0..1023
            int m = idx >> 4, kk = idx & 15;
            As[kk][m] = A[(size_t)(m0 + m) * K + k0 + kk];
            Bs[kk][m] = Bw[(size_t)(n0 + m) * K + k0 + kk];
        }
        __syncthreads();
#pragma unroll
        for (int kk = 0; kk < 16; kk++) {
            float a[4], b[4];
#pragma unroll
            for (int i = 0; i < 4; i++) a[i] = As[kk][ty * 4 + i];
#pragma unroll
            for (int j = 0; j < 4; j++) b[j] = Bs[kk][tx * 4 + j];
#pragma unroll
            for (int i = 0; i < 4; i++)
#pragma unroll
                for (int j = 0; j < 4; j++) acc[i][j] += a[i] * b[j];
        }
        __syncthreads();
    }
#pragma unroll
    for (int i = 0; i < 4; i++) {
        int m = m0 + ty * 4 + i;
#pragma unroll
        for (int j = 0; j < 4; j++) {
            int n = n0 + tx * 4 + j;
            float v = acc[i][j];
            if (bias) v += bias[n];
            C[(size_t)m * N + n] = v;
        }
    }
}

// ---------------------------------------------------------------------------
// Pattern selector: pooled mean -> 2-layer ReLU MLP -> softmax(logits/0.3)
// One block per batch element.
// ---------------------------------------------------------------------------
__global__ void pattern_kernel(const float* __restrict__ x,
                               const float* __restrict__ w1, const float* __restrict__ b1,
                               const float* __restrict__ w2, const float* __restrict__ b2,
                               const float* __restrict__ w3, const float* __restrict__ b3,
                               const float* __restrict__ pbias)
{
    int b = blockIdx.x, tid = threadIdx.x;
    __shared__ float pooled[DD];
    __shared__ float h1[DD];
    __shared__ float h2[DD / 2];
    __shared__ float lg[3];

    for (int d = tid; d < DD; d += 256) {
        float s = 0.f;
        const float* xp = x + (size_t)b * LL * DD + d;
        for (int l = 0; l < LL; l++) s += xp[(size_t)l * DD];
        pooled[d] = s * (1.0f / LL);
    }
    __syncthreads();
    for (int i = tid; i < DD; i += 256) {
        float a = b1[i];
        const float* wr = w1 + (size_t)i * DD;
        for (int k = 0; k < DD; k++) a += pooled[k] * wr[k];
        h1[i] = fmaxf(a, 0.f);
    }
    __syncthreads();
    for (int i = tid; i < DD / 2; i += 256) {
        float a = b2[i];
        const float* wr = w2 + (size_t)i * DD;
        for (int k = 0; k < DD; k++) a += h1[k] * wr[k];
        h2[i] = fmaxf(a, 0.f);
    }
    __syncthreads();
    if (tid < 3) {
        float a = b3[tid] + pbias[tid];
        const float* wr = w3 + (size_t)tid * (DD / 2);
        for (int k = 0; k < DD / 2; k++) a += h2[k] * wr[k];
        lg[tid] = a / 0.3f;
    }
    __syncthreads();
    if (tid == 0) {
        float m = fmaxf(lg[0], fmaxf(lg[1], lg[2]));
        float e0 = expf(lg[0] - m), e1 = expf(lg[1] - m), e2 = expf(lg[2] - m);
        float inv = 1.f / (e0 + e1 + e2);
        g_pw[b * 3 + 0] = e0 * inv;
        g_pw[b * 3 + 1] = e1 * inv;
        g_pw[b * 3 + 2] = e2 * inv;
    }
}

// ---------------------------------------------------------------------------
// Fused attention: scores, radix-select sparse threshold, mask, softmax, AV.
// One block handles QB=4 query rows of one (b,h). 256 threads.
// ---------------------------------------------------------------------------
__device__ __forceinline__ unsigned fkey(float f) {
    unsigned u = __float_as_uint(f);
    return (u & 0x80000000u) ? ~u : (u | 0x80000000u);
}

__global__ __launch_bounds__(256)
void attn_kernel(const float* __restrict__ sparse_w, const float* __restrict__ sparse_b)
{
    __shared__ float s[QB][LL];        // scores -> masked -> probs
    __shared__ float kv[64][65];       // staged K/V tile
    __shared__ float qsh[QB][HD];
    __shared__ float red[256];
    __shared__ unsigned hist[256];
    __shared__ unsigned thr[QB];
    __shared__ float finv[QB];
    __shared__ unsigned sel_prefix;
    __shared__ unsigned sel_k;
    __shared__ float mx_sh, sum_sh;

    int blk = blockIdx.x;
    int b  = blk >> 11;                // / (H * L/QB) = /2048
    int h  = (blk >> 8) & 7;
    int q0 = (blk & 255) * QB;
    int tid = threadIdx.x;

    float p0 = g_pw[b * 3 + 0];
    float p1 = g_pw[b * 3 + 1];
    float p2 = g_pw[b * 3 + 2];
    bool A00 = (p1) > THRESH;
    bool A01 = (p1 + p2) > THRESH;
    bool A10 = (p0 + p1) > THRESH;
    bool A11 = ((p0 + p1) + p2) > THRESH;
    bool need_sparse = (A00 != A01) || (A10 != A11);
    float w_h = sparse_w[h], b_h = sparse_b[h];

    // load Q rows
    {
        int r = tid >> 6, dd = tid & 63;
        qsh[r][dd] = g_qkv[(size_t)(b * LL + q0 + r) * QKVD + h * HD + dd];
    }
    __syncthreads();

    // ---- scores: s[r][j] = (q_r . k_j) * scale ----
    for (int c = 0; c < 16; c++) {
#pragma unroll
        for (int i = 0; i < 16; i++) {
            int idx = tid + i * 256;
            int jj = idx >> 6, dd = idx & 63;
            kv[jj][dd] = g_qkv[(size_t)(b * LL + c * 64 + jj) * QKVD + DD + h * HD + dd];
        }
        __syncthreads();
        int r = tid >> 6, jj = tid & 63;
        float acc = 0.f;
#pragma unroll
        for (int dd = 0; dd < HD; dd++) acc += qsh[r][dd] * kv[jj][dd];
        s[r][c * 64 + jj] = acc * SCALE;
        __syncthreads();
    }

    // ---- radix select: 716th-largest of s2 = s*w_h + b_h per row ----
    if (need_sparse) {
        for (int r = 0; r < QB; r++) {
            if (tid == 0) { sel_prefix = 0u; sel_k = KTOP; }
            __syncthreads();
            for (int shift = 24; shift >= 0; shift -= 8) {
                hist[tid] = 0u;
                __syncthreads();
                unsigned pref = sel_prefix;
                unsigned hm = (shift == 24) ? 0u : (0xFFFFFFFFu << (shift + 8));
                for (int j = tid; j < LL; j += 256) {
                    float v = __fadd_rn(__fmul_rn(s[r][j], w_h), b_h);
                    unsigned u = fkey(v);
                    if ((u & hm) == pref) atomicAdd(&hist[(u >> shift) & 255u], 1u);
                }
                __syncthreads();
                if (tid == 0) {
                    unsigned k = sel_k, cum = 0;
                    for (int dgt = 255; dgt >= 0; --dgt) {
                        unsigned c = hist[dgt];
                        if (cum + c >= k) {
                            sel_prefix = pref | ((unsigned)dgt << shift);
                            sel_k = k - cum;
                            break;
                        }
                        cum += c;
                    }
                }
                __syncthreads();
            }
            if (tid == 0) thr[r] = sel_prefix;
            __syncthreads();
        }
    }

    // ---- mask + softmax per row ----
    for (int r = 0; r < QB; r++) {
        int qg = q0 + r;
        unsigned tu = need_sparse ? thr[r] : 0u;
        float lm = NEG_INF;
        for (int j = tid; j < LL; j += 256) {
            float sv = s[r][j];
            float lf = (abs(qg - j) <= 16) ? 1.f : 0.f;
            float sf = 0.f;
            if (need_sparse) {
                float v = __fadd_rn(__fmul_rn(sv, w_h), b_h);
                sf = (fkey(v) >= tu) ? 1.f : 0.f;
            }
            float comb = (p0 * lf + p1) + p2 * sf;
            float mv = (comb > THRESH) ? sv : NEG_INF;
            s[r][j] = mv;
            lm = fmaxf(lm, mv);
        }
        // max reduce
        red[tid] = lm; __syncthreads();
        for (int o = 128; o > 0; o >>= 1) {
            if (tid < o) red[tid] = fmaxf(red[tid], red[tid + o]);
            __syncthreads();
        }
        if (tid == 0) {
            float mx = red[0];
            if (mx == NEG_INF) { s[r][0] = 0.f; mx = 0.f; }   // all-masked fallback
            mx_sh = mx;
        }
        __syncthreads();
        float mx = mx_sh;
        float ls = 0.f;
        for (int j = tid; j < LL; j += 256) {
            float e = expf(s[r][j] - mx);
            s[r][j] = e;
            ls += e;
        }
        red[tid] = ls; __syncthreads();
        for (int o = 128; o > 0; o >>= 1) {
            if (tid < o) red[tid] += red[tid + o];
            __syncthreads();
        }
        if (tid == 0) { sum_sh = red[0]; finv[r] = 1.f / red[0]; }
        __syncthreads();
    }

    // ---- AV: out[r][d] = (1/sum_r) * sum_j p[r][j] * v[j][d] ----
    int r = tid >> 6, d = tid & 63;
    float acc = 0.f;
    for (int c = 0; c < 16; c++) {
#pragma unroll
        for (int i = 0; i < 16; i++) {
            int idx = tid + i * 256;
            int jj = idx >> 6, dd = idx & 63;
            kv[jj][dd] = g_qkv[(size_t)(b * LL + c * 64 + jj) * QKVD + 2 * DD + h * HD + dd];
        }
        __syncthreads();
#pragma unroll
        for (int jj = 0; jj < 64; jj++) acc += s[r][c * 64 + jj] * kv[jj][d];
        __syncthreads();
    }
    g_attn[(size_t)(b * LL + q0 + r) * DD + h * HD + d] = acc * finv[r];
}

// ---------------------------------------------------------------------------
extern "C" void kernel_launch(void* const* d_in, const int* in_sizes, int n_in,
                              void* d_out, int out_size)
{
    const float* x       = (const float*)d_in[0];
    const float* qkv_w   = (const float*)d_in[1];
    const float* proj_w  = (const float*)d_in[2];
    const float* proj_b  = (const float*)d_in[3];
    const float* ps_w1   = (const float*)d_in[4];
    const float* ps_b1   = (const float*)d_in[5];
    const float* ps_w2   = (const float*)d_in[6];
    const float* ps_b2   = (const float*)d_in[7];
    const float* ps_w3   = (const float*)d_in[8];
    const float* ps_b3   = (const float*)d_in[9];
    const float* pbias   = (const float*)d_in[10];
    const float* sparse_w = (const float*)d_in[11];
    const float* sparse_b = (const float*)d_in[12];
    float* out = (float*)d_out;

    float *qkv_ptr, *attn_ptr;
    cudaGetSymbolAddress((void**)&qkv_ptr, g_qkv);
    cudaGetSymbolAddress((void**)&attn_ptr, g_attn);

    // QKV projection: (4096,512) @ (1536,512)^T -> (4096,1536)
    gemm_nt<<<dim3(QKVD / 64, ML / 64), 256>>>(x, qkv_w, nullptr, qkv_ptr, ML, QKVD, DD);
    // Pattern selector (independent of QKV)
    pattern_kernel<<<BB, 256>>>(x, ps_w1, ps_b1, ps_w2, ps_b2, ps_w3, ps_b3, pbias);
    // Fused attention
    attn_kernel<<<BB * HH * (LL / QB), 256>>>(sparse_w, sparse_b);
    // Output projection: (4096,512) @ (512,512)^T + bias -> (4096,512)
    gemm_nt<<<dim3(DD / 64, ML / 64), 256>>>(attn_ptr, proj_w, proj_b, out, ML, DD, DD);
}

// round 2
// speedup vs baseline: 1.4957x; 1.4957x over previous
#include <cuda_runtime.h>
#include <cuda_bf16.h>
#include <math.h>

#define BB 4
#define LL 1024
#define DD 512
#define HH 8
#define HD 64
#define QKVD 1536
#define ML (BB*LL)
#define KTOP 716
#define THRESH 0.05f
#define SCALE 0.125f
#define NEG_INF __int_as_float(0xff800000)

// Scratch (device globals; no allocations allowed)
__device__ float g_qkv[ML * QKVD];                 // (B*L, 3*D)
__device__ float g_scores[(size_t)BB * HH * LL * LL]; // 134 MB: per (b,h) LxL
__device__ float g_attn[ML * DD];
__device__ float g_pw[BB * 3];
__device__ float g_pool_part[32][DD];
__device__ float g_pooled[BB][DD];

// ---------------------------------------------------------------------------
// Batched strided GEMM: C[m,n] = alpha * sum_k A[m,k] * B(n,k) (+bias[n])
// bTrans=1: B stored [N,K] row-major (NT).  bTrans=0: B stored [K,N] (NN).
// Batch index z = blockIdx.z; b = z/nh, h = z%nh; per-matrix offsets applied.
// 64x64 tile, 16-deep k staging, 4x4 per thread.
// ---------------------------------------------------------------------------
__global__ __launch_bounds__(256)
void gemm_bt(const float* __restrict__ A, int lda, long sAb, long sAh,
             const float* __restrict__ B, int ldb, long sBb, long sBh,
             float* __restrict__ C, int ldc, long sCb, long sCh,
             int M, int N, int K, float alpha,
             const float* __restrict__ bias, int nh, int bTrans)
{
    __shared__ float As[16][65];
    __shared__ float Bs[16][65];
    int z = blockIdx.z;
    int b = z / nh, h = z % nh;
    A += (size_t)b * sAb + (size_t)h * sAh;
    B += (size_t)b * sBb + (size_t)h * sBh;
    C += (size_t)b * sCb + (size_t)h * sCh;

    int tid = threadIdx.x;
    int tx = tid & 15, ty = tid >> 4;
    int m0 = blockIdx.y * 64, n0 = blockIdx.x * 64;

    float acc[4][4];
#pragma unroll
    for (int i = 0; i < 4; i++)
#pragma unroll
        for (int j = 0; j < 4; j++) acc[i][j] = 0.f;

    for (int k0 = 0; k0 < K; k0 += 16) {
#pragma unroll
        for (int i = 0; i < 4; i++) {
            int idx = tid + i * 256;
            int m = idx >> 4, kk = idx & 15;
            As[kk][m] = A[(size_t)(m0 + m) * lda + k0 + kk];
        }
        if (bTrans) {
#pragma unroll
            for (int i = 0; i < 4; i++) {
                int idx = tid + i * 256;
                int n = idx >> 4, kk = idx & 15;
                Bs[kk][n] = B[(size_t)(n0 + n) * ldb + k0 + kk];
            }
        } else {
#pragma unroll
            for (int i = 0; i < 4; i++) {
                int idx = tid + i * 256;
                int n = idx & 63, kk = idx >> 6;   // kk in 0..15 over i
                Bs[kk][n] = B[(size_t)(k0 + kk) * ldb + n0 + n];
            }
        }
        __syncthreads();
#pragma unroll
        for (int kk = 0; kk < 16; kk++) {
            float a[4], bb[4];
#pragma unroll
            for (int i = 0; i < 4; i++) a[i] = As[kk][ty * 4 + i];
#pragma unroll
            for (int j = 0; j < 4; j++) bb[j] = Bs[kk][tx * 4 + j];
#pragma unroll
            for (int i = 0; i < 4; i++)
#pragma unroll
                for (int j = 0; j < 4; j++) acc[i][j] += a[i] * bb[j];
        }
        __syncthreads();
    }
#pragma unroll
    for (int i = 0; i < 4; i++) {
        int m = m0 + ty * 4 + i;
#pragma unroll
        for (int j = 0; j < 4; j++) {
            int n = n0 + tx * 4 + j;
            float v = acc[i][j] * alpha;
            if (bias) v += bias[n];
            C[(size_t)m * ldc + n] = v;
        }
    }
}

// ---------------------------------------------------------------------------
// Pooling stage 1: 32 blocks, each sums 128 rows of one batch. Deterministic.
// ---------------------------------------------------------------------------
__global__ __launch_bounds__(256)
void pool1_kernel(const float* __restrict__ x)
{
    int blk = blockIdx.x;        // 0..31
    int b = blk >> 3, c = blk & 7;
    int tid = threadIdx.x;
    const float2* xp = (const float2*)(x + ((size_t)b * LL + c * 128) * DD) + tid;
    float s0 = 0.f, s1 = 0.f;
    for (int l = 0; l < 128; l++) {
        float2 v = xp[(size_t)l * (DD / 2)];
        s0 += v.x; s1 += v.y;
    }
    g_pool_part[blk][tid * 2]     = s0;
    g_pool_part[blk][tid * 2 + 1] = s1;
}

// ---------------------------------------------------------------------------
// Pattern selector MLP (4 blocks, one per batch)
// ---------------------------------------------------------------------------
__global__ __launch_bounds__(256)
void pattern_kernel(const float* __restrict__ w1, const float* __restrict__ b1,
                    const float* __restrict__ w2, const float* __restrict__ b2,
                    const float* __restrict__ w3, const float* __restrict__ b3,
                    const float* __restrict__ pbias)
{
    int b = blockIdx.x, tid = threadIdx.x;
    __shared__ float pooled[DD];
    __shared__ float h1[DD];
    __shared__ float h2[DD / 2];
    __shared__ float lg[3];

    for (int d = tid; d < DD; d += 256) {
        float s = 0.f;
#pragma unroll
        for (int c = 0; c < 8; c++) s += g_pool_part[b * 8 + c][d];
        pooled[d] = s * (1.0f / LL);
    }
    __syncthreads();
    for (int i = tid; i < DD; i += 256) {
        float a = b1[i];
        const float* wr = w1 + (size_t)i * DD;
        for (int k = 0; k < DD; k++) a += pooled[k] * wr[k];
        h1[i] = fmaxf(a, 0.f);
    }
    __syncthreads();
    for (int i = tid; i < DD / 2; i += 256) {
        float a = b2[i];
        const float* wr = w2 + (size_t)i * DD;
        for (int k = 0; k < DD; k++) a += h1[k] * wr[k];
        h2[i] = fmaxf(a, 0.f);
    }
    __syncthreads();
    if (tid < 3) {
        float a = b3[tid] + pbias[tid];
        const float* wr = w3 + (size_t)tid * (DD / 2);
        for (int k = 0; k < DD / 2; k++) a += h2[k] * wr[k];
        lg[tid] = a / 0.3f;
    }
    __syncthreads();
    if (tid == 0) {
        float m = fmaxf(lg[0], fmaxf(lg[1], lg[2]));
        float e0 = expf(lg[0] - m), e1 = expf(lg[1] - m), e2 = expf(lg[2] - m);
        float inv = 1.f / (e0 + e1 + e2);
        g_pw[b * 3 + 0] = e0 * inv;
        g_pw[b * 3 + 1] = e1 * inv;
        g_pw[b * 3 + 2] = e2 * inv;
    }
}

// ---------------------------------------------------------------------------
// Mask + softmax, one block per (b,h,q) row. Probabilities (already /sum)
// written back in place.
// ---------------------------------------------------------------------------
__device__ __forceinline__ unsigned fkey(float f) {
    unsigned u = __float_as_uint(f);
    return (u & 0x80000000u) ? ~u : (u | 0x80000000u);
}

__global__ __launch_bounds__(256)
void softmax_kernel(const float* __restrict__ sparse_w,
                    const float* __restrict__ sparse_b)
{
    __shared__ float s[LL];
    __shared__ float red[256];
    __shared__ unsigned hist[256];
    __shared__ unsigned sel_prefix, sel_k;
    __shared__ float mx_sh;

    int row = blockIdx.x;           // 0..32767
    int z = row >> 10, q = row & 1023;
    int b = z >> 3, h = z & 7;
    float* srow = g_scores + ((size_t)z << 20) + ((size_t)q << 10);
    int tid = threadIdx.x;

    ((float4*)s)[tid] = ((const float4*)srow)[tid];

    float p0 = g_pw[b * 3 + 0];
    float p1 = g_pw[b * 3 + 1];
    float p2 = g_pw[b * 3 + 2];
    bool A00 = p1 > THRESH;
    bool A01 = (p1 + p2) > THRESH;
    bool A10 = (p0 + p1) > THRESH;
    bool A11 = ((p0 + p1) + p2) > THRESH;
    bool need_sparse = (A00 != A01) || (A10 != A11);
    float w_h = sparse_w[h], b_h = sparse_b[h];
    __syncthreads();

    unsigned tu = 0u;
    if (need_sparse) {
        if (tid == 0) { sel_prefix = 0u; sel_k = KTOP; }
        __syncthreads();
        for (int shift = 24; shift >= 0; shift -= 8) {
            hist[tid] = 0u;
            __syncthreads();
            unsigned pref = sel_prefix;
            unsigned hm = (shift == 24) ? 0u : (0xFFFFFFFFu << (shift + 8));
            for (int j = tid; j < LL; j += 256) {
                float v = __fadd_rn(__fmul_rn(s[j], w_h), b_h);
                unsigned u = fkey(v);
                if ((u & hm) == pref) atomicAdd(&hist[(u >> shift) & 255u], 1u);
            }
            __syncthreads();
            if (tid == 0) {
                unsigned k = sel_k, cum = 0;
                for (int dgt = 255; dgt >= 0; --dgt) {
                    unsigned c = hist[dgt];
                    if (cum + c >= k) {
                        sel_prefix = pref | ((unsigned)dgt << shift);
                        sel_k = k - cum;
                        break;
                    }
                    cum += c;
                }
            }
            __syncthreads();
        }
        tu = sel_prefix;
        __syncthreads();
    }

    // mask + local max (each thread owns j = 4*tid .. 4*tid+3)
    float v[4];
    float lm = NEG_INF;
#pragma unroll
    for (int i = 0; i < 4; i++) {
        int j = tid * 4 + i;
        float sv = s[j];
        bool lf = (abs(q - j) <= 16);
        bool allow;
        if (need_sparse) {
            float s2 = __fadd_rn(__fmul_rn(sv, w_h), b_h);
            float sf = (fkey(s2) >= tu) ? 1.f : 0.f;
            float comb = (p0 * (lf ? 1.f : 0.f) + p1) + p2 * sf;
            allow = comb > THRESH;
        } else {
            allow = lf ? A10 : A00;
        }
        v[i] = allow ? sv : NEG_INF;
        lm = fmaxf(lm, v[i]);
    }
    red[tid] = lm; __syncthreads();
    for (int o = 128; o > 0; o >>= 1) {
        if (tid < o) red[tid] = fmaxf(red[tid], red[tid + o]);
        __syncthreads();
    }
    if (tid == 0) mx_sh = red[0];
    __syncthreads();
    float mx = mx_sh;

    if (mx == NEG_INF) {
        // fully masked row: position 0 unmasked with score 0 -> prob 1 at j=0
        float4 o;
        o.x = (tid == 0) ? 1.f : 0.f; o.y = 0.f; o.z = 0.f; o.w = 0.f;
        ((float4*)srow)[tid] = o;
        return;
    }

    float ls = 0.f;
#pragma unroll
    for (int i = 0; i < 4; i++) {
        v[i] = __expf(v[i] - mx);
        ls += v[i];
    }
    red[tid] = ls; __syncthreads();
    for (int o = 128; o > 0; o >>= 1) {
        if (tid < o) red[tid] += red[tid + o];
        __syncthreads();
    }
    if (tid == 0) mx_sh = 1.f / red[0];
    __syncthreads();
    float inv = mx_sh;
    float4 o;
    o.x = v[0] * inv; o.y = v[1] * inv; o.z = v[2] * inv; o.w = v[3] * inv;
    ((float4*)srow)[tid] = o;
}

// ---------------------------------------------------------------------------
extern "C" void kernel_launch(void* const* d_in, const int* in_sizes, int n_in,
                              void* d_out, int out_size)
{
    const float* x        = (const float*)d_in[0];
    const float* qkv_w    = (const float*)d_in[1];
    const float* proj_w   = (const float*)d_in[2];
    const float* proj_b   = (const float*)d_in[3];
    const float* ps_w1    = (const float*)d_in[4];
    const float* ps_b1    = (const float*)d_in[5];
    const float* ps_w2    = (const float*)d_in[6];
    const float* ps_b2    = (const float*)d_in[7];
    const float* ps_w3    = (const float*)d_in[8];
    const float* ps_b3    = (const float*)d_in[9];
    const float* pbias    = (const float*)d_in[10];
    const float* sparse_w = (const float*)d_in[11];
    const float* sparse_b = (const float*)d_in[12];
    float* out = (float*)d_out;

    float *qkv_p, *sc_p, *attn_p;
    cudaGetSymbolAddress((void**)&qkv_p,  g_qkv);
    cudaGetSymbolAddress((void**)&sc_p,   g_scores);
    cudaGetSymbolAddress((void**)&attn_p, g_attn);

    // pattern selector (pool then MLP)
    pool1_kernel<<<32, 256>>>(x);
    pattern_kernel<<<BB, 256>>>(ps_w1, ps_b1, ps_w2, ps_b2, ps_w3, ps_b3, pbias);

    // QKV projection: (4096,1536) = x(4096,512) @ qkv_w(1536,512)^T   [NT]
    gemm_bt<<<dim3(QKVD / 64, ML / 64, 1), 256>>>(
        x, DD, 0, 0,  qkv_w, DD, 0, 0,  qkv_p, QKVD, 0, 0,
        ML, QKVD, DD, 1.f, nullptr, 1, 1);

    // Scores: per (b,h): S(1024,1024) = Q(1024,64) @ K(1024,64)^T * SCALE  [NT]
    gemm_bt<<<dim3(LL / 64, LL / 64, BB * HH), 256>>>(
        qkv_p, QKVD, (long)LL * QKVD, HD,
        qkv_p + DD, QKVD, (long)LL * QKVD, HD,
        sc_p, LL, (long)HH * LL * LL, (long)LL * LL,
        LL, LL, HD, SCALE, nullptr, HH, 1);

    // Mask + softmax (normalized probs in place)
    softmax_kernel<<<BB * HH * LL, 256>>>(sparse_w, sparse_b);

    // AV: per (b,h): O(1024,64) = P(1024,1024) @ V(1024,64)   [NN]
    gemm_bt<<<dim3(HD / 64, LL / 64, BB * HH), 256>>>(
        sc_p, LL, (long)HH * LL * LL, (long)LL * LL,
        qkv_p + 2 * DD, QKVD, (long)LL * QKVD, HD,
        attn_p, DD, (long)LL * DD, HD,
        LL, HD, LL, 1.f, nullptr, HH, 0);

    // Output projection: (4096,512) = attn @ proj_w^T + proj_b   [NT]
    gemm_bt<<<dim3(DD / 64, ML / 64, 1), 256>>>(
        attn_p, DD, 0, 0,  proj_w, DD, 0, 0,  out, DD, 0, 0,
        ML, DD, DD, 1.f, proj_b, 1, 1);
}

// round 3
// speedup vs baseline: 2.5378x; 1.6968x over previous
#include <cuda_runtime.h>
#include <cuda_bf16.h>
#include <math.h>

#define BB 4
#define LL 1024
#define DD 512
#define HH 8
#define HD 64
#define QKVD 1536
#define ML (BB*LL)
#define KTOP 716
#define THRESH 0.05f
#define SCALE 0.125f
#define NEG_INF __int_as_float(0xff800000)

// Scratch (device globals; no allocations allowed)
__device__ float g_qkv[ML * QKVD];                    // (B*L, 3*D)
__device__ float g_scores[(size_t)BB * HH * LL * LL]; // full-path only
__device__ float g_attn[ML * DD];
__device__ float g_pw[BB * 3];
__device__ int   g_mode[BB];                          // 0=full 1=local 2=allmasked
__device__ float g_pool_part[32][DD];

// ---------------------------------------------------------------------------
// Batched strided GEMM (NT/NN). gate!=nullptr -> only run when mode[b]==0.
// ---------------------------------------------------------------------------
__global__ __launch_bounds__(256)
void gemm_bt(const float* __restrict__ A, int lda, long sAb, long sAh,
             const float* __restrict__ B, int ldb, long sBb, long sBh,
             float* __restrict__ C, int ldc, long sCb, long sCh,
             int M, int N, int K, float alpha,
             const float* __restrict__ bias, int nh, int bTrans,
             const int* __restrict__ gate)
{
    __shared__ float As[16][65];
    __shared__ float Bs[16][65];
    int z = blockIdx.z;
    int b = z / nh, h = z % nh;
    if (gate && gate[b] != 0) return;
    A += (size_t)b * sAb + (size_t)h * sAh;
    B += (size_t)b * sBb + (size_t)h * sBh;
    C += (size_t)b * sCb + (size_t)h * sCh;

    int tid = threadIdx.x;
    int tx = tid & 15, ty = tid >> 4;
    int m0 = blockIdx.y * 64, n0 = blockIdx.x * 64;

    float acc[4][4];
#pragma unroll
    for (int i = 0; i < 4; i++)
#pragma unroll
        for (int j = 0; j < 4; j++) acc[i][j] = 0.f;

    for (int k0 = 0; k0 < K; k0 += 16) {
#pragma unroll
        for (int i = 0; i < 4; i++) {
            int idx = tid + i * 256;
            int m = idx >> 4, kk = idx & 15;
            As[kk][m] = A[(size_t)(m0 + m) * lda + k0 + kk];
        }
        if (bTrans) {
#pragma unroll
            for (int i = 0; i < 4; i++) {
                int idx = tid + i * 256;
                int n = idx >> 4, kk = idx & 15;
                Bs[kk][n] = B[(size_t)(n0 + n) * ldb + k0 + kk];
            }
        } else {
#pragma unroll
            for (int i = 0; i < 4; i++) {
                int idx = tid + i * 256;
                int n = idx & 63, kk = idx >> 6;
                Bs[kk][n] = B[(size_t)(k0 + kk) * ldb + n0 + n];
            }
        }
        __syncthreads();
#pragma unroll
        for (int kk = 0; kk < 16; kk++) {
            float a[4], bb[4];
#pragma unroll
            for (int i = 0; i < 4; i++) a[i] = As[kk][ty * 4 + i];
#pragma unroll
            for (int j = 0; j < 4; j++) bb[j] = Bs[kk][tx * 4 + j];
#pragma unroll
            for (int i = 0; i < 4; i++)
#pragma unroll
                for (int j = 0; j < 4; j++) acc[i][j] += a[i] * bb[j];
        }
        __syncthreads();
    }
#pragma unroll
    for (int i = 0; i < 4; i++) {
        int m = m0 + ty * 4 + i;
#pragma unroll
        for (int j = 0; j < 4; j++) {
            int n = n0 + tx * 4 + j;
            float v = acc[i][j] * alpha;
            if (bias) v += bias[n];
            C[(size_t)m * ldc + n] = v;
        }
    }
}

// ---------------------------------------------------------------------------
// Pooling stage 1
// ---------------------------------------------------------------------------
__global__ __launch_bounds__(256)
void pool1_kernel(const float* __restrict__ x)
{
    int blk = blockIdx.x;
    int b = blk >> 3, c = blk & 7;
    int tid = threadIdx.x;
    const float2* xp = (const float2*)(x + ((size_t)b * LL + c * 128) * DD) + tid;
    float s0 = 0.f, s1 = 0.f;
    for (int l = 0; l < 128; l++) {
        float2 v = xp[(size_t)l * (DD / 2)];
        s0 += v.x; s1 += v.y;
    }
    g_pool_part[blk][tid * 2]     = s0;
    g_pool_part[blk][tid * 2 + 1] = s1;
}

// ---------------------------------------------------------------------------
// Pattern selector MLP + mode classification
// ---------------------------------------------------------------------------
__global__ __launch_bounds__(256)
void pattern_kernel(const float* __restrict__ w1, const float* __restrict__ b1,
                    const float* __restrict__ w2, const float* __restrict__ b2,
                    const float* __restrict__ w3, const float* __restrict__ b3,
                    const float* __restrict__ pbias)
{
    int b = blockIdx.x, tid = threadIdx.x;
    __shared__ float pooled[DD];
    __shared__ float h1[DD];
    __shared__ float h2[DD / 2];
    __shared__ float lg[3];

    for (int d = tid; d < DD; d += 256) {
        float s = 0.f;
#pragma unroll
        for (int c = 0; c < 8; c++) s += g_pool_part[b * 8 + c][d];
        pooled[d] = s * (1.0f / LL);
    }
    __syncthreads();
    for (int i = tid; i < DD; i += 256) {
        float a = b1[i];
        const float* wr = w1 + (size_t)i * DD;
        for (int k = 0; k < DD; k++) a += pooled[k] * wr[k];
        h1[i] = fmaxf(a, 0.f);
    }
    __syncthreads();
    for (int i = tid; i < DD / 2; i += 256) {
        float a = b2[i];
        const float* wr = w2 + (size_t)i * DD;
        for (int k = 0; k < DD; k++) a += h1[k] * wr[k];
        h2[i] = fmaxf(a, 0.f);
    }
    __syncthreads();
    if (tid < 3) {
        float a = b3[tid] + pbias[tid];
        const float* wr = w3 + (size_t)tid * (DD / 2);
        for (int k = 0; k < DD / 2; k++) a += h2[k] * wr[k];
        lg[tid] = a / 0.3f;
    }
    __syncthreads();
    if (tid == 0) {
        float m = fmaxf(lg[0], fmaxf(lg[1], lg[2]));
        float e0 = expf(lg[0] - m), e1 = expf(lg[1] - m), e2 = expf(lg[2] - m);
        float inv = 1.f / (e0 + e1 + e2);
        float p0 = e0 * inv, p1 = e1 * inv, p2 = e2 * inv;
        g_pw[b * 3 + 0] = p0;
        g_pw[b * 3 + 1] = p1;
        g_pw[b * 3 + 2] = p2;
        bool A00 = p1 > THRESH;
        bool A01 = (p1 + p2) > THRESH;
        bool A10 = (p0 + p1) > THRESH;
        bool A11 = ((p0 + p1) + p2) > THRESH;
        bool need_sparse = (A00 != A01) || (A10 != A11);
        int mode;
        if (need_sparse || A00) mode = 0;          // need full scores
        else if (A10)           mode = 1;          // local window only
        else                    mode = 2;          // everything masked
        g_mode[b] = mode;
    }
}

// ---------------------------------------------------------------------------
// Local-window fused attention (mode 1) + all-masked fallback (mode 2).
// 16 query rows per block, 256 threads (8 warps x 2 rows).
// ---------------------------------------------------------------------------
__global__ __launch_bounds__(256)
void local_attn_kernel()
{
    __shared__ float ksh[48][65];
    __shared__ float vsh[48][65];
    __shared__ float qsh[16][64];
    __shared__ float psh[16][33];

    int blk = blockIdx.x;
    int b = blk >> 9;               // 8 heads * 64 chunks
    int h = (blk >> 6) & 7;
    int q0 = (blk & 63) * 16;
    int mode = g_mode[b];
    if (mode == 0) return;
    int tid = threadIdx.x;
    const float* base = g_qkv + (size_t)b * LL * QKVD + h * HD;

    if (mode == 2) {
        // fully-masked rows: prob 1 at j=0 -> out = V[0]
        const float* v0 = base + 2 * DD;
#pragma unroll
        for (int i = 0; i < 4; i++) {
            int idx = tid + i * 256;
            int r = idx >> 6, d = idx & 63;
            g_attn[(size_t)(b * LL + q0 + r) * DD + h * HD + d] = v0[d];
        }
        return;
    }

    int kb0 = max(q0 - 16, 0);
    int kend = min(q0 + 15 + 16, LL - 1);
    int klen = kend - kb0 + 1;      // <= 48

    for (int i = tid; i < klen * 64; i += 256) {
        int jj = i >> 6, d = i & 63;
        const float* src = base + (size_t)(kb0 + jj) * QKVD;
        ksh[jj][d] = src[DD + d];
        vsh[jj][d] = src[2 * DD + d];
    }
#pragma unroll
    for (int i = 0; i < 4; i++) {
        int idx = tid + i * 256;
        int r = idx >> 6, d = idx & 63;
        qsh[r][d] = base[(size_t)(q0 + r) * QKVD + d];
    }
    __syncthreads();

    int warp = tid >> 5, lane = tid & 31;
#pragma unroll
    for (int rr = 0; rr < 2; rr++) {
        int r = warp * 2 + rr;
        int q = q0 + r;
        int w0 = max(q - 16, 0), w1 = min(q + 16, LL - 1);
        int cnt = w1 - w0 + 1;      // <= 33
        int off = w0 - kb0;

        float s0 = NEG_INF, s1 = NEG_INF;
        if (lane < cnt) {
            float acc = 0.f;
#pragma unroll
            for (int d = 0; d < 64; d++) acc += qsh[r][d] * ksh[off + lane][d];
            s0 = acc * SCALE;
        }
        if (lane + 32 < cnt) {
            float acc = 0.f;
#pragma unroll
            for (int d = 0; d < 64; d++) acc += qsh[r][d] * ksh[off + lane + 32][d];
            s1 = acc * SCALE;
        }
        float m = fmaxf(s0, s1);
#pragma unroll
        for (int o = 16; o > 0; o >>= 1) m = fmaxf(m, __shfl_xor_sync(~0u, m, o));
        float e0 = (lane < cnt) ? __expf(s0 - m) : 0.f;
        float e1 = (lane + 32 < cnt) ? __expf(s1 - m) : 0.f;
        float sum = e0 + e1;
#pragma unroll
        for (int o = 16; o > 0; o >>= 1) sum += __shfl_xor_sync(~0u, sum, o);
        float inv = 1.f / sum;
        if (lane < cnt) psh[r][lane] = e0 * inv;
        if (lane + 32 < cnt) psh[r][lane + 32] = e1 * inv;
        __syncwarp();

        float o0 = 0.f, o1 = 0.f;
        for (int jj = 0; jj < cnt; jj++) {
            float p = psh[r][jj];
            o0 += p * vsh[off + jj][lane];
            o1 += p * vsh[off + jj][lane + 32];
        }
        float* dst = g_attn + (size_t)(b * LL + q) * DD + h * HD;
        dst[lane] = o0;
        dst[lane + 32] = o1;
    }
}

// ---------------------------------------------------------------------------
// Full-path mask + softmax (mode 0 only)
// ---------------------------------------------------------------------------
__device__ __forceinline__ unsigned fkey(float f) {
    unsigned u = __float_as_uint(f);
    return (u & 0x80000000u) ? ~u : (u | 0x80000000u);
}

__global__ __launch_bounds__(256)
void softmax_kernel(const float* __restrict__ sparse_w,
                    const float* __restrict__ sparse_b)
{
    __shared__ float s[LL];
    __shared__ float red[256];
    __shared__ unsigned hist[256];
    __shared__ unsigned sel_prefix, sel_k;
    __shared__ float mx_sh;

    int row = blockIdx.x;
    int z = row >> 10, q = row & 1023;
    int b = z >> 3, h = z & 7;
    if (g_mode[b] != 0) return;
    float* srow = g_scores + ((size_t)z << 20) + ((size_t)q << 10);
    int tid = threadIdx.x;

    ((float4*)s)[tid] = ((const float4*)srow)[tid];

    float p0 = g_pw[b * 3 + 0];
    float p1 = g_pw[b * 3 + 1];
    float p2 = g_pw[b * 3 + 2];
    bool A00 = p1 > THRESH;
    bool A01 = (p1 + p2) > THRESH;
    bool A10 = (p0 + p1) > THRESH;
    bool A11 = ((p0 + p1) + p2) > THRESH;
    bool need_sparse = (A00 != A01) || (A10 != A11);
    float w_h = sparse_w[h], b_h = sparse_b[h];
    __syncthreads();

    unsigned tu = 0u;
    if (need_sparse) {
        if (tid == 0) { sel_prefix = 0u; sel_k = KTOP; }
        __syncthreads();
        for (int shift = 24; shift >= 0; shift -= 8) {
            hist[tid] = 0u;
            __syncthreads();
            unsigned pref = sel_prefix;
            unsigned hm = (shift == 24) ? 0u : (0xFFFFFFFFu << (shift + 8));
            for (int j = tid; j < LL; j += 256) {
                float v = __fadd_rn(__fmul_rn(s[j], w_h), b_h);
                unsigned u = fkey(v);
                if ((u & hm) == pref) atomicAdd(&hist[(u >> shift) & 255u], 1u);
            }
            __syncthreads();
            if (tid == 0) {
                unsigned k = sel_k, cum = 0;
                for (int dgt = 255; dgt >= 0; --dgt) {
                    unsigned c = hist[dgt];
                    if (cum + c >= k) {
                        sel_prefix = pref | ((unsigned)dgt << shift);
                        sel_k = k - cum;
                        break;
                    }
                    cum += c;
                }
            }
            __syncthreads();
        }
        tu = sel_prefix;
        __syncthreads();
    }

    float v[4];
    float lm = NEG_INF;
#pragma unroll
    for (int i = 0; i < 4; i++) {
        int j = tid * 4 + i;
        float sv = s[j];
        bool lf = (abs(q - j) <= 16);
        bool allow;
        if (need_sparse) {
            float s2 = __fadd_rn(__fmul_rn(sv, w_h), b_h);
            float sf = (fkey(s2) >= tu) ? 1.f : 0.f;
            float comb = (p0 * (lf ? 1.f : 0.f) + p1) + p2 * sf;
            allow = comb > THRESH;
        } else {
            allow = lf ? A10 : A00;
        }
        v[i] = allow ? sv : NEG_INF;
        lm = fmaxf(lm, v[i]);
    }
    red[tid] = lm; __syncthreads();
    for (int o = 128; o > 0; o >>= 1) {
        if (tid < o) red[tid] = fmaxf(red[tid], red[tid + o]);
        __syncthreads();
    }
    if (tid == 0) mx_sh = red[0];
    __syncthreads();
    float mx = mx_sh;

    if (mx == NEG_INF) {
        float4 o;
        o.x = (tid == 0) ? 1.f : 0.f; o.y = 0.f; o.z = 0.f; o.w = 0.f;
        ((float4*)srow)[tid] = o;
        return;
    }

    float ls = 0.f;
#pragma unroll
    for (int i = 0; i < 4; i++) {
        v[i] = __expf(v[i] - mx);
        ls += v[i];
    }
    red[tid] = ls; __syncthreads();
    for (int o = 128; o > 0; o >>= 1) {
        if (tid < o) red[tid] += red[tid + o];
        __syncthreads();
    }
    if (tid == 0) mx_sh = 1.f / red[0];
    __syncthreads();
    float inv = mx_sh;
    float4 o;
    o.x = v[0] * inv; o.y = v[1] * inv; o.z = v[2] * inv; o.w = v[3] * inv;
    ((float4*)srow)[tid] = o;
}

// ---------------------------------------------------------------------------
extern "C" void kernel_launch(void* const* d_in, const int* in_sizes, int n_in,
                              void* d_out, int out_size)
{
    const float* x        = (const float*)d_in[0];
    const float* qkv_w    = (const float*)d_in[1];
    const float* proj_w   = (const float*)d_in[2];
    const float* proj_b   = (const float*)d_in[3];
    const float* ps_w1    = (const float*)d_in[4];
    const float* ps_b1    = (const float*)d_in[5];
    const float* ps_w2    = (const float*)d_in[6];
    const float* ps_b2    = (const float*)d_in[7];
    const float* ps_w3    = (const float*)d_in[8];
    const float* ps_b3    = (const float*)d_in[9];
    const float* pbias    = (const float*)d_in[10];
    const float* sparse_w = (const float*)d_in[11];
    const float* sparse_b = (const float*)d_in[12];
    float* out = (float*)d_out;

    float *qkv_p, *sc_p, *attn_p;
    int *mode_p;
    cudaGetSymbolAddress((void**)&qkv_p,  g_qkv);
    cudaGetSymbolAddress((void**)&sc_p,   g_scores);
    cudaGetSymbolAddress((void**)&attn_p, g_attn);
    cudaGetSymbolAddress((void**)&mode_p, g_mode);

    // pattern selector + mode classification
    pool1_kernel<<<32, 256>>>(x);
    pattern_kernel<<<BB, 256>>>(ps_w1, ps_b1, ps_w2, ps_b2, ps_w3, ps_b3, pbias);

    // QKV projection (always)
    gemm_bt<<<dim3(QKVD / 64, ML / 64, 1), 256>>>(
        x, DD, 0, 0,  qkv_w, DD, 0, 0,  qkv_p, QKVD, 0, 0,
        ML, QKVD, DD, 1.f, nullptr, 1, 1, nullptr);

    // ---- full path (gated on mode==0) ----
    gemm_bt<<<dim3(LL / 64, LL / 64, BB * HH), 256>>>(
        qkv_p, QKVD, (long)LL * QKVD, HD,
        qkv_p + DD, QKVD, (long)LL * QKVD, HD,
        sc_p, LL, (long)HH * LL * LL, (long)LL * LL,
        LL, LL, HD, SCALE, nullptr, HH, 1, mode_p);
    softmax_kernel<<<BB * HH * LL, 256>>>(sparse_w, sparse_b);
    gemm_bt<<<dim3(HD / 64, LL / 64, BB * HH), 256>>>(
        sc_p, LL, (long)HH * LL * LL, (long)LL * LL,
        qkv_p + 2 * DD, QKVD, (long)LL * QKVD, HD,
        attn_p, DD, (long)LL * DD, HD,
        LL, HD, LL, 1.f, nullptr, HH, 0, mode_p);

    // ---- local/all-masked path (gated on mode!=0) ----
    local_attn_kernel<<<BB * HH * (LL / 16), 256>>>();

    // Output projection (always)
    gemm_bt<<<dim3(DD / 64, ML / 64, 1), 256>>>(
        attn_p, DD, 0, 0,  proj_w, DD, 0, 0,  out, DD, 0, 0,
        ML, DD, DD, 1.f, proj_b, 1, 1, nullptr);
}

// round 4
// speedup vs baseline: 4.7982x; 1.8907x over previous
#include <cuda_runtime.h>
#include <cuda_bf16.h>
#include <math.h>

#define BB 4
#define LL 1024
#define DD 512
#define HH 8
#define HD 64
#define QKVD 1536
#define ML (BB*LL)
#define KTOP 716
#define THRESH 0.05f
#define SCALE 0.125f
#define NEG_INF __int_as_float(0xff800000)

// Scratch (device globals; no allocations allowed)
__device__ float g_qkv[ML * QKVD];
__device__ float g_scores[(size_t)BB * HH * LL * LL];
__device__ float g_attn[ML * DD];
__device__ float g_pw[BB * 3];
__device__ int   g_mode[BB];
__device__ float g_pool_part[32][DD];

// ---------------------------------------------------------------------------
// 128x128x16 tile SGEMM (NT), 8x8 micro-tile, batched strided, gated.
// ---------------------------------------------------------------------------
__global__ __launch_bounds__(256)
void gemm128(const float* __restrict__ A, int lda, long sAb, long sAh,
             const float* __restrict__ B, int ldb, long sBb, long sBh,
             float* __restrict__ C, int ldc, long sCb, long sCh,
             int K, float alpha, const float* __restrict__ bias,
             int nh, const int* __restrict__ gate)
{
    __shared__ float As[16][132];
    __shared__ float Bs[16][132];
    int z = blockIdx.z;
    int b = z / nh, h = z % nh;
    if (gate && gate[b] != 0) return;
    A += (size_t)b * sAb + (size_t)h * sAh;
    B += (size_t)b * sBb + (size_t)h * sBh;
    C += (size_t)b * sCb + (size_t)h * sCh;

    int tid = threadIdx.x;
    int tx = tid & 15, ty = tid >> 4;
    int m0 = blockIdx.y * 128, n0 = blockIdx.x * 128;

    float acc[8][8];
#pragma unroll
    for (int i = 0; i < 8; i++)
#pragma unroll
        for (int j = 0; j < 8; j++) acc[i][j] = 0.f;

    for (int k0 = 0; k0 < K; k0 += 16) {
#pragma unroll
        for (int i = 0; i < 8; i++) {
            int idx = tid + i * 256;
            int m = idx >> 4, kk = idx & 15;
            As[kk][m] = A[(size_t)(m0 + m) * lda + k0 + kk];
            Bs[kk][m] = B[(size_t)(n0 + m) * ldb + k0 + kk];
        }
        __syncthreads();
#pragma unroll
        for (int kk = 0; kk < 16; kk++) {
            float4 a0 = *(const float4*)&As[kk][ty * 8];
            float4 a1 = *(const float4*)&As[kk][ty * 8 + 4];
            float4 b0 = *(const float4*)&Bs[kk][tx * 8];
            float4 b1 = *(const float4*)&Bs[kk][tx * 8 + 4];
            float av[8] = {a0.x, a0.y, a0.z, a0.w, a1.x, a1.y, a1.z, a1.w};
            float bv[8] = {b0.x, b0.y, b0.z, b0.w, b1.x, b1.y, b1.z, b1.w};
#pragma unroll
            for (int i = 0; i < 8; i++)
#pragma unroll
                for (int j = 0; j < 8; j++) acc[i][j] += av[i] * bv[j];
        }
        __syncthreads();
    }
#pragma unroll
    for (int i = 0; i < 8; i++) {
        int m = m0 + ty * 8 + i;
        float out[8];
#pragma unroll
        for (int j = 0; j < 8; j++) {
            out[j] = acc[i][j] * alpha;
            if (bias) out[j] += bias[n0 + tx * 8 + j];
        }
        float4* cp = (float4*)&C[(size_t)m * ldc + n0 + tx * 8];
        cp[0] = make_float4(out[0], out[1], out[2], out[3]);
        cp[1] = make_float4(out[4], out[5], out[6], out[7]);
    }
}

// ---------------------------------------------------------------------------
// 64x64 SGEMM (NT/NN) kept for the gated AV path (N=64).
// ---------------------------------------------------------------------------
__global__ __launch_bounds__(256)
void gemm_bt(const float* __restrict__ A, int lda, long sAb, long sAh,
             const float* __restrict__ B, int ldb, long sBb, long sBh,
             float* __restrict__ C, int ldc, long sCb, long sCh,
             int M, int N, int K, float alpha,
             const float* __restrict__ bias, int nh, int bTrans,
             const int* __restrict__ gate)
{
    __shared__ float As[16][65];
    __shared__ float Bs[16][65];
    int z = blockIdx.z;
    int b = z / nh, h = z % nh;
    if (gate && gate[b] != 0) return;
    A += (size_t)b * sAb + (size_t)h * sAh;
    B += (size_t)b * sBb + (size_t)h * sBh;
    C += (size_t)b * sCb + (size_t)h * sCh;

    int tid = threadIdx.x;
    int tx = tid & 15, ty = tid >> 4;
    int m0 = blockIdx.y * 64, n0 = blockIdx.x * 64;

    float acc[4][4];
#pragma unroll
    for (int i = 0; i < 4; i++)
#pragma unroll
        for (int j = 0; j < 4; j++) acc[i][j] = 0.f;

    for (int k0 = 0; k0 < K; k0 += 16) {
#pragma unroll
        for (int i = 0; i < 4; i++) {
            int idx = tid + i * 256;
            int m = idx >> 4, kk = idx & 15;
            As[kk][m] = A[(size_t)(m0 + m) * lda + k0 + kk];
        }
        if (bTrans) {
#pragma unroll
            for (int i = 0; i < 4; i++) {
                int idx = tid + i * 256;
                int n = idx >> 4, kk = idx & 15;
                Bs[kk][n] = B[(size_t)(n0 + n) * ldb + k0 + kk];
            }
        } else {
#pragma unroll
            for (int i = 0; i < 4; i++) {
                int idx = tid + i * 256;
                int n = idx & 63, kk = idx >> 6;
                Bs[kk][n] = B[(size_t)(k0 + kk) * ldb + n0 + n];
            }
        }
        __syncthreads();
#pragma unroll
        for (int kk = 0; kk < 16; kk++) {
            float a[4], bb[4];
#pragma unroll
            for (int i = 0; i < 4; i++) a[i] = As[kk][ty * 4 + i];
#pragma unroll
            for (int j = 0; j < 4; j++) bb[j] = Bs[kk][tx * 4 + j];
#pragma unroll
            for (int i = 0; i < 4; i++)
#pragma unroll
                for (int j = 0; j < 4; j++) acc[i][j] += a[i] * bb[j];
        }
        __syncthreads();
    }
#pragma unroll
    for (int i = 0; i < 4; i++) {
        int m = m0 + ty * 4 + i;
#pragma unroll
        for (int j = 0; j < 4; j++) {
            int n = n0 + tx * 4 + j;
            float v = acc[i][j] * alpha;
            if (bias) v += bias[n];
            C[(size_t)m * ldc + n] = v;
        }
    }
}

// ---------------------------------------------------------------------------
__global__ __launch_bounds__(256)
void pool1_kernel(const float* __restrict__ x)
{
    int blk = blockIdx.x;
    int b = blk >> 3, c = blk & 7;
    int tid = threadIdx.x;
    const float2* xp = (const float2*)(x + ((size_t)b * LL + c * 128) * DD) + tid;
    float s0 = 0.f, s1 = 0.f;
    for (int l = 0; l < 128; l++) {
        float2 v = xp[(size_t)l * (DD / 2)];
        s0 += v.x; s1 += v.y;
    }
    g_pool_part[blk][tid * 2]     = s0;
    g_pool_part[blk][tid * 2 + 1] = s1;
}

// ---------------------------------------------------------------------------
// Pattern selector MLP, warp-per-output-row (coalesced weight reads).
// ---------------------------------------------------------------------------
__global__ __launch_bounds__(256)
void pattern_kernel(const float* __restrict__ w1, const float* __restrict__ b1,
                    const float* __restrict__ w2, const float* __restrict__ b2,
                    const float* __restrict__ w3, const float* __restrict__ b3,
                    const float* __restrict__ pbias)
{
    int b = blockIdx.x, tid = threadIdx.x;
    int warp = tid >> 5, lane = tid & 31;
    __shared__ float pooled[DD];
    __shared__ float h1[DD];
    __shared__ float h2[DD / 2];
    __shared__ float lg[3];

    for (int d = tid; d < DD; d += 256) {
        float s = 0.f;
#pragma unroll
        for (int c = 0; c < 8; c++) s += g_pool_part[b * 8 + c][d];
        pooled[d] = s * (1.0f / LL);
    }
    __syncthreads();
    for (int i = warp; i < DD; i += 8) {
        const float* wr = w1 + (size_t)i * DD;
        float a = 0.f;
        for (int k = lane; k < DD; k += 32) a += pooled[k] * wr[k];
#pragma unroll
        for (int o = 16; o > 0; o >>= 1) a += __shfl_xor_sync(~0u, a, o);
        if (lane == 0) h1[i] = fmaxf(a + b1[i], 0.f);
    }
    __syncthreads();
    for (int i = warp; i < DD / 2; i += 8) {
        const float* wr = w2 + (size_t)i * DD;
        float a = 0.f;
        for (int k = lane; k < DD; k += 32) a += h1[k] * wr[k];
#pragma unroll
        for (int o = 16; o > 0; o >>= 1) a += __shfl_xor_sync(~0u, a, o);
        if (lane == 0) h2[i] = fmaxf(a + b2[i], 0.f);
    }
    __syncthreads();
    if (warp < 3) {
        const float* wr = w3 + (size_t)warp * (DD / 2);
        float a = 0.f;
        for (int k = lane; k < DD / 2; k += 32) a += h2[k] * wr[k];
#pragma unroll
        for (int o = 16; o > 0; o >>= 1) a += __shfl_xor_sync(~0u, a, o);
        if (lane == 0) lg[warp] = (a + b3[warp] + pbias[warp]) / 0.3f;
    }
    __syncthreads();
    if (tid == 0) {
        float m = fmaxf(lg[0], fmaxf(lg[1], lg[2]));
        float e0 = expf(lg[0] - m), e1 = expf(lg[1] - m), e2 = expf(lg[2] - m);
        float inv = 1.f / (e0 + e1 + e2);
        float p0 = e0 * inv, p1 = e1 * inv, p2 = e2 * inv;
        g_pw[b * 3 + 0] = p0;
        g_pw[b * 3 + 1] = p1;
        g_pw[b * 3 + 2] = p2;
        bool A00 = p1 > THRESH;
        bool A01 = (p1 + p2) > THRESH;
        bool A10 = (p0 + p1) > THRESH;
        bool A11 = ((p0 + p1) + p2) > THRESH;
        bool need_sparse = (A00 != A01) || (A10 != A11);
        int mode;
        if (need_sparse || A00) mode = 0;
        else if (A10)           mode = 1;
        else                    mode = 2;
        g_mode[b] = mode;
    }
}

// ---------------------------------------------------------------------------
// Local-window fused attention (mode 1) + all-masked fallback (mode 2).
// ---------------------------------------------------------------------------
__global__ __launch_bounds__(256)
void local_attn_kernel()
{
    __shared__ float ksh[48][65];
    __shared__ float vsh[48][65];
    __shared__ float qsh[16][64];
    __shared__ float psh[16][33];

    int blk = blockIdx.x;
    int b = blk >> 9;
    int h = (blk >> 6) & 7;
    int q0 = (blk & 63) * 16;
    int mode = g_mode[b];
    if (mode == 0) return;
    int tid = threadIdx.x;
    const float* base = g_qkv + (size_t)b * LL * QKVD + h * HD;

    if (mode == 2) {
        const float* v0 = base + 2 * DD;
#pragma unroll
        for (int i = 0; i < 4; i++) {
            int idx = tid + i * 256;
            int r = idx >> 6, d = idx & 63;
            g_attn[(size_t)(b * LL + q0 + r) * DD + h * HD + d] = v0[d];
        }
        return;
    }

    int kb0 = max(q0 - 16, 0);
    int kend = min(q0 + 15 + 16, LL - 1);
    int klen = kend - kb0 + 1;

    for (int i = tid; i < klen * 64; i += 256) {
        int jj = i >> 6, d = i & 63;
        const float* src = base + (size_t)(kb0 + jj) * QKVD;
        ksh[jj][d] = src[DD + d];
        vsh[jj][d] = src[2 * DD + d];
    }
#pragma unroll
    for (int i = 0; i < 4; i++) {
        int idx = tid + i * 256;
        int r = idx >> 6, d = idx & 63;
        qsh[r][d] = base[(size_t)(q0 + r) * QKVD + d];
    }
    __syncthreads();

    int warp = tid >> 5, lane = tid & 31;
#pragma unroll
    for (int rr = 0; rr < 2; rr++) {
        int r = warp * 2 + rr;
        int q = q0 + r;
        int w0 = max(q - 16, 0), w1 = min(q + 16, LL - 1);
        int cnt = w1 - w0 + 1;
        int off = w0 - kb0;

        float s0 = NEG_INF, s1 = NEG_INF;
        if (lane < cnt) {
            float acc = 0.f;
#pragma unroll
            for (int d = 0; d < 64; d++) acc += qsh[r][d] * ksh[off + lane][d];
            s0 = acc * SCALE;
        }
        if (lane + 32 < cnt) {
            float acc = 0.f;
#pragma unroll
            for (int d = 0; d < 64; d++) acc += qsh[r][d] * ksh[off + lane + 32][d];
            s1 = acc * SCALE;
        }
        float m = fmaxf(s0, s1);
#pragma unroll
        for (int o = 16; o > 0; o >>= 1) m = fmaxf(m, __shfl_xor_sync(~0u, m, o));
        float e0 = (lane < cnt) ? __expf(s0 - m) : 0.f;
        float e1 = (lane + 32 < cnt) ? __expf(s1 - m) : 0.f;
        float sum = e0 + e1;
#pragma unroll
        for (int o = 16; o > 0; o >>= 1) sum += __shfl_xor_sync(~0u, sum, o);
        float inv = 1.f / sum;
        if (lane < cnt) psh[r][lane] = e0 * inv;
        if (lane + 32 < cnt) psh[r][lane + 32] = e1 * inv;
        __syncwarp();

        float o0 = 0.f, o1 = 0.f;
        for (int jj = 0; jj < cnt; jj++) {
            float p = psh[r][jj];
            o0 += p * vsh[off + jj][lane];
            o1 += p * vsh[off + jj][lane + 32];
        }
        float* dst = g_attn + (size_t)(b * LL + q) * DD + h * HD;
        dst[lane] = o0;
        dst[lane + 32] = o1;
    }
}

// ---------------------------------------------------------------------------
// Full-path mask + softmax (mode 0 only). 4 rows per block.
// ---------------------------------------------------------------------------
__device__ __forceinline__ unsigned fkey(float f) {
    unsigned u = __float_as_uint(f);
    return (u & 0x80000000u) ? ~u : (u | 0x80000000u);
}

__global__ __launch_bounds__(256)
void softmax_kernel(const float* __restrict__ sparse_w,
                    const float* __restrict__ sparse_b)
{
    __shared__ float s[LL];
    __shared__ float red[256];
    __shared__ unsigned hist[256];
    __shared__ unsigned sel_prefix, sel_k;
    __shared__ float mx_sh;

    int grp = blockIdx.x;               // 0..8191, 4 rows each
    int z = grp >> 8;                   // (b,h)
    int b = z >> 3, h = z & 7;
    if (g_mode[b] != 0) return;
    int q_base = (grp & 255) * 4;
    int tid = threadIdx.x;

    float p0 = g_pw[b * 3 + 0];
    float p1 = g_pw[b * 3 + 1];
    float p2 = g_pw[b * 3 + 2];
    bool A00 = p1 > THRESH;
    bool A01 = (p1 + p2) > THRESH;
    bool A10 = (p0 + p1) > THRESH;
    bool A11 = ((p0 + p1) + p2) > THRESH;
    bool need_sparse = (A00 != A01) || (A10 != A11);
    float w_h = sparse_w[h], b_h = sparse_b[h];

    for (int r = 0; r < 4; r++) {
        int q = q_base + r;
        float* srow = g_scores + ((size_t)z << 20) + ((size_t)q << 10);
        ((float4*)s)[tid] = ((const float4*)srow)[tid];
        __syncthreads();

        unsigned tu = 0u;
        if (need_sparse) {
            if (tid == 0) { sel_prefix = 0u; sel_k = KTOP; }
            __syncthreads();
            for (int shift = 24; shift >= 0; shift -= 8) {
                hist[tid] = 0u;
                __syncthreads();
                unsigned pref = sel_prefix;
                unsigned hm = (shift == 24) ? 0u : (0xFFFFFFFFu << (shift + 8));
                for (int j = tid; j < LL; j += 256) {
                    float v = __fadd_rn(__fmul_rn(s[j], w_h), b_h);
                    unsigned u = fkey(v);
                    if ((u & hm) == pref) atomicAdd(&hist[(u >> shift) & 255u], 1u);
                }
                __syncthreads();
                if (tid == 0) {
                    unsigned k = sel_k, cum = 0;
                    for (int dgt = 255; dgt >= 0; --dgt) {
                        unsigned c = hist[dgt];
                        if (cum + c >= k) {
                            sel_prefix = pref | ((unsigned)dgt << shift);
                            sel_k = k - cum;
                            break;
                        }
                        cum += c;
                    }
                }
                __syncthreads();
            }
            tu = sel_prefix;
            __syncthreads();
        }

        float v[4];
        float lm = NEG_INF;
#pragma unroll
        for (int i = 0; i < 4; i++) {
            int j = tid * 4 + i;
            float sv = s[j];
            bool lf = (abs(q - j) <= 16);
            bool allow;
            if (need_sparse) {
                float s2 = __fadd_rn(__fmul_rn(sv, w_h), b_h);
                float sf = (fkey(s2) >= tu) ? 1.f : 0.f;
                float comb = (p0 * (lf ? 1.f : 0.f) + p1) + p2 * sf;
                allow = comb > THRESH;
            } else {
                allow = lf ? A10 : A00;
            }
            v[i] = allow ? sv : NEG_INF;
            lm = fmaxf(lm, v[i]);
        }
        red[tid] = lm; __syncthreads();
        for (int o = 128; o > 0; o >>= 1) {
            if (tid < o) red[tid] = fmaxf(red[tid], red[tid + o]);
            __syncthreads();
        }
        if (tid == 0) mx_sh = red[0];
        __syncthreads();
        float mx = mx_sh;

        if (mx == NEG_INF) {
            float4 o;
            o.x = (tid == 0) ? 1.f : 0.f; o.y = 0.f; o.z = 0.f; o.w = 0.f;
            ((float4*)srow)[tid] = o;
            __syncthreads();
            continue;
        }

        float ls = 0.f;
#pragma unroll
        for (int i = 0; i < 4; i++) {
            v[i] = __expf(v[i] - mx);
            ls += v[i];
        }
        red[tid] = ls; __syncthreads();
        for (int o = 128; o > 0; o >>= 1) {
            if (tid < o) red[tid] += red[tid + o];
            __syncthreads();
        }
        if (tid == 0) mx_sh = 1.f / red[0];
        __syncthreads();
        float inv = mx_sh;
        float4 o;
        o.x = v[0] * inv; o.y = v[1] * inv; o.z = v[2] * inv; o.w = v[3] * inv;
        ((float4*)srow)[tid] = o;
        __syncthreads();
    }
}

// ---------------------------------------------------------------------------
extern "C" void kernel_launch(void* const* d_in, const int* in_sizes, int n_in,
                              void* d_out, int out_size)
{
    const float* x        = (const float*)d_in[0];
    const float* qkv_w    = (const float*)d_in[1];
    const float* proj_w   = (const float*)d_in[2];
    const float* proj_b   = (const float*)d_in[3];
    const float* ps_w1    = (const float*)d_in[4];
    const float* ps_b1    = (const float*)d_in[5];
    const float* ps_w2    = (const float*)d_in[6];
    const float* ps_b2    = (const float*)d_in[7];
    const float* ps_w3    = (const float*)d_in[8];
    const float* ps_b3    = (const float*)d_in[9];
    const float* pbias    = (const float*)d_in[10];
    const float* sparse_w = (const float*)d_in[11];
    const float* sparse_b = (const float*)d_in[12];
    float* out = (float*)d_out;

    float *qkv_p, *sc_p, *attn_p;
    int *mode_p;
    cudaGetSymbolAddress((void**)&qkv_p,  g_qkv);
    cudaGetSymbolAddress((void**)&sc_p,   g_scores);
    cudaGetSymbolAddress((void**)&attn_p, g_attn);
    cudaGetSymbolAddress((void**)&mode_p, g_mode);

    pool1_kernel<<<32, 256>>>(x);
    pattern_kernel<<<BB, 256>>>(ps_w1, ps_b1, ps_w2, ps_b2, ps_w3, ps_b3, pbias);

    // QKV projection: (4096,1536) = x @ qkv_w^T
    gemm128<<<dim3(QKVD / 128, ML / 128, 1), 256>>>(
        x, DD, 0, 0,  qkv_w, DD, 0, 0,  qkv_p, QKVD, 0, 0,
        DD, 1.f, nullptr, 1, nullptr);

    // ---- full path (gated on mode==0) ----
    gemm128<<<dim3(LL / 128, LL / 128, BB * HH), 256>>>(
        qkv_p, QKVD, (long)LL * QKVD, HD,
        qkv_p + DD, QKVD, (long)LL * QKVD, HD,
        sc_p, LL, (long)HH * LL * LL, (long)LL * LL,
        HD, SCALE, nullptr, HH, mode_p);
    softmax_kernel<<<BB * HH * (LL / 4), 256>>>(sparse_w, sparse_b);
    gemm_bt<<<dim3(HD / 64, LL / 64, BB * HH), 256>>>(
        sc_p, LL, (long)HH * LL * LL, (long)LL * LL,
        qkv_p + 2 * DD, QKVD, (long)LL * QKVD, HD,
        attn_p, DD, (long)LL * DD, HD,
        LL, HD, LL, 1.f, nullptr, HH, 0, mode_p);

    // ---- local/all-masked path (gated on mode!=0) ----
    local_attn_kernel<<<BB * HH * (LL / 16), 256>>>();

    // Output projection
    gemm128<<<dim3(DD / 128, ML / 128, 1), 256>>>(
        attn_p, DD, 0, 0,  proj_w, DD, 0, 0,  out, DD, 0, 0,
        DD, 1.f, proj_b, 1, nullptr);
}

// round 6
// speedup vs baseline: 5.7408x; 1.1965x over previous
#include <cuda_runtime.h>
#include <cuda_bf16.h>
#include <cstdint>
#include <math.h>

#define BB 4
#define LL 1024
#define DD 512
#define HH 8
#define HD 64
#define QKVD 1536
#define ML (BB*LL)
#define K3 1536              // 3 * 512 split-K for bf16x2 GEMM
#define KTOP 716
#define THRESH 0.05f
#define SCALE 0.125f
#define NEG_INF __int_as_float(0xff800000)

// Scratch (device globals; no allocations allowed)
__device__ float g_qkv[ML * QKVD];
__device__ float g_scores[(size_t)BB * HH * LL * LL];
__device__ float g_attn[ML * DD];
__device__ float g_pw[BB * 3];
__device__ int   g_mode[BB];
__device__ float g_pool_part[32][DD];
// bf16x2 split buffers
__device__ __nv_bfloat16 g_xhl[ML * K3];
__device__ __nv_bfloat16 g_wqhl[QKVD * K3];
__device__ __nv_bfloat16 g_ahl[ML * K3];
__device__ __nv_bfloat16 g_pwhl[DD * K3];

// ---------------------------------------------------------------------------
// fp32 -> bf16 hi/lo split. Astyle: [hi | lo | hi]. Bstyle: [hi | hi | lo].
// ---------------------------------------------------------------------------
template<int ASTYLE>
__global__ __launch_bounds__(256)
void cvt_split(const float* __restrict__ src, __nv_bfloat16* __restrict__ dst, int M)
{
    int i = blockIdx.x * 256 + threadIdx.x;     // one float4 per thread
    int total = M * (DD / 4);
    if (i >= total) return;
    int m = i / (DD / 4), c = i % (DD / 4);
    float4 v = ((const float4*)(src + (size_t)m * DD))[c];
    __nv_bfloat16 hi[4], lo[4];
    float vv[4] = {v.x, v.y, v.z, v.w};
#pragma unroll
    for (int t = 0; t < 4; t++) {
        hi[t] = __float2bfloat16(vv[t]);
        lo[t] = __float2bfloat16(vv[t] - __bfloat162float(hi[t]));
    }
    __nv_bfloat16* d = dst + (size_t)m * K3 + c * 4;
    __nv_bfloat162* d0 = (__nv_bfloat162*)(d);
    __nv_bfloat162* d1 = (__nv_bfloat162*)(d + DD);
    __nv_bfloat162* d2 = (__nv_bfloat162*)(d + 2 * DD);
    __nv_bfloat162 hp0 = {hi[0], hi[1]}, hp1 = {hi[2], hi[3]};
    __nv_bfloat162 lp0 = {lo[0], lo[1]}, lp1 = {lo[2], lo[3]};
    d0[0] = hp0; d0[1] = hp1;
    if (ASTYLE) {
        d1[0] = lp0; d1[1] = lp1;      // A: [hi, lo, hi]
        d2[0] = hp0; d2[1] = hp1;
    } else {
        d1[0] = hp0; d1[1] = hp1;      // B: [hi, hi, lo]
        d2[0] = lp0; d2[1] = lp1;
    }
}

// ---------------------------------------------------------------------------
// bf16 NT GEMM via mma.sync m16n8k16: C[M,N] = A2[M,K3] @ B2[N,K3]^T (+bias)
// 128x128 tile, 8 warps (4m x 2n), warp tile 32x64, KB=64.
// ---------------------------------------------------------------------------
__device__ __forceinline__ uint32_t smem_u32(const void* p) {
    return (uint32_t)__cvta_generic_to_shared(p);
}

__global__ __launch_bounds__(256, 2)
void gemm_mma(const __nv_bfloat16* __restrict__ A2,
              const __nv_bfloat16* __restrict__ B2,
              float* __restrict__ C, int ldc, int N,
              const float* __restrict__ bias)
{
    __shared__ __nv_bfloat16 As[128][72];
    __shared__ __nv_bfloat16 Bs[128][72];
    int tid = threadIdx.x;
    int warp = tid >> 5, lane = tid & 31;
    int wm = warp >> 1, wn = warp & 1;
    int m0 = blockIdx.y * 128, n0 = blockIdx.x * 128;
    int m0w = wm * 32, n0w = wn * 64;

    float acc[2][8][4];
#pragma unroll
    for (int a = 0; a < 2; a++)
#pragma unroll
        for (int b = 0; b < 8; b++)
#pragma unroll
            for (int c = 0; c < 4; c++) acc[a][b][c] = 0.f;

    int lrow = tid >> 3, lch = tid & 7;
    for (int k0 = 0; k0 < K3; k0 += 64) {
#pragma unroll
        for (int p = 0; p < 4; p++) {
            int r = lrow + p * 32;
            *(uint4*)&As[r][lch * 8] =
                *(const uint4*)&A2[(size_t)(m0 + r) * K3 + k0 + lch * 8];
            *(uint4*)&Bs[r][lch * 8] =
                *(const uint4*)&B2[(size_t)(n0 + r) * K3 + k0 + lch * 8];
        }
        __syncthreads();
#pragma unroll
        for (int kk = 0; kk < 64; kk += 16) {
            uint32_t a[2][4];
#pragma unroll
            for (int mt = 0; mt < 2; mt++) {
                int mrow = m0w + mt * 16 + (lane & 15);
                int kcol = kk + ((lane >> 4) << 3);
                uint32_t ad = smem_u32(&As[mrow][kcol]);
                asm volatile("ldmatrix.sync.aligned.m8n8.x4.shared.b16 {%0,%1,%2,%3}, [%4];"
                    : "=r"(a[mt][0]), "=r"(a[mt][1]), "=r"(a[mt][2]), "=r"(a[mt][3])
                    : "r"(ad));
            }
            uint32_t bfr[4][4];
#pragma unroll
            for (int g = 0; g < 4; g++) {
                int nrow = n0w + g * 16 + ((lane >> 4) << 3) + (lane & 7);
                int kcol = kk + (((lane >> 3) & 1) << 3);
                uint32_t ad = smem_u32(&Bs[nrow][kcol]);
                asm volatile("ldmatrix.sync.aligned.m8n8.x4.shared.b16 {%0,%1,%2,%3}, [%4];"
                    : "=r"(bfr[g][0]), "=r"(bfr[g][1]), "=r"(bfr[g][2]), "=r"(bfr[g][3])
                    : "r"(ad));
            }
#pragma unroll
            for (int mt = 0; mt < 2; mt++)
#pragma unroll
                for (int nt = 0; nt < 8; nt++) {
                    int g = nt >> 1, pr = (nt & 1) * 2;
                    asm volatile(
                        "mma.sync.aligned.m16n8k16.row.col.f32.bf16.bf16.f32 "
                        "{%0,%1,%2,%3}, {%4,%5,%6,%7}, {%8,%9}, {%0,%1,%2,%3};"
                        : "+f"(acc[mt][nt][0]), "+f"(acc[mt][nt][1]),
                          "+f"(acc[mt][nt][2]), "+f"(acc[mt][nt][3])
                        : "r"(a[mt][0]), "r"(a[mt][1]), "r"(a[mt][2]), "r"(a[mt][3]),
                          "r"(bfr[g][pr]), "r"(bfr[g][pr + 1]));
                }
        }
        __syncthreads();
    }

    // epilogue
#pragma unroll
    for (int mt = 0; mt < 2; mt++) {
        int mA = m0 + m0w + mt * 16 + (lane >> 2);
#pragma unroll
        for (int nt = 0; nt < 8; nt++) {
            int n = n0 + n0w + nt * 8 + (lane & 3) * 2;
            if (n >= N) continue;
            float b0 = bias ? bias[n] : 0.f;
            float b1 = bias ? bias[n + 1] : 0.f;
            *(float2*)&C[(size_t)mA * ldc + n] =
                make_float2(acc[mt][nt][0] + b0, acc[mt][nt][1] + b1);
            *(float2*)&C[(size_t)(mA + 8) * ldc + n] =
                make_float2(acc[mt][nt][2] + b0, acc[mt][nt][3] + b1);
        }
    }
}

// ---------------------------------------------------------------------------
// 128x128 fp32 SGEMM (NT) for the gated full-path scores.
// ---------------------------------------------------------------------------
__global__ __launch_bounds__(256)
void gemm128(const float* __restrict__ A, int lda, long sAb, long sAh,
             const float* __restrict__ B, int ldb, long sBb, long sBh,
             float* __restrict__ C, int ldc, long sCb, long sCh,
             int K, float alpha, const float* __restrict__ bias,
             int nh, const int* __restrict__ gate)
{
    __shared__ float As[16][132];
    __shared__ float Bs[16][132];
    int z = blockIdx.z;
    int b = z / nh, h = z % nh;
    if (gate && gate[b] != 0) return;
    A += (size_t)b * sAb + (size_t)h * sAh;
    B += (size_t)b * sBb + (size_t)h * sBh;
    C += (size_t)b * sCb + (size_t)h * sCh;

    int tid = threadIdx.x;
    int tx = tid & 15, ty = tid >> 4;
    int m0 = blockIdx.y * 128, n0 = blockIdx.x * 128;

    float acc[8][8];
#pragma unroll
    for (int i = 0; i < 8; i++)
#pragma unroll
        for (int j = 0; j < 8; j++) acc[i][j] = 0.f;

    for (int k0 = 0; k0 < K; k0 += 16) {
#pragma unroll
        for (int i = 0; i < 8; i++) {
            int idx = tid + i * 256;
            int m = idx >> 4, kk = idx & 15;
            As[kk][m] = A[(size_t)(m0 + m) * lda + k0 + kk];
            Bs[kk][m] = B[(size_t)(n0 + m) * ldb + k0 + kk];
        }
        __syncthreads();
#pragma unroll
        for (int kk = 0; kk < 16; kk++) {
            float4 a0 = *(const float4*)&As[kk][ty * 8];
            float4 a1 = *(const float4*)&As[kk][ty * 8 + 4];
            float4 b0 = *(const float4*)&Bs[kk][tx * 8];
            float4 b1 = *(const float4*)&Bs[kk][tx * 8 + 4];
            float av[8] = {a0.x, a0.y, a0.z, a0.w, a1.x, a1.y, a1.z, a1.w};
            float bv[8] = {b0.x, b0.y, b0.z, b0.w, b1.x, b1.y, b1.z, b1.w};
#pragma unroll
            for (int i = 0; i < 8; i++)
#pragma unroll
                for (int j = 0; j < 8; j++) acc[i][j] += av[i] * bv[j];
        }
        __syncthreads();
    }
#pragma unroll
    for (int i = 0; i < 8; i++) {
        int m = m0 + ty * 8 + i;
        float out[8];
#pragma unroll
        for (int j = 0; j < 8; j++) {
            out[j] = acc[i][j] * alpha;
            if (bias) out[j] += bias[n0 + tx * 8 + j];
        }
        float4* cp = (float4*)&C[(size_t)m * ldc + n0 + tx * 8];
        cp[0] = make_float4(out[0], out[1], out[2], out[3]);
        cp[1] = make_float4(out[4], out[5], out[6], out[7]);
    }
}

// ---------------------------------------------------------------------------
// 64x64 SGEMM (NT/NN) for the gated AV path.
// ---------------------------------------------------------------------------
__global__ __launch_bounds__(256)
void gemm_bt(const float* __restrict__ A, int lda, long sAb, long sAh,
             const float* __restrict__ B, int ldb, long sBb, long sBh,
             float* __restrict__ C, int ldc, long sCb, long sCh,
             int M, int N, int K, float alpha,
             const float* __restrict__ bias, int nh, int bTrans,
             const int* __restrict__ gate)
{
    __shared__ float As[16][65];
    __shared__ float Bs[16][65];
    int z = blockIdx.z;
    int b = z / nh, h = z % nh;
    if (gate && gate[b] != 0) return;
    A += (size_t)b * sAb + (size_t)h * sAh;
    B += (size_t)b * sBb + (size_t)h * sBh;
    C += (size_t)b * sCb + (size_t)h * sCh;

    int tid = threadIdx.x;
    int tx = tid & 15, ty = tid >> 4;
    int m0 = blockIdx.y * 64, n0 = blockIdx.x * 64;

    float acc[4][4];
#pragma unroll
    for (int i = 0; i < 4; i++)
#pragma unroll
        for (int j = 0; j < 4; j++) acc[i][j] = 0.f;

    for (int k0 = 0; k0 < K; k0 += 16) {
#pragma unroll
        for (int i = 0; i < 4; i++) {
            int idx = tid + i * 256;
            int m = idx >> 4, kk = idx & 15;
            As[kk][m] = A[(size_t)(m0 + m) * lda + k0 + kk];
        }
        if (bTrans) {
#pragma unroll
            for (int i = 0; i < 4; i++) {
                int idx = tid + i * 256;
                int n = idx >> 4, kk = idx & 15;
                Bs[kk][n] = B[(size_t)(n0 + n) * ldb + k0 + kk];
            }
        } else {
#pragma unroll
            for (int i = 0; i < 4; i++) {
                int idx = tid + i * 256;
                int n = idx & 63, kk = idx >> 6;
                Bs[kk][n] = B[(size_t)(k0 + kk) * ldb + n0 + n];
            }
        }
        __syncthreads();
#pragma unroll
        for (int kk = 0; kk < 16; kk++) {
            float a[4], bb[4];
#pragma unroll
            for (int i = 0; i < 4; i++) a[i] = As[kk][ty * 4 + i];
#pragma unroll
            for (int j = 0; j < 4; j++) bb[j] = Bs[kk][tx * 4 + j];
#pragma unroll
            for (int i = 0; i < 4; i++)
#pragma unroll
                for (int j = 0; j < 4; j++) acc[i][j] += a[i] * bb[j];
        }
        __syncthreads();
    }
#pragma unroll
    for (int i = 0; i < 4; i++) {
        int m = m0 + ty * 4 + i;
#pragma unroll
        for (int j = 0; j < 4; j++) {
            int n = n0 + tx * 4 + j;
            float v = acc[i][j] * alpha;
            if (bias) v += bias[n];
            C[(size_t)m * ldc + n] = v;
        }
    }
}

// ---------------------------------------------------------------------------
__global__ __launch_bounds__(256)
void pool1_kernel(const float* __restrict__ x)
{
    int blk = blockIdx.x;
    int b = blk >> 3, c = blk & 7;
    int tid = threadIdx.x;
    const float2* xp = (const float2*)(x + ((size_t)b * LL + c * 128) * DD) + tid;
    float s0 = 0.f, s1 = 0.f;
    for (int l = 0; l < 128; l++) {
        float2 v = xp[(size_t)l * (DD / 2)];
        s0 += v.x; s1 += v.y;
    }
    g_pool_part[blk][tid * 2]     = s0;
    g_pool_part[blk][tid * 2 + 1] = s1;
}

// ---------------------------------------------------------------------------
__global__ __launch_bounds__(256)
void pattern_kernel(const float* __restrict__ w1, const float* __restrict__ b1,
                    const float* __restrict__ w2, const float* __restrict__ b2,
                    const float* __restrict__ w3, const float* __restrict__ b3,
                    const float* __restrict__ pbias)
{
    int b = blockIdx.x, tid = threadIdx.x;
    int warp = tid >> 5, lane = tid & 31;
    __shared__ float pooled[DD];
    __shared__ float h1[DD];
    __shared__ float h2[DD / 2];
    __shared__ float lg[3];

    for (int d = tid; d < DD; d += 256) {
        float s = 0.f;
#pragma unroll
        for (int c = 0; c < 8; c++) s += g_pool_part[b * 8 + c][d];
        pooled[d] = s * (1.0f / LL);
    }
    __syncthreads();
    for (int i = warp; i < DD; i += 8) {
        const float* wr = w1 + (size_t)i * DD;
        float a = 0.f;
        for (int k = lane; k < DD; k += 32) a += pooled[k] * wr[k];
#pragma unroll
        for (int o = 16; o > 0; o >>= 1) a += __shfl_xor_sync(~0u, a, o);
        if (lane == 0) h1[i] = fmaxf(a + b1[i], 0.f);
    }
    __syncthreads();
    for (int i = warp; i < DD / 2; i += 8) {
        const float* wr = w2 + (size_t)i * DD;
        float a = 0.f;
        for (int k = lane; k < DD; k += 32) a += h1[k] * wr[k];
#pragma unroll
        for (int o = 16; o > 0; o >>= 1) a += __shfl_xor_sync(~0u, a, o);
        if (lane == 0) h2[i] = fmaxf(a + b2[i], 0.f);
    }
    __syncthreads();
    if (warp < 3) {
        const float* wr = w3 + (size_t)warp * (DD / 2);
        float a = 0.f;
        for (int k = lane; k < DD / 2; k += 32) a += h2[k] * wr[k];
#pragma unroll
        for (int o = 16; o > 0; o >>= 1) a += __shfl_xor_sync(~0u, a, o);
        if (lane == 0) lg[warp] = (a + b3[warp] + pbias[warp]) / 0.3f;
    }
    __syncthreads();
    if (tid == 0) {
        float m = fmaxf(lg[0], fmaxf(lg[1], lg[2]));
        float e0 = expf(lg[0] - m), e1 = expf(lg[1] - m), e2 = expf(lg[2] - m);
        float inv = 1.f / (e0 + e1 + e2);
        float p0 = e0 * inv, p1 = e1 * inv, p2 = e2 * inv;
        g_pw[b * 3 + 0] = p0;
        g_pw[b * 3 + 1] = p1;
        g_pw[b * 3 + 2] = p2;
        bool A00 = p1 > THRESH;
        bool A01 = (p1 + p2) > THRESH;
        bool A10 = (p0 + p1) > THRESH;
        bool A11 = ((p0 + p1) + p2) > THRESH;
        bool need_sparse = (A00 != A01) || (A10 != A11);
        int mode;
        if (need_sparse || A00) mode = 0;
        else if (A10)           mode = 1;
        else                    mode = 2;
        g_mode[b] = mode;
    }
}

// ---------------------------------------------------------------------------
// Local-window fused attention (mode 1) + all-masked fallback (mode 2).
// ---------------------------------------------------------------------------
__global__ __launch_bounds__(256)
void local_attn_kernel()
{
    __shared__ float ksh[48][65];
    __shared__ float vsh[48][65];
    __shared__ float qsh[16][64];
    __shared__ float psh[16][33];

    int blk = blockIdx.x;
    int b = blk >> 9;
    int h = (blk >> 6) & 7;
    int q0 = (blk & 63) * 16;
    int mode = g_mode[b];
    if (mode == 0) return;
    int tid = threadIdx.x;
    const float* base = g_qkv + (size_t)b * LL * QKVD + h * HD;

    if (mode == 2) {
        const float* v0 = base + 2 * DD;
#pragma unroll
        for (int i = 0; i < 4; i++) {
            int idx = tid + i * 256;
            int r = idx >> 6, d = idx & 63;
            g_attn[(size_t)(b * LL + q0 + r) * DD + h * HD + d] = v0[d];
        }
        return;
    }

    int kb0 = max(q0 - 16, 0);
    int kend = min(q0 + 15 + 16, LL - 1);
    int klen = kend - kb0 + 1;

    for (int i = tid; i < klen * 64; i += 256) {
        int jj = i >> 6, d = i & 63;
        const float* src = base + (size_t)(kb0 + jj) * QKVD;
        ksh[jj][d] = src[DD + d];
        vsh[jj][d] = src[2 * DD + d];
    }
#pragma unroll
    for (int i = 0; i < 4; i++) {
        int idx = tid + i * 256;
        int r = idx >> 6, d = idx & 63;
        qsh[r][d] = base[(size_t)(q0 + r) * QKVD + d];
    }
    __syncthreads();

    int warp = tid >> 5, lane = tid & 31;
#pragma unroll
    for (int rr = 0; rr < 2; rr++) {
        int r = warp * 2 + rr;
        int q = q0 + r;
        int w0 = max(q - 16, 0), w1 = min(q + 16, LL - 1);
        int cnt = w1 - w0 + 1;
        int off = w0 - kb0;

        float s0 = NEG_INF, s1 = NEG_INF;
        if (lane < cnt) {
            float acc = 0.f;
#pragma unroll
            for (int d = 0; d < 64; d++) acc += qsh[r][d] * ksh[off + lane][d];
            s0 = acc * SCALE;
        }
        if (lane + 32 < cnt) {
            float acc = 0.f;
#pragma unroll
            for (int d = 0; d < 64; d++) acc += qsh[r][d] * ksh[off + lane + 32][d];
            s1 = acc * SCALE;
        }
        float m = fmaxf(s0, s1);
#pragma unroll
        for (int o = 16; o > 0; o >>= 1) m = fmaxf(m, __shfl_xor_sync(~0u, m, o));
        float e0 = (lane < cnt) ? __expf(s0 - m) : 0.f;
        float e1 = (lane + 32 < cnt) ? __expf(s1 - m) : 0.f;
        float sum = e0 + e1;
#pragma unroll
        for (int o = 16; o > 0; o >>= 1) sum += __shfl_xor_sync(~0u, sum, o);
        float inv = 1.f / sum;
        if (lane < cnt) psh[r][lane] = e0 * inv;
        if (lane + 32 < cnt) psh[r][lane + 32] = e1 * inv;
        __syncwarp();

        float o0 = 0.f, o1 = 0.f;
        for (int jj = 0; jj < cnt; jj++) {
            float p = psh[r][jj];
            o0 += p * vsh[off + jj][lane];
            o1 += p * vsh[off + jj][lane + 32];
        }
        float* dst = g_attn + (size_t)(b * LL + q) * DD + h * HD;
        dst[lane] = o0;
        dst[lane + 32] = o1;
    }
}

// ---------------------------------------------------------------------------
// Full-path mask + softmax (mode 0 only). 4 rows per block.
// ---------------------------------------------------------------------------
__device__ __forceinline__ unsigned fkey(float f) {
    unsigned u = __float_as_uint(f);
    return (u & 0x80000000u) ? ~u : (u | 0x80000000u);
}

__global__ __launch_bounds__(256)
void softmax_kernel(const float* __restrict__ sparse_w,
                    const float* __restrict__ sparse_b)
{
    __shared__ float s[LL];
    __shared__ float red[256];
    __shared__ unsigned hist[256];
    __shared__ unsigned sel_prefix, sel_k;
    __shared__ float mx_sh;

    int grp = blockIdx.x;
    int z = grp >> 8;
    int b = z >> 3, h = z & 7;
    if (g_mode[b] != 0) return;
    int q_base = (grp & 255) * 4;
    int tid = threadIdx.x;

    float p0 = g_pw[b * 3 + 0];
    float p1 = g_pw[b * 3 + 1];
    float p2 = g_pw[b * 3 + 2];
    bool A00 = p1 > THRESH;
    bool A01 = (p1 + p2) > THRESH;
    bool A10 = (p0 + p1) > THRESH;
    bool A11 = ((p0 + p1) + p2) > THRESH;
    bool need_sparse = (A00 != A01) || (A10 != A11);
    float w_h = sparse_w[h], b_h = sparse_b[h];

    for (int r = 0; r < 4; r++) {
        int q = q_base + r;
        float* srow = g_scores + ((size_t)z << 20) + ((size_t)q << 10);
        ((float4*)s)[tid] = ((const float4*)srow)[tid];
        __syncthreads();

        unsigned tu = 0u;
        if (need_sparse) {
            if (tid == 0) { sel_prefix = 0u; sel_k = KTOP; }
            __syncthreads();
            for (int shift = 24; shift >= 0; shift -= 8) {
                hist[tid] = 0u;
                __syncthreads();
                unsigned pref = sel_prefix;
                unsigned hm = (shift == 24) ? 0u : (0xFFFFFFFFu << (shift + 8));
                for (int j = tid; j < LL; j += 256) {
                    float v = __fadd_rn(__fmul_rn(s[j], w_h), b_h);
                    unsigned u = fkey(v);
                    if ((u & hm) == pref) atomicAdd(&hist[(u >> shift) & 255u], 1u);
                }
                __syncthreads();
                if (tid == 0) {
                    unsigned k = sel_k, cum = 0;
                    for (int dgt = 255; dgt >= 0; --dgt) {
                        unsigned c = hist[dgt];
                        if (cum + c >= k) {
                            sel_prefix = pref | ((unsigned)dgt << shift);
                            sel_k = k - cum;
                            break;
                        }
                        cum += c;
                    }
                }
                __syncthreads();
            }
            tu = sel_prefix;
            __syncthreads();
        }

        float v[4];
        float lm = NEG_INF;
#pragma unroll
        for (int i = 0; i < 4; i++) {
            int j = tid * 4 + i;
            float sv = s[j];
            bool lf = (abs(q - j) <= 16);
            bool allow;
            if (need_sparse) {
                float s2 = __fadd_rn(__fmul_rn(sv, w_h), b_h);
                float sf = (fkey(s2) >= tu) ? 1.f : 0.f;
                float comb = (p0 * (lf ? 1.f : 0.f) + p1) + p2 * sf;
                allow = comb > THRESH;
            } else {
                allow = lf ? A10 : A00;
            }
            v[i] = allow ? sv : NEG_INF;
            lm = fmaxf(lm, v[i]);
        }
        red[tid] = lm; __syncthreads();
        for (int o = 128; o > 0; o >>= 1) {
            if (tid < o) red[tid] = fmaxf(red[tid], red[tid + o]);
            __syncthreads();
        }
        if (tid == 0) mx_sh = red[0];
        __syncthreads();
        float mx = mx_sh;

        if (mx == NEG_INF) {
            float4 o;
            o.x = (tid == 0) ? 1.f : 0.f; o.y = 0.f; o.z = 0.f; o.w = 0.f;
            ((float4*)srow)[tid] = o;
            __syncthreads();
            continue;
        }

        float ls = 0.f;
#pragma unroll
        for (int i = 0; i < 4; i++) {
            v[i] = __expf(v[i] - mx);
            ls += v[i];
        }
        red[tid] = ls; __syncthreads();
        for (int o = 128; o > 0; o >>= 1) {
            if (tid < o) red[tid] += red[tid + o];
            __syncthreads();
        }
        if (tid == 0) mx_sh = 1.f / red[0];
        __syncthreads();
        float inv = mx_sh;
        float4 o;
        o.x = v[0] * inv; o.y = v[1] * inv; o.z = v[2] * inv; o.w = v[3] * inv;
        ((float4*)srow)[tid] = o;
        __syncthreads();
    }
}

// ---------------------------------------------------------------------------
extern "C" void kernel_launch(void* const* d_in, const int* in_sizes, int n_in,
                              void* d_out, int out_size)
{
    const float* x        = (const float*)d_in[0];
    const float* qkv_w    = (const float*)d_in[1];
    const float* proj_w   = (const float*)d_in[2];
    const float* proj_b   = (const float*)d_in[3];
    const float* ps_w1    = (const float*)d_in[4];
    const float* ps_b1    = (const float*)d_in[5];
    const float* ps_w2    = (const float*)d_in[6];
    const float* ps_b2    = (const float*)d_in[7];
    const float* ps_w3    = (const float*)d_in[8];
    const float* ps_b3    = (const float*)d_in[9];
    const float* pbias    = (const float*)d_in[10];
    const float* sparse_w = (const float*)d_in[11];
    const float* sparse_b = (const float*)d_in[12];
    float* out = (float*)d_out;

    float *qkv_p, *sc_p, *attn_p;
    int *mode_p;
    __nv_bfloat16 *xhl_p, *wqhl_p, *ahl_p, *pwhl_p;
    cudaGetSymbolAddress((void**)&qkv_p,  g_qkv);
    cudaGetSymbolAddress((void**)&sc_p,   g_scores);
    cudaGetSymbolAddress((void**)&attn_p, g_attn);
    cudaGetSymbolAddress((void**)&mode_p, g_mode);
    cudaGetSymbolAddress((void**)&xhl_p,  g_xhl);
    cudaGetSymbolAddress((void**)&wqhl_p, g_wqhl);
    cudaGetSymbolAddress((void**)&ahl_p,  g_ahl);
    cudaGetSymbolAddress((void**)&pwhl_p, g_pwhl);

    pool1_kernel<<<32, 256>>>(x);
    pattern_kernel<<<BB, 256>>>(ps_w1, ps_b1, ps_w2, ps_b2, ps_w3, ps_b3, pbias);

    // bf16x2 splits
    cvt_split<1><<<(ML * DD / 4 + 255) / 256, 256>>>(x, xhl_p, ML);
    cvt_split<0><<<(QKVD * DD / 4 + 255) / 256, 256>>>(qkv_w, wqhl_p, QKVD);
    cvt_split<0><<<(DD * DD / 4 + 255) / 256, 256>>>(proj_w, pwhl_p, DD);

    // QKV projection: (4096,1536) via bf16x2 tensor-core GEMM
    gemm_mma<<<dim3(QKVD / 128, ML / 128), 256>>>(
        xhl_p, wqhl_p, qkv_p, QKVD, QKVD, nullptr);

    // ---- full path (gated on mode==0) ----
    gemm128<<<dim3(LL / 128, LL / 128, BB * HH), 256>>>(
        qkv_p, QKVD, (long)LL * QKVD, HD,
        qkv_p + DD, QKVD, (long)LL * QKVD, HD,
        sc_p, LL, (long)HH * LL * LL, (long)LL * LL,
        HD, SCALE, nullptr, HH, mode_p);
    softmax_kernel<<<BB * HH * (LL / 4), 256>>>(sparse_w, sparse_b);
    gemm_bt<<<dim3(HD / 64, LL / 64, BB * HH), 256>>>(
        sc_p, LL, (long)HH * LL * LL, (long)LL * LL,
        qkv_p + 2 * DD, QKVD, (long)LL * QKVD, HD,
        attn_p, DD, (long)LL * DD, HD,
        LL, HD, LL, 1.f, nullptr, HH, 0, mode_p);

    // ---- local/all-masked path (gated on mode!=0) ----
    local_attn_kernel<<<BB * HH * (LL / 16), 256>>>();

    // Output projection via bf16x2 tensor-core GEMM
    cvt_split<1><<<(ML * DD / 4 + 255) / 256, 256>>>(attn_p, ahl_p, ML);
    gemm_mma<<<dim3(DD / 128, ML / 128), 256>>>(
        ahl_p, pwhl_p, out, DD, DD, proj_b);
}

// round 7
// speedup vs baseline: 6.7048x; 1.1679x over previous
#include <cuda_runtime.h>
#include <cuda_bf16.h>
#include <cstdint>
#include <math.h>

#define BB 4
#define LL 1024
#define DD 512
#define HH 8
#define HD 64
#define QKVD 1536
#define ML (BB*LL)
#define K3 1536              // 3 * 512 split-K for bf16x2 GEMM
#define KTOP 716
#define THRESH 0.05f
#define SCALE 0.125f
#define NEG_INF __int_as_float(0xff800000)

#define SM_STRIDE 72
#define SM_CHUNK (128 * SM_STRIDE)
#define NCHUNK (K3 / 64)

// Scratch (device globals; no allocations allowed)
__device__ float g_qkv[ML * QKVD];
__device__ float g_scores[(size_t)BB * HH * LL * LL];
__device__ float g_attn[ML * DD];
__device__ float g_pw[BB * 3];
__device__ int   g_mode[BB];
__device__ float g_pool_part[32][DD];
// bf16x2 split buffers
__device__ __nv_bfloat16 g_xhl[ML * K3];
__device__ __nv_bfloat16 g_wqhl[QKVD * K3];
__device__ __nv_bfloat16 g_ahl[ML * K3];
__device__ __nv_bfloat16 g_pwhl[DD * K3];

__device__ __forceinline__ uint32_t smem_u32(const void* p) {
    return (uint32_t)__cvta_generic_to_shared(p);
}
__device__ __forceinline__ void cp16(uint32_t dst, const void* src) {
    asm volatile("cp.async.cg.shared.global [%0], [%1], 16;\n" :: "r"(dst), "l"(src));
}

// ---------------------------------------------------------------------------
// fp32 -> bf16 hi/lo split. Astyle: [hi | lo | hi]. Bstyle: [hi | hi | lo].
// gate != nullptr: only process rows whose batch (m/LL) has mode 0.
// ---------------------------------------------------------------------------
template<int ASTYLE>
__global__ __launch_bounds__(256)
void cvt_split(const float* __restrict__ src, __nv_bfloat16* __restrict__ dst,
               int M, const int* __restrict__ gate)
{
    int i = blockIdx.x * 256 + threadIdx.x;     // one float4 per thread
    int total = M * (DD / 4);
    if (i >= total) return;
    int m = i / (DD / 4), c = i % (DD / 4);
    if (gate && gate[m / LL] != 0) return;
    float4 v = ((const float4*)(src + (size_t)m * DD))[c];
    __nv_bfloat16 hi[4], lo[4];
    float vv[4] = {v.x, v.y, v.z, v.w};
#pragma unroll
    for (int t = 0; t < 4; t++) {
        hi[t] = __float2bfloat16(vv[t]);
        lo[t] = __float2bfloat16(vv[t] - __bfloat162float(hi[t]));
    }
    __nv_bfloat16* d = dst + (size_t)m * K3 + c * 4;
    __nv_bfloat162* d0 = (__nv_bfloat162*)(d);
    __nv_bfloat162* d1 = (__nv_bfloat162*)(d + DD);
    __nv_bfloat162* d2 = (__nv_bfloat162*)(d + 2 * DD);
    __nv_bfloat162 hp0 = {hi[0], hi[1]}, hp1 = {hi[2], hi[3]};
    __nv_bfloat162 lp0 = {lo[0], lo[1]}, lp1 = {lo[2], lo[3]};
    d0[0] = hp0; d0[1] = hp1;
    if (ASTYLE) {
        d1[0] = lp0; d1[1] = lp1;      // A: [hi, lo, hi]
        d2[0] = hp0; d2[1] = hp1;
    } else {
        d1[0] = hp0; d1[1] = hp1;      // B: [hi, hi, lo]
        d2[0] = lp0; d2[1] = lp1;
    }
}

// ---------------------------------------------------------------------------
// bf16 NT GEMM via mma.sync m16n8k16, cp.async double-buffered.
// 128x128 tile, 8 warps (4m x 2n), warp tile 32x64, KB=64.
// Dynamic smem: [bufA0 | bufB0 | bufA1 | bufB1], each 128x72 bf16.
// ---------------------------------------------------------------------------
__global__ __launch_bounds__(256, 2)
void gemm_mma(const __nv_bfloat16* __restrict__ A2,
              const __nv_bfloat16* __restrict__ B2,
              float* __restrict__ C, int ldc, int N,
              const float* __restrict__ bias)
{
    extern __shared__ __nv_bfloat16 sm[];
    int tid = threadIdx.x;
    int warp = tid >> 5, lane = tid & 31;
    int wm = warp >> 1, wn = warp & 1;
    int m0 = blockIdx.y * 128, n0 = blockIdx.x * 128;
    int m0w = wm * 32, n0w = wn * 64;

    float acc[2][8][4];
#pragma unroll
    for (int a = 0; a < 2; a++)
#pragma unroll
        for (int b = 0; b < 8; b++)
#pragma unroll
            for (int c = 0; c < 4; c++) acc[a][b][c] = 0.f;

    int lrow = tid >> 3, lch = tid & 7;

    auto issue = [&](int chunk) {
        int buf = chunk & 1;
        __nv_bfloat16* Ab = sm + buf * 2 * SM_CHUNK;
        __nv_bfloat16* Bb = sm + buf * 2 * SM_CHUNK + SM_CHUNK;
        int k0 = chunk * 64;
#pragma unroll
        for (int p = 0; p < 4; p++) {
            int r = lrow + p * 32;
            cp16(smem_u32(Ab + r * SM_STRIDE + lch * 8),
                 A2 + (size_t)(m0 + r) * K3 + k0 + lch * 8);
            cp16(smem_u32(Bb + r * SM_STRIDE + lch * 8),
                 B2 + (size_t)(n0 + r) * K3 + k0 + lch * 8);
        }
        asm volatile("cp.async.commit_group;\n");
    };

    issue(0);
    for (int c = 0; c < NCHUNK; c++) {
        int buf = c & 1;
        if (c + 1 < NCHUNK) {
            issue(c + 1);
            asm volatile("cp.async.wait_group 1;\n");
        } else {
            asm volatile("cp.async.wait_group 0;\n");
        }
        __syncthreads();
        __nv_bfloat16* Ab = sm + buf * 2 * SM_CHUNK;
        __nv_bfloat16* Bb = sm + buf * 2 * SM_CHUNK + SM_CHUNK;
#pragma unroll
        for (int kk = 0; kk < 64; kk += 16) {
            uint32_t a[2][4];
#pragma unroll
            for (int mt = 0; mt < 2; mt++) {
                int mrow = m0w + mt * 16 + (lane & 15);
                int kcol = kk + ((lane >> 4) << 3);
                uint32_t ad = smem_u32(Ab + mrow * SM_STRIDE + kcol);
                asm volatile("ldmatrix.sync.aligned.m8n8.x4.shared.b16 {%0,%1,%2,%3}, [%4];"
                    : "=r"(a[mt][0]), "=r"(a[mt][1]), "=r"(a[mt][2]), "=r"(a[mt][3])
                    : "r"(ad));
            }
            uint32_t bfr[4][4];
#pragma unroll
            for (int g = 0; g < 4; g++) {
                int nrow = n0w + g * 16 + ((lane >> 4) << 3) + (lane & 7);
                int kcol = kk + (((lane >> 3) & 1) << 3);
                uint32_t ad = smem_u32(Bb + nrow * SM_STRIDE + kcol);
                asm volatile("ldmatrix.sync.aligned.m8n8.x4.shared.b16 {%0,%1,%2,%3}, [%4];"
                    : "=r"(bfr[g][0]), "=r"(bfr[g][1]), "=r"(bfr[g][2]), "=r"(bfr[g][3])
                    : "r"(ad));
            }
#pragma unroll
            for (int mt = 0; mt < 2; mt++)
#pragma unroll
                for (int nt = 0; nt < 8; nt++) {
                    int g = nt >> 1, pr = (nt & 1) * 2;
                    asm volatile(
                        "mma.sync.aligned.m16n8k16.row.col.f32.bf16.bf16.f32 "
                        "{%0,%1,%2,%3}, {%4,%5,%6,%7}, {%8,%9}, {%0,%1,%2,%3};"
                        : "+f"(acc[mt][nt][0]), "+f"(acc[mt][nt][1]),
                          "+f"(acc[mt][nt][2]), "+f"(acc[mt][nt][3])
                        : "r"(a[mt][0]), "r"(a[mt][1]), "r"(a[mt][2]), "r"(a[mt][3]),
                          "r"(bfr[g][pr]), "r"(bfr[g][pr + 1]));
                }
        }
        __syncthreads();
    }

    // epilogue
#pragma unroll
    for (int mt = 0; mt < 2; mt++) {
        int mA = m0 + m0w + mt * 16 + (lane >> 2);
#pragma unroll
        for (int nt = 0; nt < 8; nt++) {
            int n = n0 + n0w + nt * 8 + (lane & 3) * 2;
            if (n >= N) continue;
            float b0 = bias ? bias[n] : 0.f;
            float b1 = bias ? bias[n + 1] : 0.f;
            *(float2*)&C[(size_t)mA * ldc + n] =
                make_float2(acc[mt][nt][0] + b0, acc[mt][nt][1] + b1);
            *(float2*)&C[(size_t)(mA + 8) * ldc + n] =
                make_float2(acc[mt][nt][2] + b0, acc[mt][nt][3] + b1);
        }
    }
}

// ---------------------------------------------------------------------------
// 128x128 fp32 SGEMM (NT) for the gated full-path scores.
// ---------------------------------------------------------------------------
__global__ __launch_bounds__(256)
void gemm128(const float* __restrict__ A, int lda, long sAb, long sAh,
             const float* __restrict__ B, int ldb, long sBb, long sBh,
             float* __restrict__ C, int ldc, long sCb, long sCh,
             int K, float alpha, const float* __restrict__ bias,
             int nh, const int* __restrict__ gate)
{
    __shared__ float As[16][132];
    __shared__ float Bs[16][132];
    int z = blockIdx.z;
    int b = z / nh, h = z % nh;
    if (gate && gate[b] != 0) return;
    A += (size_t)b * sAb + (size_t)h * sAh;
    B += (size_t)b * sBb + (size_t)h * sBh;
    C += (size_t)b * sCb + (size_t)h * sCh;

    int tid = threadIdx.x;
    int tx = tid & 15, ty = tid >> 4;
    int m0 = blockIdx.y * 128, n0 = blockIdx.x * 128;

    float acc[8][8];
#pragma unroll
    for (int i = 0; i < 8; i++)
#pragma unroll
        for (int j = 0; j < 8; j++) acc[i][j] = 0.f;

    for (int k0 = 0; k0 < K; k0 += 16) {
#pragma unroll
        for (int i = 0; i < 8; i++) {
            int idx = tid + i * 256;
            int m = idx >> 4, kk = idx & 15;
            As[kk][m] = A[(size_t)(m0 + m) * lda + k0 + kk];
            Bs[kk][m] = B[(size_t)(n0 + m) * ldb + k0 + kk];
        }
        __syncthreads();
#pragma unroll
        for (int kk = 0; kk < 16; kk++) {
            float4 a0 = *(const float4*)&As[kk][ty * 8];
            float4 a1 = *(const float4*)&As[kk][ty * 8 + 4];
            float4 b0 = *(const float4*)&Bs[kk][tx * 8];
            float4 b1 = *(const float4*)&Bs[kk][tx * 8 + 4];
            float av[8] = {a0.x, a0.y, a0.z, a0.w, a1.x, a1.y, a1.z, a1.w};
            float bv[8] = {b0.x, b0.y, b0.z, b0.w, b1.x, b1.y, b1.z, b1.w};
#pragma unroll
            for (int i = 0; i < 8; i++)
#pragma unroll
                for (int j = 0; j < 8; j++) acc[i][j] += av[i] * bv[j];
        }
        __syncthreads();
    }
#pragma unroll
    for (int i = 0; i < 8; i++) {
        int m = m0 + ty * 8 + i;
        float out[8];
#pragma unroll
        for (int j = 0; j < 8; j++) {
            out[j] = acc[i][j] * alpha;
            if (bias) out[j] += bias[n0 + tx * 8 + j];
        }
        float4* cp = (float4*)&C[(size_t)m * ldc + n0 + tx * 8];
        cp[0] = make_float4(out[0], out[1], out[2], out[3]);
        cp[1] = make_float4(out[4], out[5], out[6], out[7]);
    }
}

// ---------------------------------------------------------------------------
// 64x64 SGEMM (NT/NN) for the gated AV path.
// ---------------------------------------------------------------------------
__global__ __launch_bounds__(256)
void gemm_bt(const float* __restrict__ A, int lda, long sAb, long sAh,
             const float* __restrict__ B, int ldb, long sBb, long sBh,
             float* __restrict__ C, int ldc, long sCb, long sCh,
             int M, int N, int K, float alpha,
             const float* __restrict__ bias, int nh, int bTrans,
             const int* __restrict__ gate)
{
    __shared__ float As[16][65];
    __shared__ float Bs[16][65];
    int z = blockIdx.z;
    int b = z / nh, h = z % nh;
    if (gate && gate[b] != 0) return;
    A += (size_t)b * sAb + (size_t)h * sAh;
    B += (size_t)b * sBb + (size_t)h * sBh;
    C += (size_t)b * sCb + (size_t)h * sCh;

    int tid = threadIdx.x;
    int tx = tid & 15, ty = tid >> 4;
    int m0 = blockIdx.y * 64, n0 = blockIdx.x * 64;

    float acc[4][4];
#pragma unroll
    for (int i = 0; i < 4; i++)
#pragma unroll
        for (int j = 0; j < 4; j++) acc[i][j] = 0.f;

    for (int k0 = 0; k0 < K; k0 += 16) {
#pragma unroll
        for (int i = 0; i < 4; i++) {
            int idx = tid + i * 256;
            int m = idx >> 4, kk = idx & 15;
            As[kk][m] = A[(size_t)(m0 + m) * lda + k0 + kk];
        }
        if (bTrans) {
#pragma unroll
            for (int i = 0; i < 4; i++) {
                int idx = tid + i * 256;
                int n = idx >> 4, kk = idx & 15;
                Bs[kk][n] = B[(size_t)(n0 + n) * ldb + k0 + kk];
            }
        } else {
#pragma unroll
            for (int i = 0; i < 4; i++) {
                int idx = tid + i * 256;
                int n = idx & 63, kk = idx >> 6;
                Bs[kk][n] = B[(size_t)(k0 + kk) * ldb + n0 + n];
            }
        }
        __syncthreads();
#pragma unroll
        for (int kk = 0; kk < 16; kk++) {
            float a[4], bb[4];
#pragma unroll
            for (int i = 0; i < 4; i++) a[i] = As[kk][ty * 4 + i];
#pragma unroll
            for (int j = 0; j < 4; j++) bb[j] = Bs[kk][tx * 4 + j];
#pragma unroll
            for (int i = 0; i < 4; i++)
#pragma unroll
                for (int j = 0; j < 4; j++) acc[i][j] += a[i] * bb[j];
        }
        __syncthreads();
    }
#pragma unroll
    for (int i = 0; i < 4; i++) {
        int m = m0 + ty * 4 + i;
#pragma unroll
        for (int j = 0; j < 4; j++) {
            int n = n0 + tx * 4 + j;
            float v = acc[i][j] * alpha;
            if (bias) v += bias[n];
            C[(size_t)m * ldc + n] = v;
        }
    }
}

// ---------------------------------------------------------------------------
__global__ __launch_bounds__(256)
void pool1_kernel(const float* __restrict__ x)
{
    int blk = blockIdx.x;
    int b = blk >> 3, c = blk & 7;
    int tid = threadIdx.x;
    const float2* xp = (const float2*)(x + ((size_t)b * LL + c * 128) * DD) + tid;
    float s0 = 0.f, s1 = 0.f;
    for (int l = 0; l < 128; l++) {
        float2 v = xp[(size_t)l * (DD / 2)];
        s0 += v.x; s1 += v.y;
    }
    g_pool_part[blk][tid * 2]     = s0;
    g_pool_part[blk][tid * 2 + 1] = s1;
}

// ---------------------------------------------------------------------------
__global__ __launch_bounds__(256)
void pattern_kernel(const float* __restrict__ w1, const float* __restrict__ b1,
                    const float* __restrict__ w2, const float* __restrict__ b2,
                    const float* __restrict__ w3, const float* __restrict__ b3,
                    const float* __restrict__ pbias)
{
    int b = blockIdx.x, tid = threadIdx.x;
    int warp = tid >> 5, lane = tid & 31;
    __shared__ float pooled[DD];
    __shared__ float h1[DD];
    __shared__ float h2[DD / 2];
    __shared__ float lg[3];

    for (int d = tid; d < DD; d += 256) {
        float s = 0.f;
#pragma unroll
        for (int c = 0; c < 8; c++) s += g_pool_part[b * 8 + c][d];
        pooled[d] = s * (1.0f / LL);
    }
    __syncthreads();
    for (int i = warp; i < DD; i += 8) {
        const float* wr = w1 + (size_t)i * DD;
        float a = 0.f;
        for (int k = lane; k < DD; k += 32) a += pooled[k] * wr[k];
#pragma unroll
        for (int o = 16; o > 0; o >>= 1) a += __shfl_xor_sync(~0u, a, o);
        if (lane == 0) h1[i] = fmaxf(a + b1[i], 0.f);
    }
    __syncthreads();
    for (int i = warp; i < DD / 2; i += 8) {
        const float* wr = w2 + (size_t)i * DD;
        float a = 0.f;
        for (int k = lane; k < DD; k += 32) a += h1[k] * wr[k];
#pragma unroll
        for (int o = 16; o > 0; o >>= 1) a += __shfl_xor_sync(~0u, a, o);
        if (lane == 0) h2[i] = fmaxf(a + b2[i], 0.f);
    }
    __syncthreads();
    if (warp < 3) {
        const float* wr = w3 + (size_t)warp * (DD / 2);
        float a = 0.f;
        for (int k = lane; k < DD / 2; k += 32) a += h2[k] * wr[k];
#pragma unroll
        for (int o = 16; o > 0; o >>= 1) a += __shfl_xor_sync(~0u, a, o);
        if (lane == 0) lg[warp] = (a + b3[warp] + pbias[warp]) / 0.3f;
    }
    __syncthreads();
    if (tid == 0) {
        float m = fmaxf(lg[0], fmaxf(lg[1], lg[2]));
        float e0 = expf(lg[0] - m), e1 = expf(lg[1] - m), e2 = expf(lg[2] - m);
        float inv = 1.f / (e0 + e1 + e2);
        float p0 = e0 * inv, p1 = e1 * inv, p2 = e2 * inv;
        g_pw[b * 3 + 0] = p0;
        g_pw[b * 3 + 1] = p1;
        g_pw[b * 3 + 2] = p2;
        bool A00 = p1 > THRESH;
        bool A01 = (p1 + p2) > THRESH;
        bool A10 = (p0 + p1) > THRESH;
        bool A11 = ((p0 + p1) + p2) > THRESH;
        bool need_sparse = (A00 != A01) || (A10 != A11);
        int mode;
        if (need_sparse || A00) mode = 0;
        else if (A10)           mode = 1;
        else                    mode = 2;
        g_mode[b] = mode;
    }
}

// ---------------------------------------------------------------------------
// Write one attention output value as [hi|lo|hi] split into g_ahl.
// ---------------------------------------------------------------------------
__device__ __forceinline__ void write_split(int m, int col, float v)
{
    __nv_bfloat16 hi = __float2bfloat16(v);
    __nv_bfloat16 lo = __float2bfloat16(v - __bfloat162float(hi));
    __nv_bfloat16* d = g_ahl + (size_t)m * K3 + col;
    d[0] = hi; d[DD] = lo; d[2 * DD] = hi;
}

// ---------------------------------------------------------------------------
// Local-window fused attention (mode 1) + all-masked fallback (mode 2).
// Writes bf16x2 split directly to g_ahl (proj GEMM input).
// ---------------------------------------------------------------------------
__global__ __launch_bounds__(256)
void local_attn_kernel()
{
    __shared__ float ksh[48][65];
    __shared__ float vsh[48][65];
    __shared__ float qsh[16][64];
    __shared__ float psh[16][33];

    int blk = blockIdx.x;
    int b = blk >> 9;
    int h = (blk >> 6) & 7;
    int q0 = (blk & 63) * 16;
    int mode = g_mode[b];
    if (mode == 0) return;
    int tid = threadIdx.x;
    const float* base = g_qkv + (size_t)b * LL * QKVD + h * HD;

    if (mode == 2) {
        const float* v0 = base + 2 * DD;
#pragma unroll
        for (int i = 0; i < 4; i++) {
            int idx = tid + i * 256;
            int r = idx >> 6, d = idx & 63;
            write_split(b * LL + q0 + r, h * HD + d, v0[d]);
        }
        return;
    }

    int kb0 = max(q0 - 16, 0);
    int kend = min(q0 + 15 + 16, LL - 1);
    int klen = kend - kb0 + 1;

    for (int i = tid; i < klen * 64; i += 256) {
        int jj = i >> 6, d = i & 63;
        const float* src = base + (size_t)(kb0 + jj) * QKVD;
        ksh[jj][d] = src[DD + d];
        vsh[jj][d] = src[2 * DD + d];
    }
#pragma unroll
    for (int i = 0; i < 4; i++) {
        int idx = tid + i * 256;
        int r = idx >> 6, d = idx & 63;
        qsh[r][d] = base[(size_t)(q0 + r) * QKVD + d];
    }
    __syncthreads();

    int warp = tid >> 5, lane = tid & 31;
#pragma unroll
    for (int rr = 0; rr < 2; rr++) {
        int r = warp * 2 + rr;
        int q = q0 + r;
        int w0 = max(q - 16, 0), w1 = min(q + 16, LL - 1);
        int cnt = w1 - w0 + 1;
        int off = w0 - kb0;

        float s0 = NEG_INF, s1 = NEG_INF;
        if (lane < cnt) {
            float acc = 0.f;
#pragma unroll
            for (int d = 0; d < 64; d++) acc += qsh[r][d] * ksh[off + lane][d];
            s0 = acc * SCALE;
        }
        if (lane + 32 < cnt) {
            float acc = 0.f;
#pragma unroll
            for (int d = 0; d < 64; d++) acc += qsh[r][d] * ksh[off + lane + 32][d];
            s1 = acc * SCALE;
        }
        float m = fmaxf(s0, s1);
#pragma unroll
        for (int o = 16; o > 0; o >>= 1) m = fmaxf(m, __shfl_xor_sync(~0u, m, o));
        float e0 = (lane < cnt) ? __expf(s0 - m) : 0.f;
        float e1 = (lane + 32 < cnt) ? __expf(s1 - m) : 0.f;
        float sum = e0 + e1;
#pragma unroll
        for (int o = 16; o > 0; o >>= 1) sum += __shfl_xor_sync(~0u, sum, o);
        float inv = 1.f / sum;
        if (lane < cnt) psh[r][lane] = e0 * inv;
        if (lane + 32 < cnt) psh[r][lane + 32] = e1 * inv;
        __syncwarp();

        float o0 = 0.f, o1 = 0.f;
        for (int jj = 0; jj < cnt; jj++) {
            float p = psh[r][jj];
            o0 += p * vsh[off + jj][lane];
            o1 += p * vsh[off + jj][lane + 32];
        }
        int m_out = b * LL + q;
        write_split(m_out, h * HD + lane, o0);
        write_split(m_out, h * HD + lane + 32, o1);
    }
}

// ---------------------------------------------------------------------------
// Full-path mask + softmax (mode 0 only). 16 rows per block.
// ---------------------------------------------------------------------------
__device__ __forceinline__ unsigned fkey(float f) {
    unsigned u = __float_as_uint(f);
    return (u & 0x80000000u) ? ~u : (u | 0x80000000u);
}

__global__ __launch_bounds__(256)
void softmax_kernel(const float* __restrict__ sparse_w,
                    const float* __restrict__ sparse_b)
{
    __shared__ float s[LL];
    __shared__ float red[256];
    __shared__ unsigned hist[256];
    __shared__ unsigned sel_prefix, sel_k;
    __shared__ float mx_sh;

    int grp = blockIdx.x;               // 0..2047, 16 rows each
    int z = grp >> 6;
    int b = z >> 3, h = z & 7;
    if (g_mode[b] != 0) return;
    int q_base = (grp & 63) * 16;
    int tid = threadIdx.x;

    float p0 = g_pw[b * 3 + 0];
    float p1 = g_pw[b * 3 + 1];
    float p2 = g_pw[b * 3 + 2];
    bool A00 = p1 > THRESH;
    bool A01 = (p1 + p2) > THRESH;
    bool A10 = (p0 + p1) > THRESH;
    bool A11 = ((p0 + p1) + p2) > THRESH;
    bool need_sparse = (A00 != A01) || (A10 != A11);
    float w_h = sparse_w[h], b_h = sparse_b[h];

    for (int r = 0; r < 16; r++) {
        int q = q_base + r;
        float* srow = g_scores + ((size_t)z << 20) + ((size_t)q << 10);
        ((float4*)s)[tid] = ((const float4*)srow)[tid];
        __syncthreads();

        unsigned tu = 0u;
        if (need_sparse) {
            if (tid == 0) { sel_prefix = 0u; sel_k = KTOP; }
            __syncthreads();
            for (int shift = 24; shift >= 0; shift -= 8) {
                hist[tid] = 0u;
                __syncthreads();
                unsigned pref = sel_prefix;
                unsigned hm = (shift == 24) ? 0u : (0xFFFFFFFFu << (shift + 8));
                for (int j = tid; j < LL; j += 256) {
                    float v = __fadd_rn(__fmul_rn(s[j], w_h), b_h);
                    unsigned u = fkey(v);
                    if ((u & hm) == pref) atomicAdd(&hist[(u >> shift) & 255u], 1u);
                }
                __syncthreads();
                if (tid == 0) {
                    unsigned k = sel_k, cum = 0;
                    for (int dgt = 255; dgt >= 0; --dgt) {
                        unsigned c = hist[dgt];
                        if (cum + c >= k) {
                            sel_prefix = pref | ((unsigned)dgt << shift);
                            sel_k = k - cum;
                            break;
                        }
                        cum += c;
                    }
                }
                __syncthreads();
            }
            tu = sel_prefix;
            __syncthreads();
        }

        float v[4];
        float lm = NEG_INF;
#pragma unroll
        for (int i = 0; i < 4; i++) {
            int j = tid * 4 + i;
            float sv = s[j];
            bool lf = (abs(q - j) <= 16);
            bool allow;
            if (need_sparse) {
                float s2 = __fadd_rn(__fmul_rn(sv, w_h), b_h);
                float sf = (fkey(s2) >= tu) ? 1.f : 0.f;
                float comb = (p0 * (lf ? 1.f : 0.f) + p1) + p2 * sf;
                allow = comb > THRESH;
            } else {
                allow = lf ? A10 : A00;
            }
            v[i] = allow ? sv : NEG_INF;
            lm = fmaxf(lm, v[i]);
        }
        red[tid] = lm; __syncthreads();
        for (int o = 128; o > 0; o >>= 1) {
            if (tid < o) red[tid] = fmaxf(red[tid], red[tid + o]);
            __syncthreads();
        }
        if (tid == 0) mx_sh = red[0];
        __syncthreads();
        float mx = mx_sh;

        if (mx == NEG_INF) {
            float4 o;
            o.x = (tid == 0) ? 1.f : 0.f; o.y = 0.f; o.z = 0.f; o.w = 0.f;
            ((float4*)srow)[tid] = o;
            __syncthreads();
            continue;
        }

        float ls = 0.f;
#pragma unroll
        for (int i = 0; i < 4; i++) {
            v[i] = __expf(v[i] - mx);
            ls += v[i];
        }
        red[tid] = ls; __syncthreads();
        for (int o = 128; o > 0; o >>= 1) {
            if (tid < o) red[tid] += red[tid + o];
            __syncthreads();
        }
        if (tid == 0) mx_sh = 1.f / red[0];
        __syncthreads();
        float inv = mx_sh;
        float4 o;
        o.x = v[0] * inv; o.y = v[1] * inv; o.z = v[2] * inv; o.w = v[3] * inv;
        ((float4*)srow)[tid] = o;
        __syncthreads();
    }
}

// ---------------------------------------------------------------------------
extern "C" void kernel_launch(void* const* d_in, const int* in_sizes, int n_in,
                              void* d_out, int out_size)
{
    const float* x        = (const float*)d_in[0];
    const float* qkv_w    = (const float*)d_in[1];
    const float* proj_w   = (const float*)d_in[2];
    const float* proj_b   = (const float*)d_in[3];
    const float* ps_w1    = (const float*)d_in[4];
    const float* ps_b1    = (const float*)d_in[5];
    const float* ps_w2    = (const float*)d_in[6];
    const float* ps_b2    = (const float*)d_in[7];
    const float* ps_w3    = (const float*)d_in[8];
    const float* ps_b3    = (const float*)d_in[9];
    const float* pbias    = (const float*)d_in[10];
    const float* sparse_w = (const float*)d_in[11];
    const float* sparse_b = (const float*)d_in[12];
    float* out = (float*)d_out;

    float *qkv_p, *sc_p, *attn_p;
    int *mode_p;
    __nv_bfloat16 *xhl_p, *wqhl_p, *ahl_p, *pwhl_p;
    cudaGetSymbolAddress((void**)&qkv_p,  g_qkv);
    cudaGetSymbolAddress((void**)&sc_p,   g_scores);
    cudaGetSymbolAddress((void**)&attn_p, g_attn);
    cudaGetSymbolAddress((void**)&mode_p, g_mode);
    cudaGetSymbolAddress((void**)&xhl_p,  g_xhl);
    cudaGetSymbolAddress((void**)&wqhl_p, g_wqhl);
    cudaGetSymbolAddress((void**)&ahl_p,  g_ahl);
    cudaGetSymbolAddress((void**)&pwhl_p, g_pwhl);

    static int smem_set = 0;
    if (!smem_set) {
        cudaFuncSetAttribute(gemm_mma, cudaFuncAttributeMaxDynamicSharedMemorySize,
                             4 * SM_CHUNK * (int)sizeof(__nv_bfloat16));
        smem_set = 1;
    }
    const int dyn_smem = 4 * SM_CHUNK * (int)sizeof(__nv_bfloat16);

    pool1_kernel<<<32, 256>>>(x);
    pattern_kernel<<<BB, 256>>>(ps_w1, ps_b1, ps_w2, ps_b2, ps_w3, ps_b3, pbias);

    // bf16x2 splits (inputs/weights; ungated)
    cvt_split<1><<<(ML * DD / 4 + 255) / 256, 256>>>(x, xhl_p, ML, nullptr);
    cvt_split<0><<<(QKVD * DD / 4 + 255) / 256, 256>>>(qkv_w, wqhl_p, QKVD, nullptr);
    cvt_split<0><<<(DD * DD / 4 + 255) / 256, 256>>>(proj_w, pwhl_p, DD, nullptr);

    // QKV projection: (4096,1536) via pipelined bf16x2 tensor-core GEMM
    gemm_mma<<<dim3(QKVD / 128, ML / 128), 256, dyn_smem>>>(
        xhl_p, wqhl_p, qkv_p, QKVD, QKVD, nullptr);

    // ---- full path (gated on mode==0) ----
    gemm128<<<dim3(LL / 128, LL / 128, BB * HH), 256>>>(
        qkv_p, QKVD, (long)LL * QKVD, HD,
        qkv_p + DD, QKVD, (long)LL * QKVD, HD,
        sc_p, LL, (long)HH * LL * LL, (long)LL * LL,
        HD, SCALE, nullptr, HH, mode_p);
    softmax_kernel<<<BB * HH * (LL / 16), 256>>>(sparse_w, sparse_b);
    gemm_bt<<<dim3(HD / 64, LL / 64, BB * HH), 256>>>(
        sc_p, LL, (long)HH * LL * LL, (long)LL * LL,
        qkv_p + 2 * DD, QKVD, (long)LL * QKVD, HD,
        attn_p, DD, (long)LL * DD, HD,
        LL, HD, LL, 1.f, nullptr, HH, 0, mode_p);
    // full-path attn -> split (gated per batch on mode==0)
    cvt_split<1><<<(ML * DD / 4 + 255) / 256, 256>>>(attn_p, ahl_p, ML, mode_p);

    // ---- local/all-masked path (gated on mode!=0): writes split directly ----
    local_attn_kernel<<<BB * HH * (LL / 16), 256>>>();

    // Output projection via pipelined bf16x2 tensor-core GEMM
    gemm_mma<<<dim3(DD / 128, ML / 128), 256, dyn_smem>>>(
        ahl_p, pwhl_p, out, DD, DD, proj_b);
}

// round 8
// speedup vs baseline: 8.2061x; 1.2239x over previous
#include <cuda_runtime.h>
#include <cuda_bf16.h>
#include <cstdint>
#include <math.h>

#define BB 4
#define LL 1024
#define DD 512
#define HH 8
#define HD 64
#define QKVD 1536
#define ML (BB*LL)
#define K3 1536              // 3 * 512 split-K for bf16x2 GEMM
#define KTOP 716
#define THRESH 0.05f
#define SCALE 0.125f
#define NEG_INF __int_as_float(0xff800000)

#define SM_STRIDE 72
#define SM_CHUNK (128 * SM_STRIDE)
#define NCHUNK (K3 / 64)

// Scratch (device globals; no allocations allowed)
__device__ float g_qkv[ML * QKVD];
__device__ float g_scores[(size_t)BB * HH * LL * LL];
__device__ float g_attn[ML * DD];
__device__ float g_pw[BB * 3];
__device__ int   g_mode[BB];
__device__ float g_pool_part[32][DD];
// bf16x2 split buffers
__device__ __nv_bfloat16 g_xhl[ML * K3];
__device__ __nv_bfloat16 g_wqhl[QKVD * K3];
__device__ __nv_bfloat16 g_ahl[ML * K3];
__device__ __nv_bfloat16 g_pwhl[DD * K3];

__device__ __forceinline__ uint32_t smem_u32(const void* p) {
    return (uint32_t)__cvta_generic_to_shared(p);
}
__device__ __forceinline__ void cp16(uint32_t dst, const void* src) {
    asm volatile("cp.async.cg.shared.global [%0], [%1], 16;\n" :: "r"(dst), "l"(src));
}

// ---------------------------------------------------------------------------
// fp32 -> bf16 hi/lo split. Astyle: [hi | lo | hi]. Bstyle: [hi | hi | lo].
// gate != nullptr: only process rows whose batch (m/LL) has mode 0.
// ---------------------------------------------------------------------------
template<int ASTYLE>
__global__ __launch_bounds__(256)
void cvt_split(const float* __restrict__ src, __nv_bfloat16* __restrict__ dst,
               int M, const int* __restrict__ gate)
{
    int i = blockIdx.x * 256 + threadIdx.x;     // one float4 per thread
    int total = M * (DD / 4);
    if (i >= total) return;
    int m = i / (DD / 4), c = i % (DD / 4);
    if (gate && gate[m / LL] != 0) return;
    float4 v = ((const float4*)(src + (size_t)m * DD))[c];
    __nv_bfloat16 hi[4], lo[4];
    float vv[4] = {v.x, v.y, v.z, v.w};
#pragma unroll
    for (int t = 0; t < 4; t++) {
        hi[t] = __float2bfloat16(vv[t]);
        lo[t] = __float2bfloat16(vv[t] - __bfloat162float(hi[t]));
    }
    __nv_bfloat16* d = dst + (size_t)m * K3 + c * 4;
    __nv_bfloat162* d0 = (__nv_bfloat162*)(d);
    __nv_bfloat162* d1 = (__nv_bfloat162*)(d + DD);
    __nv_bfloat162* d2 = (__nv_bfloat162*)(d + 2 * DD);
    __nv_bfloat162 hp0 = {hi[0], hi[1]}, hp1 = {hi[2], hi[3]};
    __nv_bfloat162 lp0 = {lo[0], lo[1]}, lp1 = {lo[2], lo[3]};
    d0[0] = hp0; d0[1] = hp1;
    if (ASTYLE) {
        d1[0] = lp0; d1[1] = lp1;      // A: [hi, lo, hi]
        d2[0] = hp0; d2[1] = hp1;
    } else {
        d1[0] = hp0; d1[1] = hp1;      // B: [hi, hi, lo]
        d2[0] = lp0; d2[1] = lp1;
    }
}

// ---------------------------------------------------------------------------
// bf16 NT GEMM via mma.sync m16n8k16, cp.async double-buffered.
// ---------------------------------------------------------------------------
__global__ __launch_bounds__(256, 2)
void gemm_mma(const __nv_bfloat16* __restrict__ A2,
              const __nv_bfloat16* __restrict__ B2,
              float* __restrict__ C, int ldc, int N,
              const float* __restrict__ bias)
{
    extern __shared__ __nv_bfloat16 sm[];
    int tid = threadIdx.x;
    int warp = tid >> 5, lane = tid & 31;
    int wm = warp >> 1, wn = warp & 1;
    int m0 = blockIdx.y * 128, n0 = blockIdx.x * 128;
    int m0w = wm * 32, n0w = wn * 64;

    float acc[2][8][4];
#pragma unroll
    for (int a = 0; a < 2; a++)
#pragma unroll
        for (int b = 0; b < 8; b++)
#pragma unroll
            for (int c = 0; c < 4; c++) acc[a][b][c] = 0.f;

    int lrow = tid >> 3, lch = tid & 7;

    auto issue = [&](int chunk) {
        int buf = chunk & 1;
        __nv_bfloat16* Ab = sm + buf * 2 * SM_CHUNK;
        __nv_bfloat16* Bb = sm + buf * 2 * SM_CHUNK + SM_CHUNK;
        int k0 = chunk * 64;
#pragma unroll
        for (int p = 0; p < 4; p++) {
            int r = lrow + p * 32;
            cp16(smem_u32(Ab + r * SM_STRIDE + lch * 8),
                 A2 + (size_t)(m0 + r) * K3 + k0 + lch * 8);
            cp16(smem_u32(Bb + r * SM_STRIDE + lch * 8),
                 B2 + (size_t)(n0 + r) * K3 + k0 + lch * 8);
        }
        asm volatile("cp.async.commit_group;\n");
    };

    issue(0);
    for (int c = 0; c < NCHUNK; c++) {
        int buf = c & 1;
        if (c + 1 < NCHUNK) {
            issue(c + 1);
            asm volatile("cp.async.wait_group 1;\n");
        } else {
            asm volatile("cp.async.wait_group 0;\n");
        }
        __syncthreads();
        __nv_bfloat16* Ab = sm + buf * 2 * SM_CHUNK;
        __nv_bfloat16* Bb = sm + buf * 2 * SM_CHUNK + SM_CHUNK;
#pragma unroll
        for (int kk = 0; kk < 64; kk += 16) {
            uint32_t a[2][4];
#pragma unroll
            for (int mt = 0; mt < 2; mt++) {
                int mrow = m0w + mt * 16 + (lane & 15);
                int kcol = kk + ((lane >> 4) << 3);
                uint32_t ad = smem_u32(Ab + mrow * SM_STRIDE + kcol);
                asm volatile("ldmatrix.sync.aligned.m8n8.x4.shared.b16 {%0,%1,%2,%3}, [%4];"
                    : "=r"(a[mt][0]), "=r"(a[mt][1]), "=r"(a[mt][2]), "=r"(a[mt][3])
                    : "r"(ad));
            }
            uint32_t bfr[4][4];
#pragma unroll
            for (int g = 0; g < 4; g++) {
                int nrow = n0w + g * 16 + ((lane >> 4) << 3) + (lane & 7);
                int kcol = kk + (((lane >> 3) & 1) << 3);
                uint32_t ad = smem_u32(Bb + nrow * SM_STRIDE + kcol);
                asm volatile("ldmatrix.sync.aligned.m8n8.x4.shared.b16 {%0,%1,%2,%3}, [%4];"
                    : "=r"(bfr[g][0]), "=r"(bfr[g][1]), "=r"(bfr[g][2]), "=r"(bfr[g][3])
                    : "r"(ad));
            }
#pragma unroll
            for (int mt = 0; mt < 2; mt++)
#pragma unroll
                for (int nt = 0; nt < 8; nt++) {
                    int g = nt >> 1, pr = (nt & 1) * 2;
                    asm volatile(
                        "mma.sync.aligned.m16n8k16.row.col.f32.bf16.bf16.f32 "
                        "{%0,%1,%2,%3}, {%4,%5,%6,%7}, {%8,%9}, {%0,%1,%2,%3};"
                        : "+f"(acc[mt][nt][0]), "+f"(acc[mt][nt][1]),
                          "+f"(acc[mt][nt][2]), "+f"(acc[mt][nt][3])
                        : "r"(a[mt][0]), "r"(a[mt][1]), "r"(a[mt][2]), "r"(a[mt][3]),
                          "r"(bfr[g][pr]), "r"(bfr[g][pr + 1]));
                }
        }
        __syncthreads();
    }

    // epilogue
#pragma unroll
    for (int mt = 0; mt < 2; mt++) {
        int mA = m0 + m0w + mt * 16 + (lane >> 2);
#pragma unroll
        for (int nt = 0; nt < 8; nt++) {
            int n = n0 + n0w + nt * 8 + (lane & 3) * 2;
            if (n >= N) continue;
            float b0 = bias ? bias[n] : 0.f;
            float b1 = bias ? bias[n + 1] : 0.f;
            *(float2*)&C[(size_t)mA * ldc + n] =
                make_float2(acc[mt][nt][0] + b0, acc[mt][nt][1] + b1);
            *(float2*)&C[(size_t)(mA + 8) * ldc + n] =
                make_float2(acc[mt][nt][2] + b0, acc[mt][nt][3] + b1);
        }
    }
}

// ---------------------------------------------------------------------------
// 128x128 fp32 SGEMM (NT) for the gated full-path scores.
// ---------------------------------------------------------------------------
__global__ __launch_bounds__(256)
void gemm128(const float* __restrict__ A, int lda, long sAb, long sAh,
             const float* __restrict__ B, int ldb, long sBb, long sBh,
             float* __restrict__ C, int ldc, long sCb, long sCh,
             int K, float alpha, const float* __restrict__ bias,
             int nh, const int* __restrict__ gate)
{
    __shared__ float As[16][132];
    __shared__ float Bs[16][132];
    int z = blockIdx.z;
    int b = z / nh, h = z % nh;
    if (gate && gate[b] != 0) return;
    A += (size_t)b * sAb + (size_t)h * sAh;
    B += (size_t)b * sBb + (size_t)h * sBh;
    C += (size_t)b * sCb + (size_t)h * sCh;

    int tid = threadIdx.x;
    int tx = tid & 15, ty = tid >> 4;
    int m0 = blockIdx.y * 128, n0 = blockIdx.x * 128;

    float acc[8][8];
#pragma unroll
    for (int i = 0; i < 8; i++)
#pragma unroll
        for (int j = 0; j < 8; j++) acc[i][j] = 0.f;

    for (int k0 = 0; k0 < K; k0 += 16) {
#pragma unroll
        for (int i = 0; i < 8; i++) {
            int idx = tid + i * 256;
            int m = idx >> 4, kk = idx & 15;
            As[kk][m] = A[(size_t)(m0 + m) * lda + k0 + kk];
            Bs[kk][m] = B[(size_t)(n0 + m) * ldb + k0 + kk];
        }
        __syncthreads();
#pragma unroll
        for (int kk = 0; kk < 16; kk++) {
            float4 a0 = *(const float4*)&As[kk][ty * 8];
            float4 a1 = *(const float4*)&As[kk][ty * 8 + 4];
            float4 b0 = *(const float4*)&Bs[kk][tx * 8];
            float4 b1 = *(const float4*)&Bs[kk][tx * 8 + 4];
            float av[8] = {a0.x, a0.y, a0.z, a0.w, a1.x, a1.y, a1.z, a1.w};
            float bv[8] = {b0.x, b0.y, b0.z, b0.w, b1.x, b1.y, b1.z, b1.w};
#pragma unroll
            for (int i = 0; i < 8; i++)
#pragma unroll
                for (int j = 0; j < 8; j++) acc[i][j] += av[i] * bv[j];
        }
        __syncthreads();
    }
#pragma unroll
    for (int i = 0; i < 8; i++) {
        int m = m0 + ty * 8 + i;
        float out[8];
#pragma unroll
        for (int j = 0; j < 8; j++) {
            out[j] = acc[i][j] * alpha;
            if (bias) out[j] += bias[n0 + tx * 8 + j];
        }
        float4* cp = (float4*)&C[(size_t)m * ldc + n0 + tx * 8];
        cp[0] = make_float4(out[0], out[1], out[2], out[3]);
        cp[1] = make_float4(out[4], out[5], out[6], out[7]);
    }
}

// ---------------------------------------------------------------------------
// 64x64 SGEMM (NT/NN) for the gated AV path.
// ---------------------------------------------------------------------------
__global__ __launch_bounds__(256)
void gemm_bt(const float* __restrict__ A, int lda, long sAb, long sAh,
             const float* __restrict__ B, int ldb, long sBb, long sBh,
             float* __restrict__ C, int ldc, long sCb, long sCh,
             int M, int N, int K, float alpha,
             const float* __restrict__ bias, int nh, int bTrans,
             const int* __restrict__ gate)
{
    __shared__ float As[16][65];
    __shared__ float Bs[16][65];
    int z = blockIdx.z;
    int b = z / nh, h = z % nh;
    if (gate && gate[b] != 0) return;
    A += (size_t)b * sAb + (size_t)h * sAh;
    B += (size_t)b * sBb + (size_t)h * sBh;
    C += (size_t)b * sCb + (size_t)h * sCh;

    int tid = threadIdx.x;
    int tx = tid & 15, ty = tid >> 4;
    int m0 = blockIdx.y * 64, n0 = blockIdx.x * 64;

    float acc[4][4];
#pragma unroll
    for (int i = 0; i < 4; i++)
#pragma unroll
        for (int j = 0; j < 4; j++) acc[i][j] = 0.f;

    for (int k0 = 0; k0 < K; k0 += 16) {
#pragma unroll
        for (int i = 0; i < 4; i++) {
            int idx = tid + i * 256;
            int m = idx >> 4, kk = idx & 15;
            As[kk][m] = A[(size_t)(m0 + m) * lda + k0 + kk];
        }
        if (bTrans) {
#pragma unroll
            for (int i = 0; i < 4; i++) {
                int idx = tid + i * 256;
                int n = idx >> 4, kk = idx & 15;
                Bs[kk][n] = B[(size_t)(n0 + n) * ldb + k0 + kk];
            }
        } else {
#pragma unroll
            for (int i = 0; i < 4; i++) {
                int idx = tid + i * 256;
                int n = idx & 63, kk = idx >> 6;
                Bs[kk][n] = B[(size_t)(k0 + kk) * ldb + n0 + n];
            }
        }
        __syncthreads();
#pragma unroll
        for (int kk = 0; kk < 16; kk++) {
            float a[4], bb[4];
#pragma unroll
            for (int i = 0; i < 4; i++) a[i] = As[kk][ty * 4 + i];
#pragma unroll
            for (int j = 0; j < 4; j++) bb[j] = Bs[kk][tx * 4 + j];
#pragma unroll
            for (int i = 0; i < 4; i++)
#pragma unroll
                for (int j = 0; j < 4; j++) acc[i][j] += a[i] * bb[j];
        }
        __syncthreads();
    }
#pragma unroll
    for (int i = 0; i < 4; i++) {
        int m = m0 + ty * 4 + i;
#pragma unroll
        for (int j = 0; j < 4; j++) {
            int n = n0 + tx * 4 + j;
            float v = acc[i][j] * alpha;
            if (bias) v += bias[n];
            C[(size_t)m * ldc + n] = v;
        }
    }
}

// ---------------------------------------------------------------------------
__global__ __launch_bounds__(256)
void pool1_kernel(const float* __restrict__ x)
{
    int blk = blockIdx.x;
    int b = blk >> 3, c = blk & 7;
    int tid = threadIdx.x;
    const float2* xp = (const float2*)(x + ((size_t)b * LL + c * 128) * DD) + tid;
    float s0 = 0.f, s1 = 0.f;
    for (int l = 0; l < 128; l++) {
        float2 v = xp[(size_t)l * (DD / 2)];
        s0 += v.x; s1 += v.y;
    }
    g_pool_part[blk][tid * 2]     = s0;
    g_pool_part[blk][tid * 2 + 1] = s1;
}

// ---------------------------------------------------------------------------
__global__ __launch_bounds__(256)
void pattern_kernel(const float* __restrict__ w1, const float* __restrict__ b1,
                    const float* __restrict__ w2, const float* __restrict__ b2,
                    const float* __restrict__ w3, const float* __restrict__ b3,
                    const float* __restrict__ pbias)
{
    int b = blockIdx.x, tid = threadIdx.x;
    int warp = tid >> 5, lane = tid & 31;
    __shared__ float pooled[DD];
    __shared__ float h1[DD];
    __shared__ float h2[DD / 2];
    __shared__ float lg[3];

    for (int d = tid; d < DD; d += 256) {
        float s = 0.f;
#pragma unroll
        for (int c = 0; c < 8; c++) s += g_pool_part[b * 8 + c][d];
        pooled[d] = s * (1.0f / LL);
    }
    __syncthreads();
    for (int i = warp; i < DD; i += 8) {
        const float* wr = w1 + (size_t)i * DD;
        float a = 0.f;
        for (int k = lane; k < DD; k += 32) a += pooled[k] * wr[k];
#pragma unroll
        for (int o = 16; o > 0; o >>= 1) a += __shfl_xor_sync(~0u, a, o);
        if (lane == 0) h1[i] = fmaxf(a + b1[i], 0.f);
    }
    __syncthreads();
    for (int i = warp; i < DD / 2; i += 8) {
        const float* wr = w2 + (size_t)i * DD;
        float a = 0.f;
        for (int k = lane; k < DD; k += 32) a += h1[k] * wr[k];
#pragma unroll
        for (int o = 16; o > 0; o >>= 1) a += __shfl_xor_sync(~0u, a, o);
        if (lane == 0) h2[i] = fmaxf(a + b2[i], 0.f);
    }
    __syncthreads();
    if (warp < 3) {
        const float* wr = w3 + (size_t)warp * (DD / 2);
        float a = 0.f;
        for (int k = lane; k < DD / 2; k += 32) a += h2[k] * wr[k];
#pragma unroll
        for (int o = 16; o > 0; o >>= 1) a += __shfl_xor_sync(~0u, a, o);
        if (lane == 0) lg[warp] = (a + b3[warp] + pbias[warp]) / 0.3f;
    }
    __syncthreads();
    if (tid == 0) {
        float m = fmaxf(lg[0], fmaxf(lg[1], lg[2]));
        float e0 = expf(lg[0] - m), e1 = expf(lg[1] - m), e2 = expf(lg[2] - m);
        float inv = 1.f / (e0 + e1 + e2);
        float p0 = e0 * inv, p1 = e1 * inv, p2 = e2 * inv;
        g_pw[b * 3 + 0] = p0;
        g_pw[b * 3 + 1] = p1;
        g_pw[b * 3 + 2] = p2;
        bool A00 = p1 > THRESH;
        bool A01 = (p1 + p2) > THRESH;
        bool A10 = (p0 + p1) > THRESH;
        bool A11 = ((p0 + p1) + p2) > THRESH;
        bool need_sparse = (A00 != A01) || (A10 != A11);
        int mode;
        if (need_sparse || A00) mode = 0;
        else if (A10)           mode = 1;
        else                    mode = 2;
        g_mode[b] = mode;
    }
}

// ---------------------------------------------------------------------------
__device__ __forceinline__ void write_split(int m, int col, float v)
{
    __nv_bfloat16 hi = __float2bfloat16(v);
    __nv_bfloat16 lo = __float2bfloat16(v - __bfloat162float(hi));
    __nv_bfloat16* d = g_ahl + (size_t)m * K3 + col;
    d[0] = hi; d[DD] = lo; d[2 * DD] = hi;
}

// ---------------------------------------------------------------------------
// Local-window fused attention (mode 1) + all-masked fallback (mode 2).
// ---------------------------------------------------------------------------
__global__ __launch_bounds__(256)
void local_attn_kernel()
{
    __shared__ float ksh[48][65];
    __shared__ float vsh[48][65];
    __shared__ float qsh[16][64];
    __shared__ float psh[16][33];

    int blk = blockIdx.x;
    int b = blk >> 9;
    int h = (blk >> 6) & 7;
    int q0 = (blk & 63) * 16;
    int mode = g_mode[b];
    if (mode == 0) return;
    int tid = threadIdx.x;
    const float* base = g_qkv + (size_t)b * LL * QKVD + h * HD;

    if (mode == 2) {
        const float* v0 = base + 2 * DD;
#pragma unroll
        for (int i = 0; i < 4; i++) {
            int idx = tid + i * 256;
            int r = idx >> 6, d = idx & 63;
            write_split(b * LL + q0 + r, h * HD + d, v0[d]);
        }
        return;
    }

    int kb0 = max(q0 - 16, 0);
    int kend = min(q0 + 15 + 16, LL - 1);
    int klen = kend - kb0 + 1;

    for (int i = tid; i < klen * 64; i += 256) {
        int jj = i >> 6, d = i & 63;
        const float* src = base + (size_t)(kb0 + jj) * QKVD;
        ksh[jj][d] = src[DD + d];
        vsh[jj][d] = src[2 * DD + d];
    }
#pragma unroll
    for (int i = 0; i < 4; i++) {
        int idx = tid + i * 256;
        int r = idx >> 6, d = idx & 63;
        qsh[r][d] = base[(size_t)(q0 + r) * QKVD + d];
    }
    __syncthreads();

    int warp = tid >> 5, lane = tid & 31;
#pragma unroll
    for (int rr = 0; rr < 2; rr++) {
        int r = warp * 2 + rr;
        int q = q0 + r;
        int w0 = max(q - 16, 0), w1 = min(q + 16, LL - 1);
        int cnt = w1 - w0 + 1;
        int off = w0 - kb0;

        float s0 = NEG_INF, s1 = NEG_INF;
        if (lane < cnt) {
            float acc = 0.f;
#pragma unroll
            for (int d = 0; d < 64; d++) acc += qsh[r][d] * ksh[off + lane][d];
            s0 = acc * SCALE;
        }
        if (lane + 32 < cnt) {
            float acc = 0.f;
#pragma unroll
            for (int d = 0; d < 64; d++) acc += qsh[r][d] * ksh[off + lane + 32][d];
            s1 = acc * SCALE;
        }
        float m = fmaxf(s0, s1);
#pragma unroll
        for (int o = 16; o > 0; o >>= 1) m = fmaxf(m, __shfl_xor_sync(~0u, m, o));
        float e0 = (lane < cnt) ? __expf(s0 - m) : 0.f;
        float e1 = (lane + 32 < cnt) ? __expf(s1 - m) : 0.f;
        float sum = e0 + e1;
#pragma unroll
        for (int o = 16; o > 0; o >>= 1) sum += __shfl_xor_sync(~0u, sum, o);
        float inv = 1.f / sum;
        if (lane < cnt) psh[r][lane] = e0 * inv;
        if (lane + 32 < cnt) psh[r][lane + 32] = e1 * inv;
        __syncwarp();

        float o0 = 0.f, o1 = 0.f;
        for (int jj = 0; jj < cnt; jj++) {
            float p = psh[r][jj];
            o0 += p * vsh[off + jj][lane];
            o1 += p * vsh[off + jj][lane + 32];
        }
        int m_out = b * LL + q;
        write_split(m_out, h * HD + lane, o0);
        write_split(m_out, h * HD + lane + 32, o1);
    }
}

// ---------------------------------------------------------------------------
// Full-path mask + softmax (mode 0 only). 16 rows per block.
// ---------------------------------------------------------------------------
__device__ __forceinline__ unsigned fkey(float f) {
    unsigned u = __float_as_uint(f);
    return (u & 0x80000000u) ? ~u : (u | 0x80000000u);
}

__global__ __launch_bounds__(256)
void softmax_kernel(const float* __restrict__ sparse_w,
                    const float* __restrict__ sparse_b)
{
    __shared__ float s[LL];
    __shared__ float red[256];
    __shared__ unsigned hist[256];
    __shared__ unsigned sel_prefix, sel_k;
    __shared__ float mx_sh;

    int grp = blockIdx.x;
    int z = grp >> 6;
    int b = z >> 3, h = z & 7;
    if (g_mode[b] != 0) return;
    int q_base = (grp & 63) * 16;
    int tid = threadIdx.x;

    float p0 = g_pw[b * 3 + 0];
    float p1 = g_pw[b * 3 + 1];
    float p2 = g_pw[b * 3 + 2];
    bool A00 = p1 > THRESH;
    bool A01 = (p1 + p2) > THRESH;
    bool A10 = (p0 + p1) > THRESH;
    bool A11 = ((p0 + p1) + p2) > THRESH;
    bool need_sparse = (A00 != A01) || (A10 != A11);
    float w_h = sparse_w[h], b_h = sparse_b[h];

    for (int r = 0; r < 16; r++) {
        int q = q_base + r;
        float* srow = g_scores + ((size_t)z << 20) + ((size_t)q << 10);
        ((float4*)s)[tid] = ((const float4*)srow)[tid];
        __syncthreads();

        unsigned tu = 0u;
        if (need_sparse) {
            if (tid == 0) { sel_prefix = 0u; sel_k = KTOP; }
            __syncthreads();
            for (int shift = 24; shift >= 0; shift -= 8) {
                hist[tid] = 0u;
                __syncthreads();
                unsigned pref = sel_prefix;
                unsigned hm = (shift == 24) ? 0u : (0xFFFFFFFFu << (shift + 8));
                for (int j = tid; j < LL; j += 256) {
                    float v = __fadd_rn(__fmul_rn(s[j], w_h), b_h);
                    unsigned u = fkey(v);
                    if ((u & hm) == pref) atomicAdd(&hist[(u >> shift) & 255u], 1u);
                }
                __syncthreads();
                if (tid == 0) {
                    unsigned k = sel_k, cum = 0;
                    for (int dgt = 255; dgt >= 0; --dgt) {
                        unsigned c = hist[dgt];
                        if (cum + c >= k) {
                            sel_prefix = pref | ((unsigned)dgt << shift);
                            sel_k = k - cum;
                            break;
                        }
                        cum += c;
                    }
                }
                __syncthreads();
            }
            tu = sel_prefix;
            __syncthreads();
        }

        float v[4];
        float lm = NEG_INF;
#pragma unroll
        for (int i = 0; i < 4; i++) {
            int j = tid * 4 + i;
            float sv = s[j];
            bool lf = (abs(q - j) <= 16);
            bool allow;
            if (need_sparse) {
                float s2 = __fadd_rn(__fmul_rn(sv, w_h), b_h);
                float sf = (fkey(s2) >= tu) ? 1.f : 0.f;
                float comb = (p0 * (lf ? 1.f : 0.f) + p1) + p2 * sf;
                allow = comb > THRESH;
            } else {
                allow = lf ? A10 : A00;
            }
            v[i] = allow ? sv : NEG_INF;
            lm = fmaxf(lm, v[i]);
        }
        red[tid] = lm; __syncthreads();
        for (int o = 128; o > 0; o >>= 1) {
            if (tid < o) red[tid] = fmaxf(red[tid], red[tid + o]);
            __syncthreads();
        }
        if (tid == 0) mx_sh = red[0];
        __syncthreads();
        float mx = mx_sh;

        if (mx == NEG_INF) {
            float4 o;
            o.x = (tid == 0) ? 1.f : 0.f; o.y = 0.f; o.z = 0.f; o.w = 0.f;
            ((float4*)srow)[tid] = o;
            __syncthreads();
            continue;
        }

        float ls = 0.f;
#pragma unroll
        for (int i = 0; i < 4; i++) {
            v[i] = __expf(v[i] - mx);
            ls += v[i];
        }
        red[tid] = ls; __syncthreads();
        for (int o = 128; o > 0; o >>= 1) {
            if (tid < o) red[tid] += red[tid + o];
            __syncthreads();
        }
        if (tid == 0) mx_sh = 1.f / red[0];
        __syncthreads();
        float inv = mx_sh;
        float4 o;
        o.x = v[0] * inv; o.y = v[1] * inv; o.z = v[2] * inv; o.w = v[3] * inv;
        ((float4*)srow)[tid] = o;
        __syncthreads();
    }
}

// ---------------------------------------------------------------------------
extern "C" void kernel_launch(void* const* d_in, const int* in_sizes, int n_in,
                              void* d_out, int out_size)
{
    const float* x        = (const float*)d_in[0];
    const float* qkv_w    = (const float*)d_in[1];
    const float* proj_w   = (const float*)d_in[2];
    const float* proj_b   = (const float*)d_in[3];
    const float* ps_w1    = (const float*)d_in[4];
    const float* ps_b1    = (const float*)d_in[5];
    const float* ps_w2    = (const float*)d_in[6];
    const float* ps_b2    = (const float*)d_in[7];
    const float* ps_w3    = (const float*)d_in[8];
    const float* ps_b3    = (const float*)d_in[9];
    const float* pbias    = (const float*)d_in[10];
    const float* sparse_w = (const float*)d_in[11];
    const float* sparse_b = (const float*)d_in[12];
    float* out = (float*)d_out;

    float *qkv_p, *sc_p, *attn_p;
    int *mode_p;
    __nv_bfloat16 *xhl_p, *wqhl_p, *ahl_p, *pwhl_p;
    cudaGetSymbolAddress((void**)&qkv_p,  g_qkv);
    cudaGetSymbolAddress((void**)&sc_p,   g_scores);
    cudaGetSymbolAddress((void**)&attn_p, g_attn);
    cudaGetSymbolAddress((void**)&mode_p, g_mode);
    cudaGetSymbolAddress((void**)&xhl_p,  g_xhl);
    cudaGetSymbolAddress((void**)&wqhl_p, g_wqhl);
    cudaGetSymbolAddress((void**)&ahl_p,  g_ahl);
    cudaGetSymbolAddress((void**)&pwhl_p, g_pwhl);

    // One-time setup (first call is the uncaptured correctness run)
    static cudaStream_t s1 = nullptr, s2 = nullptr;
    static cudaEvent_t eFork = nullptr, eMode = nullptr, eWq = nullptr,
                       eWp = nullptr, eQkv = nullptr, eFull = nullptr;
    if (!s1) {
        cudaStreamCreateWithFlags(&s1, cudaStreamNonBlocking);
        cudaStreamCreateWithFlags(&s2, cudaStreamNonBlocking);
        cudaEventCreateWithFlags(&eFork, cudaEventDisableTiming);
        cudaEventCreateWithFlags(&eMode, cudaEventDisableTiming);
        cudaEventCreateWithFlags(&eWq,   cudaEventDisableTiming);
        cudaEventCreateWithFlags(&eWp,   cudaEventDisableTiming);
        cudaEventCreateWithFlags(&eQkv,  cudaEventDisableTiming);
        cudaEventCreateWithFlags(&eFull, cudaEventDisableTiming);
        cudaFuncSetAttribute(gemm_mma, cudaFuncAttributeMaxDynamicSharedMemorySize,
                             4 * SM_CHUNK * (int)sizeof(__nv_bfloat16));
    }
    const int dyn_smem = 4 * SM_CHUNK * (int)sizeof(__nv_bfloat16);

    // Fork side streams off the main (capture-origin) stream
    cudaEventRecord(eFork, 0);
    cudaStreamWaitEvent(s1, eFork, 0);
    cudaStreamWaitEvent(s2, eFork, 0);

    // s1: pattern-selector chain -> g_mode
    pool1_kernel<<<32, 256, 0, s1>>>(x);
    pattern_kernel<<<BB, 256, 0, s1>>>(ps_w1, ps_b1, ps_w2, ps_b2, ps_w3, ps_b3, pbias);
    cudaEventRecord(eMode, s1);

    // s2: weight conversions
    cvt_split<0><<<(QKVD * DD / 4 + 255) / 256, 256, 0, s2>>>(qkv_w, wqhl_p, QKVD, nullptr);
    cudaEventRecord(eWq, s2);
    cvt_split<0><<<(DD * DD / 4 + 255) / 256, 256, 0, s2>>>(proj_w, pwhl_p, DD, nullptr);
    cudaEventRecord(eWp, s2);

    // main: x conversion, then QKV GEMM (needs eWq)
    cvt_split<1><<<(ML * DD / 4 + 255) / 256, 256>>>(x, xhl_p, ML, nullptr);
    cudaStreamWaitEvent(0, eWq, 0);
    gemm_mma<<<dim3(QKVD / 128, ML / 128), 256, dyn_smem>>>(
        xhl_p, wqhl_p, qkv_p, QKVD, QKVD, nullptr);
    cudaEventRecord(eQkv, 0);

    // s1: gated full path (needs mode [already ordered on s1] and QKV)
    cudaStreamWaitEvent(s1, eQkv, 0);
    gemm128<<<dim3(LL / 128, LL / 128, BB * HH), 256, 0, s1>>>(
        qkv_p, QKVD, (long)LL * QKVD, HD,
        qkv_p + DD, QKVD, (long)LL * QKVD, HD,
        sc_p, LL, (long)HH * LL * LL, (long)LL * LL,
        HD, SCALE, nullptr, HH, mode_p);
    softmax_kernel<<<BB * HH * (LL / 16), 256, 0, s1>>>(sparse_w, sparse_b);
    gemm_bt<<<dim3(HD / 64, LL / 64, BB * HH), 256, 0, s1>>>(
        sc_p, LL, (long)HH * LL * LL, (long)LL * LL,
        qkv_p + 2 * DD, QKVD, (long)LL * QKVD, HD,
        attn_p, DD, (long)LL * DD, HD,
        LL, HD, LL, 1.f, nullptr, HH, 0, mode_p);
    cvt_split<1><<<(ML * DD / 4 + 255) / 256, 256, 0, s1>>>(attn_p, ahl_p, ML, mode_p);
    cudaEventRecord(eFull, s1);

    // main: local/all-masked path (needs mode + QKV); overlaps with s1 stubs
    cudaStreamWaitEvent(0, eMode, 0);
    local_attn_kernel<<<BB * HH * (LL / 16), 256>>>();

    // join: proj GEMM needs g_ahl complete (local + gated full) and proj weights
    cudaStreamWaitEvent(0, eFull, 0);
    cudaStreamWaitEvent(0, eWp, 0);
    gemm_mma<<<dim3(DD / 128, ML / 128), 256, dyn_smem>>>(
        ahl_p, pwhl_p, out, DD, DD, proj_b);
}

// round 10
// speedup vs baseline: 8.5246x; 1.0388x over previous
#include <cuda_runtime.h>
#include <cuda_bf16.h>
#include <cstdint>
#include <math.h>

#define BB 4
#define LL 1024
#define DD 512
#define HH 8
#define HD 64
#define QKVD 1536
#define ML (BB*LL)
#define K3 1536              // 3 * 512 split-K for bf16x2 GEMM
#define KTOP 716
#define THRESH 0.05f
#define SCALE 0.125f
#define NEG_INF __int_as_float(0xff800000)

#define NCHUNK (K3 / 64)             // 24 chunks of K=64
#define STAGE_BYTES 32768            // A(16KB) + B(16KB) per stage
#define GM_DSM (3 * STAGE_BYTES + 128)

// Scratch (device globals; no allocations allowed)
__device__ float g_qkv[ML * QKVD];
__device__ float g_scores[(size_t)BB * HH * LL * LL];
__device__ float g_attn[ML * DD];
__device__ float g_pw[BB * 3];
__device__ int   g_mode[BB];
__device__ float g_pool_part[32][DD];
// bf16x2 split buffers
__device__ __nv_bfloat16 g_xhl[ML * K3];
__device__ __nv_bfloat16 g_wqhl[QKVD * K3];
__device__ __nv_bfloat16 g_ahl[ML * K3];
__device__ __nv_bfloat16 g_pwhl[DD * K3];

__device__ __forceinline__ uint32_t smem_u32(const void* p) {
    return (uint32_t)__cvta_generic_to_shared(p);
}
__device__ __forceinline__ void cp16(uint32_t dst, const void* src) {
    asm volatile("cp.async.cg.shared.global [%0], [%1], 16;\n" :: "r"(dst), "l"(src));
}
// row r (0..127), 16B unit u (0..7) inside a 128-row x 128B swizzled buffer
__device__ __forceinline__ uint32_t swz(uint32_t bufbase, int r, int u) {
    return bufbase + r * 128 + ((u ^ (r & 7)) << 4);
}

// ---------------------------------------------------------------------------
// fp32 -> bf16 hi/lo split. Astyle: [hi | lo | hi]. Bstyle: [hi | hi | lo].
// ---------------------------------------------------------------------------
template<int ASTYLE>
__global__ __launch_bounds__(256)
void cvt_split(const float* __restrict__ src, __nv_bfloat16* __restrict__ dst,
               int M, const int* __restrict__ gate)
{
    int i = blockIdx.x * 256 + threadIdx.x;
    int total = M * (DD / 4);
    if (i >= total) return;
    int m = i / (DD / 4), c = i % (DD / 4);
    if (gate && gate[m / LL] != 0) return;
    float4 v = ((const float4*)(src + (size_t)m * DD))[c];
    __nv_bfloat16 hi[4], lo[4];
    float vv[4] = {v.x, v.y, v.z, v.w};
#pragma unroll
    for (int t = 0; t < 4; t++) {
        hi[t] = __float2bfloat16(vv[t]);
        lo[t] = __float2bfloat16(vv[t] - __bfloat162float(hi[t]));
    }
    __nv_bfloat16* d = dst + (size_t)m * K3 + c * 4;
    __nv_bfloat162* d0 = (__nv_bfloat162*)(d);
    __nv_bfloat162* d1 = (__nv_bfloat162*)(d + DD);
    __nv_bfloat162* d2 = (__nv_bfloat162*)(d + 2 * DD);
    __nv_bfloat162 hp0 = {hi[0], hi[1]}, hp1 = {hi[2], hi[3]};
    __nv_bfloat162 lp0 = {lo[0], lo[1]}, lp1 = {lo[2], lo[3]};
    d0[0] = hp0; d0[1] = hp1;
    if (ASTYLE) {
        d1[0] = lp0; d1[1] = lp1;
        d2[0] = hp0; d2[1] = hp1;
    } else {
        d1[0] = hp0; d1[1] = hp1;
        d2[0] = lp0; d2[1] = lp1;
    }
}

// ---------------------------------------------------------------------------
// bf16 NT GEMM via mma.sync m16n8k16, 3-stage cp.async pipeline,
// XOR-swizzled 128B-row smem (no padding), one barrier per K-chunk.
// 128x128 tile, 8 warps (4m x 2n), warp tile 32x64.
// ---------------------------------------------------------------------------
__global__ __launch_bounds__(256, 2)
void gemm_mma(const __nv_bfloat16* __restrict__ A2,
              const __nv_bfloat16* __restrict__ B2,
              float* __restrict__ C, int ldc, int N,
              const float* __restrict__ bias)
{
    extern __shared__ char dsm[];
    uint32_t base = (smem_u32(dsm) + 127) & ~127u;
    int tid = threadIdx.x;
    int warp = tid >> 5, lane = tid & 31;
    int wm = warp >> 1, wn = warp & 1;
    int m0 = blockIdx.y * 128, n0 = blockIdx.x * 128;
    int m0w = wm * 32, n0w = wn * 64;

    float acc[2][8][4];
#pragma unroll
    for (int a = 0; a < 2; a++)
#pragma unroll
        for (int b = 0; b < 8; b++)
#pragma unroll
            for (int c = 0; c < 4; c++) acc[a][b][c] = 0.f;

    int u = tid & 7, row0 = tid >> 3;

    auto issue = [&](int chunk) {
        int s = chunk % 3;
        uint32_t bA = base + s * STAGE_BYTES;
        uint32_t bB = bA + 16384;
        int k0 = chunk * 64;
#pragma unroll
        for (int p = 0; p < 4; p++) {
            int r = row0 + p * 32;
            cp16(swz(bA, r, u), A2 + (size_t)(m0 + r) * K3 + k0 + u * 8);
            cp16(swz(bB, r, u), B2 + (size_t)(n0 + r) * K3 + k0 + u * 8);
        }
        asm volatile("cp.async.commit_group;\n");
    };

    issue(0);
    issue(1);

    for (int c = 0; c < NCHUNK; c++) {
        if (c + 2 < NCHUNK) {
            asm volatile("cp.async.wait_group 1;\n");
        } else {
            asm volatile("cp.async.wait_group 0;\n");
        }
        __syncthreads();
        if (c + 2 < NCHUNK) issue(c + 2);

        int s = c % 3;
        uint32_t bA = base + s * STAGE_BYTES;
        uint32_t bB = bA + 16384;
#pragma unroll
        for (int kk = 0; kk < 64; kk += 16) {
            int ub = kk >> 3;
            uint32_t a[2][4];
#pragma unroll
            for (int mt = 0; mt < 2; mt++) {
                int mrow = m0w + mt * 16 + (lane & 15);
                int un = ub + (lane >> 4);
                uint32_t ad = swz(bA, mrow, un);
                asm volatile("ldmatrix.sync.aligned.m8n8.x4.shared.b16 {%0,%1,%2,%3}, [%4];"
                    : "=r"(a[mt][0]), "=r"(a[mt][1]), "=r"(a[mt][2]), "=r"(a[mt][3])
                    : "r"(ad));
            }
            uint32_t bfr[4][4];
#pragma unroll
            for (int g = 0; g < 4; g++) {
                int nrow = n0w + g * 16 + ((lane >> 4) << 3) + (lane & 7);
                int un = ub + ((lane >> 3) & 1);
                uint32_t ad = swz(bB, nrow, un);
                asm volatile("ldmatrix.sync.aligned.m8n8.x4.shared.b16 {%0,%1,%2,%3}, [%4];"
                    : "=r"(bfr[g][0]), "=r"(bfr[g][1]), "=r"(bfr[g][2]), "=r"(bfr[g][3])
                    : "r"(ad));
            }
#pragma unroll
            for (int mt = 0; mt < 2; mt++)
#pragma unroll
                for (int nt = 0; nt < 8; nt++) {
                    int g = nt >> 1, pr = (nt & 1) * 2;
                    asm volatile(
                        "mma.sync.aligned.m16n8k16.row.col.f32.bf16.bf16.f32 "
                        "{%0,%1,%2,%3}, {%4,%5,%6,%7}, {%8,%9}, {%0,%1,%2,%3};"
                        : "+f"(acc[mt][nt][0]), "+f"(acc[mt][nt][1]),
                          "+f"(acc[mt][nt][2]), "+f"(acc[mt][nt][3])
                        : "r"(a[mt][0]), "r"(a[mt][1]), "r"(a[mt][2]), "r"(a[mt][3]),
                          "r"(bfr[g][pr]), "r"(bfr[g][pr + 1]));
                }
        }
    }

    // epilogue
#pragma unroll
    for (int mt = 0; mt < 2; mt++) {
        int mA = m0 + m0w + mt * 16 + (lane >> 2);
#pragma unroll
        for (int nt = 0; nt < 8; nt++) {
            int n = n0 + n0w + nt * 8 + (lane & 3) * 2;
            if (n >= N) continue;
            float b0 = bias ? bias[n] : 0.f;
            float b1 = bias ? bias[n + 1] : 0.f;
            *(float2*)&C[(size_t)mA * ldc + n] =
                make_float2(acc[mt][nt][0] + b0, acc[mt][nt][1] + b1);
            *(float2*)&C[(size_t)(mA + 8) * ldc + n] =
                make_float2(acc[mt][nt][2] + b0, acc[mt][nt][3] + b1);
        }
    }
}

// ---------------------------------------------------------------------------
// 128x128 fp32 SGEMM (NT) for the gated full-path scores.
// ---------------------------------------------------------------------------
__global__ __launch_bounds__(256)
void gemm128(const float* __restrict__ A, int lda, long sAb, long sAh,
             const float* __restrict__ B, int ldb, long sBb, long sBh,
             float* __restrict__ C, int ldc, long sCb, long sCh,
             int K, float alpha, const float* __restrict__ bias,
             int nh, const int* __restrict__ gate)
{
    __shared__ float As[16][132];
    __shared__ float Bs[16][132];
    int z = blockIdx.z;
    int b = z / nh, h = z % nh;
    if (gate && gate[b] != 0) return;
    A += (size_t)b * sAb + (size_t)h * sAh;
    B += (size_t)b * sBb + (size_t)h * sBh;
    C += (size_t)b * sCb + (size_t)h * sCh;

    int tid = threadIdx.x;
    int tx = tid & 15, ty = tid >> 4;
    int m0 = blockIdx.y * 128, n0 = blockIdx.x * 128;

    float acc[8][8];
#pragma unroll
    for (int i = 0; i < 8; i++)
#pragma unroll
        for (int j = 0; j < 8; j++) acc[i][j] = 0.f;

    for (int k0 = 0; k0 < K; k0 += 16) {
#pragma unroll
        for (int i = 0; i < 8; i++) {
            int idx = tid + i * 256;
            int m = idx >> 4, kk = idx & 15;
            As[kk][m] = A[(size_t)(m0 + m) * lda + k0 + kk];
            Bs[kk][m] = B[(size_t)(n0 + m) * ldb + k0 + kk];
        }
        __syncthreads();
#pragma unroll
        for (int kk = 0; kk < 16; kk++) {
            float4 a0 = *(const float4*)&As[kk][ty * 8];
            float4 a1 = *(const float4*)&As[kk][ty * 8 + 4];
            float4 b0 = *(const float4*)&Bs[kk][tx * 8];
            float4 b1 = *(const float4*)&Bs[kk][tx * 8 + 4];
            float av[8] = {a0.x, a0.y, a0.z, a0.w, a1.x, a1.y, a1.z, a1.w};
            float bv[8] = {b0.x, b0.y, b0.z, b0.w, b1.x, b1.y, b1.z, b1.w};
#pragma unroll
            for (int i = 0; i < 8; i++)
#pragma unroll
                for (int j = 0; j < 8; j++) acc[i][j] += av[i] * bv[j];
        }
        __syncthreads();
    }
#pragma unroll
    for (int i = 0; i < 8; i++) {
        int m = m0 + ty * 8 + i;
        float out[8];
#pragma unroll
        for (int j = 0; j < 8; j++) {
            out[j] = acc[i][j] * alpha;
            if (bias) out[j] += bias[n0 + tx * 8 + j];
        }
        float4* cp = (float4*)&C[(size_t)m * ldc + n0 + tx * 8];
        cp[0] = make_float4(out[0], out[1], out[2], out[3]);
        cp[1] = make_float4(out[4], out[5], out[6], out[7]);
    }
}

// ---------------------------------------------------------------------------
// 64x64 SGEMM (NT/NN) for the gated AV path.
// ---------------------------------------------------------------------------
__global__ __launch_bounds__(256)
void gemm_bt(const float* __restrict__ A, int lda, long sAb, long sAh,
             const float* __restrict__ B, int ldb, long sBb, long sBh,
             float* __restrict__ C, int ldc, long sCb, long sCh,
             int M, int N, int K, float alpha,
             const float* __restrict__ bias, int nh, int bTrans,
             const int* __restrict__ gate)
{
    __shared__ float As[16][65];
    __shared__ float Bs[16][65];
    int z = blockIdx.z;
    int b = z / nh, h = z % nh;
    if (gate && gate[b] != 0) return;
    A += (size_t)b * sAb + (size_t)h * sAh;
    B += (size_t)b * sBb + (size_t)h * sBh;
    C += (size_t)b * sCb + (size_t)h * sCh;

    int tid = threadIdx.x;
    int tx = tid & 15, ty = tid >> 4;
    int m0 = blockIdx.y * 64, n0 = blockIdx.x * 64;

    float acc[4][4];
#pragma unroll
    for (int i = 0; i < 4; i++)
#pragma unroll
        for (int j = 0; j < 4; j++) acc[i][j] = 0.f;

    for (int k0 = 0; k0 < K; k0 += 16) {
#pragma unroll
        for (int i = 0; i < 4; i++) {
            int idx = tid + i * 256;
            int m = idx >> 4, kk = idx & 15;
            As[kk][m] = A[(size_t)(m0 + m) * lda + k0 + kk];
        }
        if (bTrans) {
#pragma unroll
            for (int i = 0; i < 4; i++) {
                int idx = tid + i * 256;
                int n = idx >> 4, kk = idx & 15;
                Bs[kk][n] = B[(size_t)(n0 + n) * ldb + k0 + kk];
            }
        } else {
#pragma unroll
            for (int i = 0; i < 4; i++) {
                int idx = tid + i * 256;
                int n = idx & 63, kk = idx >> 6;
                Bs[kk][n] = B[(size_t)(k0 + kk) * ldb + n0 + n];
            }
        }
        __syncthreads();
#pragma unroll
        for (int kk = 0; kk < 16; kk++) {
            float a[4], bb[4];
#pragma unroll
            for (int i = 0; i < 4; i++) a[i] = As[kk][ty * 4 + i];
#pragma unroll
            for (int j = 0; j < 4; j++) bb[j] = Bs[kk][tx * 4 + j];
#pragma unroll
            for (int i = 0; i < 4; i++)
#pragma unroll
                for (int j = 0; j < 4; j++) acc[i][j] += a[i] * bb[j];
        }
        __syncthreads();
    }
#pragma unroll
    for (int i = 0; i < 4; i++) {
        int m = m0 + ty * 4 + i;
#pragma unroll
        for (int j = 0; j < 4; j++) {
            int n = n0 + tx * 4 + j;
            float v = acc[i][j] * alpha;
            if (bias) v += bias[n];
            C[(size_t)m * ldc + n] = v;
        }
    }
}

// ---------------------------------------------------------------------------
__global__ __launch_bounds__(256)
void pool1_kernel(const float* __restrict__ x)
{
    int blk = blockIdx.x;
    int b = blk >> 3, c = blk & 7;
    int tid = threadIdx.x;
    const float2* xp = (const float2*)(x + ((size_t)b * LL + c * 128) * DD) + tid;
    float s0 = 0.f, s1 = 0.f;
    for (int l = 0; l < 128; l++) {
        float2 v = xp[(size_t)l * (DD / 2)];
        s0 += v.x; s1 += v.y;
    }
    g_pool_part[blk][tid * 2]     = s0;
    g_pool_part[blk][tid * 2 + 1] = s1;
}

// ---------------------------------------------------------------------------
__global__ __launch_bounds__(256)
void pattern_kernel(const float* __restrict__ w1, const float* __restrict__ b1,
                    const float* __restrict__ w2, const float* __restrict__ b2,
                    const float* __restrict__ w3, const float* __restrict__ b3,
                    const float* __restrict__ pbias)
{
    int b = blockIdx.x, tid = threadIdx.x;
    int warp = tid >> 5, lane = tid & 31;
    __shared__ float pooled[DD];
    __shared__ float h1[DD];
    __shared__ float h2[DD / 2];
    __shared__ float lg[3];

    for (int d = tid; d < DD; d += 256) {
        float s = 0.f;
#pragma unroll
        for (int c = 0; c < 8; c++) s += g_pool_part[b * 8 + c][d];
        pooled[d] = s * (1.0f / LL);
    }
    __syncthreads();
    for (int i = warp; i < DD; i += 8) {
        const float* wr = w1 + (size_t)i * DD;
        float a = 0.f;
        for (int k = lane; k < DD; k += 32) a += pooled[k] * wr[k];
#pragma unroll
        for (int o = 16; o > 0; o >>= 1) a += __shfl_xor_sync(~0u, a, o);
        if (lane == 0) h1[i] = fmaxf(a + b1[i], 0.f);
    }
    __syncthreads();
    for (int i = warp; i < DD / 2; i += 8) {
        const float* wr = w2 + (size_t)i * DD;
        float a = 0.f;
        for (int k = lane; k < DD; k += 32) a += h1[k] * wr[k];
#pragma unroll
        for (int o = 16; o > 0; o >>= 1) a += __shfl_xor_sync(~0u, a, o);
        if (lane == 0) h2[i] = fmaxf(a + b2[i], 0.f);
    }
    __syncthreads();
    if (warp < 3) {
        const float* wr = w3 + (size_t)warp * (DD / 2);
        float a = 0.f;
        for (int k = lane; k < DD / 2; k += 32) a += h2[k] * wr[k];
#pragma unroll
        for (int o = 16; o > 0; o >>= 1) a += __shfl_xor_sync(~0u, a, o);
        if (lane == 0) lg[warp] = (a + b3[warp] + pbias[warp]) / 0.3f;
    }
    __syncthreads();
    if (tid == 0) {
        float m = fmaxf(lg[0], fmaxf(lg[1], lg[2]));
        float e0 = expf(lg[0] - m), e1 = expf(lg[1] - m), e2 = expf(lg[2] - m);
        float inv = 1.f / (e0 + e1 + e2);
        float p0 = e0 * inv, p1 = e1 * inv, p2 = e2 * inv;
        g_pw[b * 3 + 0] = p0;
        g_pw[b * 3 + 1] = p1;
        g_pw[b * 3 + 2] = p2;
        bool A00 = p1 > THRESH;
        bool A01 = (p1 + p2) > THRESH;
        bool A10 = (p0 + p1) > THRESH;
        bool A11 = ((p0 + p1) + p2) > THRESH;
        bool need_sparse = (A00 != A01) || (A10 != A11);
        int mode;
        if (need_sparse || A00) mode = 0;
        else if (A10)           mode = 1;
        else                    mode = 2;
        g_mode[b] = mode;
    }
}

// ---------------------------------------------------------------------------
__device__ __forceinline__ void write_split(int m, int col, float v)
{
    __nv_bfloat16 hi = __float2bfloat16(v);
    __nv_bfloat16 lo = __float2bfloat16(v - __bfloat162float(hi));
    __nv_bfloat16* d = g_ahl + (size_t)m * K3 + col;
    d[0] = hi; d[DD] = lo; d[2 * DD] = hi;
}

// ---------------------------------------------------------------------------
// Local-window fused attention (mode 1) + all-masked fallback (mode 2).
// ---------------------------------------------------------------------------
__global__ __launch_bounds__(256)
void local_attn_kernel()
{
    __shared__ float ksh[48][65];
    __shared__ float vsh[48][65];
    __shared__ float qsh[16][64];
    __shared__ float psh[16][33];

    int blk = blockIdx.x;
    int b = blk >> 9;
    int h = (blk >> 6) & 7;
    int q0 = (blk & 63) * 16;
    int mode = g_mode[b];
    if (mode == 0) return;
    int tid = threadIdx.x;
    const float* base = g_qkv + (size_t)b * LL * QKVD + h * HD;

    if (mode == 2) {
        const float* v0 = base + 2 * DD;
#pragma unroll
        for (int i = 0; i < 4; i++) {
            int idx = tid + i * 256;
            int r = idx >> 6, d = idx & 63;
            write_split(b * LL + q0 + r, h * HD + d, v0[d]);
        }
        return;
    }

    int kb0 = max(q0 - 16, 0);
    int kend = min(q0 + 15 + 16, LL - 1);
    int klen = kend - kb0 + 1;

    for (int i = tid; i < klen * 64; i += 256) {
        int jj = i >> 6, d = i & 63;
        const float* src = base + (size_t)(kb0 + jj) * QKVD;
        ksh[jj][d] = src[DD + d];
        vsh[jj][d] = src[2 * DD + d];
    }
#pragma unroll
    for (int i = 0; i < 4; i++) {
        int idx = tid + i * 256;
        int r = idx >> 6, d = idx & 63;
        qsh[r][d] = base[(size_t)(q0 + r) * QKVD + d];
    }
    __syncthreads();

    int warp = tid >> 5, lane = tid & 31;
#pragma unroll
    for (int rr = 0; rr < 2; rr++) {
        int r = warp * 2 + rr;
        int q = q0 + r;
        int w0 = max(q - 16, 0), w1 = min(q + 16, LL - 1);
        int cnt = w1 - w0 + 1;
        int off = w0 - kb0;

        float s0 = NEG_INF, s1 = NEG_INF;
        if (lane < cnt) {
            float acc = 0.f;
#pragma unroll
            for (int d = 0; d < 64; d++) acc += qsh[r][d] * ksh[off + lane][d];
            s0 = acc * SCALE;
        }
        if (lane + 32 < cnt) {
            float acc = 0.f;
#pragma unroll
            for (int d = 0; d < 64; d++) acc += qsh[r][d] * ksh[off + lane + 32][d];
            s1 = acc * SCALE;
        }
        float m = fmaxf(s0, s1);
#pragma unroll
        for (int o = 16; o > 0; o >>= 1) m = fmaxf(m, __shfl_xor_sync(~0u, m, o));
        float e0 = (lane < cnt) ? __expf(s0 - m) : 0.f;
        float e1 = (lane + 32 < cnt) ? __expf(s1 - m) : 0.f;
        float sum = e0 + e1;
#pragma unroll
        for (int o = 16; o > 0; o >>= 1) sum += __shfl_xor_sync(~0u, sum, o);
        float inv = 1.f / sum;
        if (lane < cnt) psh[r][lane] = e0 * inv;
        if (lane + 32 < cnt) psh[r][lane + 32] = e1 * inv;
        __syncwarp();

        float o0 = 0.f, o1 = 0.f;
        for (int jj = 0; jj < cnt; jj++) {
            float p = psh[r][jj];
            o0 += p * vsh[off + jj][lane];
            o1 += p * vsh[off + jj][lane + 32];
        }
        int m_out = b * LL + q;
        write_split(m_out, h * HD + lane, o0);
        write_split(m_out, h * HD + lane + 32, o1);
    }
}

// ---------------------------------------------------------------------------
// Full-path mask + softmax (mode 0 only). 16 rows per block.
// ---------------------------------------------------------------------------
__device__ __forceinline__ unsigned fkey(float f) {
    unsigned u = __float_as_uint(f);
    return (u & 0x80000000u) ? ~u : (u | 0x80000000u);
}

__global__ __launch_bounds__(256)
void softmax_kernel(const float* __restrict__ sparse_w,
                    const float* __restrict__ sparse_b)
{
    __shared__ float s[LL];
    __shared__ float red[256];
    __shared__ unsigned hist[256];
    __shared__ unsigned sel_prefix, sel_k;
    __shared__ float mx_sh;

    int grp = blockIdx.x;
    int z = grp >> 6;
    int b = z >> 3, h = z & 7;
    if (g_mode[b] != 0) return;
    int q_base = (grp & 63) * 16;
    int tid = threadIdx.x;

    float p0 = g_pw[b * 3 + 0];
    float p1 = g_pw[b * 3 + 1];
    float p2 = g_pw[b * 3 + 2];
    bool A00 = p1 > THRESH;
    bool A01 = (p1 + p2) > THRESH;
    bool A10 = (p0 + p1) > THRESH;
    bool A11 = ((p0 + p1) + p2) > THRESH;
    bool need_sparse = (A00 != A01) || (A10 != A11);
    float w_h = sparse_w[h], b_h = sparse_b[h];

    for (int r = 0; r < 16; r++) {
        int q = q_base + r;
        float* srow = g_scores + ((size_t)z << 20) + ((size_t)q << 10);
        ((float4*)s)[tid] = ((const float4*)srow)[tid];
        __syncthreads();

        unsigned tu = 0u;
        if (need_sparse) {
            if (tid == 0) { sel_prefix = 0u; sel_k = KTOP; }
            __syncthreads();
            for (int shift = 24; shift >= 0; shift -= 8) {
                hist[tid] = 0u;
                __syncthreads();
                unsigned pref = sel_prefix;
                unsigned hm = (shift == 24) ? 0u : (0xFFFFFFFFu << (shift + 8));
                for (int j = tid; j < LL; j += 256) {
                    float v = __fadd_rn(__fmul_rn(s[j], w_h), b_h);
                    unsigned u = fkey(v);
                    if ((u & hm) == pref) atomicAdd(&hist[(u >> shift) & 255u], 1u);
                }
                __syncthreads();
                if (tid == 0) {
                    unsigned k = sel_k, cum = 0;
                    for (int dgt = 255; dgt >= 0; --dgt) {
                        unsigned c = hist[dgt];
                        if (cum + c >= k) {
                            sel_prefix = pref | ((unsigned)dgt << shift);
                            sel_k = k - cum;
                            break;
                        }
                        cum += c;
                    }
                }
                __syncthreads();
            }
            tu = sel_prefix;
            __syncthreads();
        }

        float v[4];
        float lm = NEG_INF;
#pragma unroll
        for (int i = 0; i < 4; i++) {
            int j = tid * 4 + i;
            float sv = s[j];
            bool lf = (abs(q - j) <= 16);
            bool allow;
            if (need_sparse) {
                float s2 = __fadd_rn(__fmul_rn(sv, w_h), b_h);
                float sf = (fkey(s2) >= tu) ? 1.f : 0.f;
                float comb = (p0 * (lf ? 1.f : 0.f) + p1) + p2 * sf;
                allow = comb > THRESH;
            } else {
                allow = lf ? A10 : A00;
            }
            v[i] = allow ? sv : NEG_INF;
            lm = fmaxf(lm, v[i]);
        }
        red[tid] = lm; __syncthreads();
        for (int o = 128; o > 0; o >>= 1) {
            if (tid < o) red[tid] = fmaxf(red[tid], red[tid + o]);
            __syncthreads();
        }
        if (tid == 0) mx_sh = red[0];
        __syncthreads();
        float mx = mx_sh;

        if (mx == NEG_INF) {
            float4 o;
            o.x = (tid == 0) ? 1.f : 0.f; o.y = 0.f; o.z = 0.f; o.w = 0.f;
            ((float4*)srow)[tid] = o;
            __syncthreads();
            continue;
        }

        float ls = 0.f;
#pragma unroll
        for (int i = 0; i < 4; i++) {
            v[i] = __expf(v[i] - mx);
            ls += v[i];
        }
        red[tid] = ls; __syncthreads();
        for (int o = 128; o > 0; o >>= 1) {
            if (tid < o) red[tid] += red[tid + o];
            __syncthreads();
        }
        if (tid == 0) mx_sh = 1.f / red[0];
        __syncthreads();
        float inv = mx_sh;
        float4 o;
        o.x = v[0] * inv; o.y = v[1] * inv; o.z = v[2] * inv; o.w = v[3] * inv;
        ((float4*)srow)[tid] = o;
        __syncthreads();
    }
}

// ---------------------------------------------------------------------------
extern "C" void kernel_launch(void* const* d_in, const int* in_sizes, int n_in,
                              void* d_out, int out_size)
{
    const float* x        = (const float*)d_in[0];
    const float* qkv_w    = (const float*)d_in[1];
    const float* proj_w   = (const float*)d_in[2];
    const float* proj_b   = (const float*)d_in[3];
    const float* ps_w1    = (const float*)d_in[4];
    const float* ps_b1    = (const float*)d_in[5];
    const float* ps_w2    = (const float*)d_in[6];
    const float* ps_b2    = (const float*)d_in[7];
    const float* ps_w3    = (const float*)d_in[8];
    const float* ps_b3    = (const float*)d_in[9];
    const float* pbias    = (const float*)d_in[10];
    const float* sparse_w = (const float*)d_in[11];
    const float* sparse_b = (const float*)d_in[12];
    float* out = (float*)d_out;

    float *qkv_p, *sc_p, *attn_p;
    int *mode_p;
    __nv_bfloat16 *xhl_p, *wqhl_p, *ahl_p, *pwhl_p;
    cudaGetSymbolAddress((void**)&qkv_p,  g_qkv);
    cudaGetSymbolAddress((void**)&sc_p,   g_scores);
    cudaGetSymbolAddress((void**)&attn_p, g_attn);
    cudaGetSymbolAddress((void**)&mode_p, g_mode);
    cudaGetSymbolAddress((void**)&xhl_p,  g_xhl);
    cudaGetSymbolAddress((void**)&wqhl_p, g_wqhl);
    cudaGetSymbolAddress((void**)&ahl_p,  g_ahl);
    cudaGetSymbolAddress((void**)&pwhl_p, g_pwhl);

    // One-time setup (first call is the uncaptured correctness run)
    static cudaStream_t s1 = nullptr, s2 = nullptr;
    static cudaEvent_t eFork = nullptr, eMode = nullptr, eWq = nullptr,
                       eWp = nullptr, eQkv = nullptr, eFull = nullptr;
    if (!s1) {
        cudaStreamCreateWithFlags(&s1, cudaStreamNonBlocking);
        cudaStreamCreateWithFlags(&s2, cudaStreamNonBlocking);
        cudaEventCreateWithFlags(&eFork, cudaEventDisableTiming);
        cudaEventCreateWithFlags(&eMode, cudaEventDisableTiming);
        cudaEventCreateWithFlags(&eWq,   cudaEventDisableTiming);
        cudaEventCreateWithFlags(&eWp,   cudaEventDisableTiming);
        cudaEventCreateWithFlags(&eQkv,  cudaEventDisableTiming);
        cudaEventCreateWithFlags(&eFull, cudaEventDisableTiming);
        cudaFuncSetAttribute(gemm_mma, cudaFuncAttributeMaxDynamicSharedMemorySize, GM_DSM);
    }

    // Fork side streams off the main (capture-origin) stream
    cudaEventRecord(eFork, 0);
    cudaStreamWaitEvent(s1, eFork, 0);
    cudaStreamWaitEvent(s2, eFork, 0);

    // s1: pattern-selector chain -> g_mode
    pool1_kernel<<<32, 256, 0, s1>>>(x);
    pattern_kernel<<<BB, 256, 0, s1>>>(ps_w1, ps_b1, ps_w2, ps_b2, ps_w3, ps_b3, pbias);
    cudaEventRecord(eMode, s1);

    // s2: weight conversions
    cvt_split<0><<<(QKVD * DD / 4 + 255) / 256, 256, 0, s2>>>(qkv_w, wqhl_p, QKVD, nullptr);
    cudaEventRecord(eWq, s2);
    cvt_split<0><<<(DD * DD / 4 + 255) / 256, 256, 0, s2>>>(proj_w, pwhl_p, DD, nullptr);
    cudaEventRecord(eWp, s2);

    // main: x conversion, then QKV GEMM (needs eWq)
    cvt_split<1><<<(ML * DD / 4 + 255) / 256, 256>>>(x, xhl_p, ML, nullptr);
    cudaStreamWaitEvent(0, eWq, 0);
    gemm_mma<<<dim3(QKVD / 128, ML / 128), 256, GM_DSM>>>(
        xhl_p, wqhl_p, qkv_p, QKVD, QKVD, nullptr);
    cudaEventRecord(eQkv, 0);

    // s1: gated full path (needs mode [already ordered on s1] and QKV)
    cudaStreamWaitEvent(s1, eQkv, 0);
    gemm128<<<dim3(LL / 128, LL / 128, BB * HH), 256, 0, s1>>>(
        qkv_p, QKVD, (long)LL * QKVD, HD,
        qkv_p + DD, QKVD, (long)LL * QKVD, HD,
        sc_p, LL, (long)HH * LL * LL, (long)LL * LL,
        HD, SCALE, nullptr, HH, mode_p);
    softmax_kernel<<<BB * HH * (LL / 16), 256, 0, s1>>>(sparse_w, sparse_b);
    gemm_bt<<<dim3(HD / 64, LL / 64, BB * HH), 256, 0, s1>>>(
        sc_p, LL, (long)HH * LL * LL, (long)LL * LL,
        qkv_p + 2 * DD, QKVD, (long)LL * QKVD, HD,
        attn_p, DD, (long)LL * DD, HD,
        LL, HD, LL, 1.f, nullptr, HH, 0, mode_p);
    cvt_split<1><<<(ML * DD / 4 + 255) / 256, 256, 0, s1>>>(attn_p, ahl_p, ML, mode_p);
    cudaEventRecord(eFull, s1);

    // main: local/all-masked path (needs mode + QKV); overlaps with s1 stubs
    cudaStreamWaitEvent(0, eMode, 0);
    local_attn_kernel<<<BB * HH * (LL / 16), 256>>>();

    // join: proj GEMM needs g_ahl complete (local + gated full) and proj weights
    cudaStreamWaitEvent(0, eFull, 0);
    cudaStreamWaitEvent(0, eWp, 0);
    gemm_mma<<<dim3(DD / 128, ML / 128), 256, GM_DSM>>>(
        ahl_p, pwhl_p, out, DD, DD, proj_b);
}

// round 11
// speedup vs baseline: 9.4424x; 1.1077x over previous
#include <cuda_runtime.h>
#include <cuda_bf16.h>
#include <cstdint>
#include <math.h>

#define BB 4
#define LL 1024
#define DD 512
#define HH 8
#define HD 64
#define QKVD 1536
#define ML (BB*LL)
#define K3 1536              // 3 * 512 split-K for bf16x2 GEMM
#define KTOP 716
#define THRESH 0.05f
#define SCALE 0.125f
#define NEG_INF __int_as_float(0xff800000)

#define NCHUNK (K3 / 64)             // 24 chunks of K=64
#define STAGE_BYTES 32768            // A(16KB) + B(16KB) per stage
#define GM_DSM (3 * STAGE_BYTES + 128)

// Scratch (device globals; no allocations allowed)
__device__ float g_qkv[ML * QKVD];
__device__ float g_scores[(size_t)BB * HH * LL * LL];
__device__ float g_attn[ML * DD];
__device__ float g_pw[BB * 3];
__device__ int   g_mode[BB];
__device__ float g_pool_part[32][DD];
// bf16x2 split buffers
__device__ __nv_bfloat16 g_xhl[ML * K3];
__device__ __nv_bfloat16 g_wqhl[QKVD * K3];
__device__ __nv_bfloat16 g_ahl[ML * K3];
__device__ __nv_bfloat16 g_pwhl[DD * K3];

__device__ __forceinline__ uint32_t smem_u32(const void* p) {
    return (uint32_t)__cvta_generic_to_shared(p);
}
__device__ __forceinline__ void cp16(uint32_t dst, const void* src) {
    asm volatile("cp.async.cg.shared.global [%0], [%1], 16;\n" :: "r"(dst), "l"(src));
}
// row r (0..127), 16B unit u (0..7) inside a 128-row x 128B swizzled buffer
__device__ __forceinline__ uint32_t swz(uint32_t bufbase, int r, int u) {
    return bufbase + r * 128 + ((u ^ (r & 7)) << 4);
}

// ---------------------------------------------------------------------------
// fp32 -> bf16 hi/lo split. Astyle: [hi | lo | hi]. Bstyle: [hi | hi | lo].
// ---------------------------------------------------------------------------
template<int ASTYLE>
__global__ __launch_bounds__(256)
void cvt_split(const float* __restrict__ src, __nv_bfloat16* __restrict__ dst,
               int M, const int* __restrict__ gate)
{
    int i = blockIdx.x * 256 + threadIdx.x;
    int total = M * (DD / 4);
    if (i >= total) return;
    int m = i / (DD / 4), c = i % (DD / 4);
    if (gate && gate[m / LL] != 0) return;
    float4 v = ((const float4*)(src + (size_t)m * DD))[c];
    __nv_bfloat16 hi[4], lo[4];
    float vv[4] = {v.x, v.y, v.z, v.w};
#pragma unroll
    for (int t = 0; t < 4; t++) {
        hi[t] = __float2bfloat16(vv[t]);
        lo[t] = __float2bfloat16(vv[t] - __bfloat162float(hi[t]));
    }
    __nv_bfloat16* d = dst + (size_t)m * K3 + c * 4;
    __nv_bfloat162* d0 = (__nv_bfloat162*)(d);
    __nv_bfloat162* d1 = (__nv_bfloat162*)(d + DD);
    __nv_bfloat162* d2 = (__nv_bfloat162*)(d + 2 * DD);
    __nv_bfloat162 hp0 = {hi[0], hi[1]}, hp1 = {hi[2], hi[3]};
    __nv_bfloat162 lp0 = {lo[0], lo[1]}, lp1 = {lo[2], lo[3]};
    d0[0] = hp0; d0[1] = hp1;
    if (ASTYLE) {
        d1[0] = lp0; d1[1] = lp1;
        d2[0] = hp0; d2[1] = hp1;
    } else {
        d1[0] = hp0; d1[1] = hp1;
        d2[0] = lp0; d2[1] = lp1;
    }
}

// ---------------------------------------------------------------------------
// bf16 NT GEMM via mma.sync m16n8k16, 3-stage cp.async pipeline,
// XOR-swizzled smem, one barrier per K-chunk. m_base allows row-split launches.
// ---------------------------------------------------------------------------
__global__ __launch_bounds__(256, 2)
void gemm_mma(const __nv_bfloat16* __restrict__ A2,
              const __nv_bfloat16* __restrict__ B2,
              float* __restrict__ C, int ldc, int N,
              const float* __restrict__ bias, int m_base)
{
    extern __shared__ char dsm[];
    uint32_t base = (smem_u32(dsm) + 127) & ~127u;
    int tid = threadIdx.x;
    int warp = tid >> 5, lane = tid & 31;
    int wm = warp >> 1, wn = warp & 1;
    int m0 = m_base + blockIdx.y * 128, n0 = blockIdx.x * 128;
    int m0w = wm * 32, n0w = wn * 64;

    float acc[2][8][4];
#pragma unroll
    for (int a = 0; a < 2; a++)
#pragma unroll
        for (int b = 0; b < 8; b++)
#pragma unroll
            for (int c = 0; c < 4; c++) acc[a][b][c] = 0.f;

    int u = tid & 7, row0 = tid >> 3;

    auto issue = [&](int chunk) {
        int s = chunk % 3;
        uint32_t bA = base + s * STAGE_BYTES;
        uint32_t bB = bA + 16384;
        int k0 = chunk * 64;
#pragma unroll
        for (int p = 0; p < 4; p++) {
            int r = row0 + p * 32;
            cp16(swz(bA, r, u), A2 + (size_t)(m0 + r) * K3 + k0 + u * 8);
            cp16(swz(bB, r, u), B2 + (size_t)(n0 + r) * K3 + k0 + u * 8);
        }
        asm volatile("cp.async.commit_group;\n");
    };

    issue(0);
    issue(1);

    for (int c = 0; c < NCHUNK; c++) {
        if (c + 2 < NCHUNK) {
            asm volatile("cp.async.wait_group 1;\n");
        } else {
            asm volatile("cp.async.wait_group 0;\n");
        }
        __syncthreads();
        if (c + 2 < NCHUNK) issue(c + 2);

        int s = c % 3;
        uint32_t bA = base + s * STAGE_BYTES;
        uint32_t bB = bA + 16384;
#pragma unroll
        for (int kk = 0; kk < 64; kk += 16) {
            int ub = kk >> 3;
            uint32_t a[2][4];
#pragma unroll
            for (int mt = 0; mt < 2; mt++) {
                int mrow = m0w + mt * 16 + (lane & 15);
                int un = ub + (lane >> 4);
                uint32_t ad = swz(bA, mrow, un);
                asm volatile("ldmatrix.sync.aligned.m8n8.x4.shared.b16 {%0,%1,%2,%3}, [%4];"
                    : "=r"(a[mt][0]), "=r"(a[mt][1]), "=r"(a[mt][2]), "=r"(a[mt][3])
                    : "r"(ad));
            }
            uint32_t bfr[4][4];
#pragma unroll
            for (int g = 0; g < 4; g++) {
                int nrow = n0w + g * 16 + ((lane >> 4) << 3) + (lane & 7);
                int un = ub + ((lane >> 3) & 1);
                uint32_t ad = swz(bB, nrow, un);
                asm volatile("ldmatrix.sync.aligned.m8n8.x4.shared.b16 {%0,%1,%2,%3}, [%4];"
                    : "=r"(bfr[g][0]), "=r"(bfr[g][1]), "=r"(bfr[g][2]), "=r"(bfr[g][3])
                    : "r"(ad));
            }
#pragma unroll
            for (int mt = 0; mt < 2; mt++)
#pragma unroll
                for (int nt = 0; nt < 8; nt++) {
                    int g = nt >> 1, pr = (nt & 1) * 2;
                    asm volatile(
                        "mma.sync.aligned.m16n8k16.row.col.f32.bf16.bf16.f32 "
                        "{%0,%1,%2,%3}, {%4,%5,%6,%7}, {%8,%9}, {%0,%1,%2,%3};"
                        : "+f"(acc[mt][nt][0]), "+f"(acc[mt][nt][1]),
                          "+f"(acc[mt][nt][2]), "+f"(acc[mt][nt][3])
                        : "r"(a[mt][0]), "r"(a[mt][1]), "r"(a[mt][2]), "r"(a[mt][3]),
                          "r"(bfr[g][pr]), "r"(bfr[g][pr + 1]));
                }
        }
    }

    // epilogue
#pragma unroll
    for (int mt = 0; mt < 2; mt++) {
        int mA = m0 + m0w + mt * 16 + (lane >> 2);
#pragma unroll
        for (int nt = 0; nt < 8; nt++) {
            int n = n0 + n0w + nt * 8 + (lane & 3) * 2;
            if (n >= N) continue;
            float b0 = bias ? bias[n] : 0.f;
            float b1 = bias ? bias[n + 1] : 0.f;
            *(float2*)&C[(size_t)mA * ldc + n] =
                make_float2(acc[mt][nt][0] + b0, acc[mt][nt][1] + b1);
            *(float2*)&C[(size_t)(mA + 8) * ldc + n] =
                make_float2(acc[mt][nt][2] + b0, acc[mt][nt][3] + b1);
        }
    }
}

// ---------------------------------------------------------------------------
// 128x128 fp32 SGEMM (NT) for the gated full-path scores.
// ---------------------------------------------------------------------------
__global__ __launch_bounds__(256)
void gemm128(const float* __restrict__ A, int lda, long sAb, long sAh,
             const float* __restrict__ B, int ldb, long sBb, long sBh,
             float* __restrict__ C, int ldc, long sCb, long sCh,
             int K, float alpha, const float* __restrict__ bias,
             int nh, const int* __restrict__ gate)
{
    __shared__ float As[16][132];
    __shared__ float Bs[16][132];
    int z = blockIdx.z;
    int b = z / nh, h = z % nh;
    if (gate && gate[b] != 0) return;
    A += (size_t)b * sAb + (size_t)h * sAh;
    B += (size_t)b * sBb + (size_t)h * sBh;
    C += (size_t)b * sCb + (size_t)h * sCh;

    int tid = threadIdx.x;
    int tx = tid & 15, ty = tid >> 4;
    int m0 = blockIdx.y * 128, n0 = blockIdx.x * 128;

    float acc[8][8];
#pragma unroll
    for (int i = 0; i < 8; i++)
#pragma unroll
        for (int j = 0; j < 8; j++) acc[i][j] = 0.f;

    for (int k0 = 0; k0 < K; k0 += 16) {
#pragma unroll
        for (int i = 0; i < 8; i++) {
            int idx = tid + i * 256;
            int m = idx >> 4, kk = idx & 15;
            As[kk][m] = A[(size_t)(m0 + m) * lda + k0 + kk];
            Bs[kk][m] = B[(size_t)(n0 + m) * ldb + k0 + kk];
        }
        __syncthreads();
#pragma unroll
        for (int kk = 0; kk < 16; kk++) {
            float4 a0 = *(const float4*)&As[kk][ty * 8];
            float4 a1 = *(const float4*)&As[kk][ty * 8 + 4];
            float4 b0 = *(const float4*)&Bs[kk][tx * 8];
            float4 b1 = *(const float4*)&Bs[kk][tx * 8 + 4];
            float av[8] = {a0.x, a0.y, a0.z, a0.w, a1.x, a1.y, a1.z, a1.w};
            float bv[8] = {b0.x, b0.y, b0.z, b0.w, b1.x, b1.y, b1.z, b1.w};
#pragma unroll
            for (int i = 0; i < 8; i++)
#pragma unroll
                for (int j = 0; j < 8; j++) acc[i][j] += av[i] * bv[j];
        }
        __syncthreads();
    }
#pragma unroll
    for (int i = 0; i < 8; i++) {
        int m = m0 + ty * 8 + i;
        float out[8];
#pragma unroll
        for (int j = 0; j < 8; j++) {
            out[j] = acc[i][j] * alpha;
            if (bias) out[j] += bias[n0 + tx * 8 + j];
        }
        float4* cp = (float4*)&C[(size_t)m * ldc + n0 + tx * 8];
        cp[0] = make_float4(out[0], out[1], out[2], out[3]);
        cp[1] = make_float4(out[4], out[5], out[6], out[7]);
    }
}

// ---------------------------------------------------------------------------
// 64x64 SGEMM (NT/NN) for the gated AV path.
// ---------------------------------------------------------------------------
__global__ __launch_bounds__(256)
void gemm_bt(const float* __restrict__ A, int lda, long sAb, long sAh,
             const float* __restrict__ B, int ldb, long sBb, long sBh,
             float* __restrict__ C, int ldc, long sCb, long sCh,
             int M, int N, int K, float alpha,
             const float* __restrict__ bias, int nh, int bTrans,
             const int* __restrict__ gate)
{
    __shared__ float As[16][65];
    __shared__ float Bs[16][65];
    int z = blockIdx.z;
    int b = z / nh, h = z % nh;
    if (gate && gate[b] != 0) return;
    A += (size_t)b * sAb + (size_t)h * sAh;
    B += (size_t)b * sBb + (size_t)h * sBh;
    C += (size_t)b * sCb + (size_t)h * sCh;

    int tid = threadIdx.x;
    int tx = tid & 15, ty = tid >> 4;
    int m0 = blockIdx.y * 64, n0 = blockIdx.x * 64;

    float acc[4][4];
#pragma unroll
    for (int i = 0; i < 4; i++)
#pragma unroll
        for (int j = 0; j < 4; j++) acc[i][j] = 0.f;

    for (int k0 = 0; k0 < K; k0 += 16) {
#pragma unroll
        for (int i = 0; i < 4; i++) {
            int idx = tid + i * 256;
            int m = idx >> 4, kk = idx & 15;
            As[kk][m] = A[(size_t)(m0 + m) * lda + k0 + kk];
        }
        if (bTrans) {
#pragma unroll
            for (int i = 0; i < 4; i++) {
                int idx = tid + i * 256;
                int n = idx >> 4, kk = idx & 15;
                Bs[kk][n] = B[(size_t)(n0 + n) * ldb + k0 + kk];
            }
        } else {
#pragma unroll
            for (int i = 0; i < 4; i++) {
                int idx = tid + i * 256;
                int n = idx & 63, kk = idx >> 6;
                Bs[kk][n] = B[(size_t)(k0 + kk) * ldb + n0 + n];
            }
        }
        __syncthreads();
#pragma unroll
        for (int kk = 0; kk < 16; kk++) {
            float a[4], bb[4];
#pragma unroll
            for (int i = 0; i < 4; i++) a[i] = As[kk][ty * 4 + i];
#pragma unroll
            for (int j = 0; j < 4; j++) bb[j] = Bs[kk][tx * 4 + j];
#pragma unroll
            for (int i = 0; i < 4; i++)
#pragma unroll
                for (int j = 0; j < 4; j++) acc[i][j] += a[i] * bb[j];
        }
        __syncthreads();
    }
#pragma unroll
    for (int i = 0; i < 4; i++) {
        int m = m0 + ty * 4 + i;
#pragma unroll
        for (int j = 0; j < 4; j++) {
            int n = n0 + tx * 4 + j;
            float v = acc[i][j] * alpha;
            if (bias) v += bias[n];
            C[(size_t)m * ldc + n] = v;
        }
    }
}

// ---------------------------------------------------------------------------
__global__ __launch_bounds__(256)
void pool1_kernel(const float* __restrict__ x)
{
    int blk = blockIdx.x;
    int b = blk >> 3, c = blk & 7;
    int tid = threadIdx.x;
    const float2* xp = (const float2*)(x + ((size_t)b * LL + c * 128) * DD) + tid;
    float s0 = 0.f, s1 = 0.f;
    for (int l = 0; l < 128; l++) {
        float2 v = xp[(size_t)l * (DD / 2)];
        s0 += v.x; s1 += v.y;
    }
    g_pool_part[blk][tid * 2]     = s0;
    g_pool_part[blk][tid * 2 + 1] = s1;
}

// ---------------------------------------------------------------------------
__global__ __launch_bounds__(256)
void pattern_kernel(const float* __restrict__ w1, const float* __restrict__ b1,
                    const float* __restrict__ w2, const float* __restrict__ b2,
                    const float* __restrict__ w3, const float* __restrict__ b3,
                    const float* __restrict__ pbias)
{
    int b = blockIdx.x, tid = threadIdx.x;
    int warp = tid >> 5, lane = tid & 31;
    __shared__ float pooled[DD];
    __shared__ float h1[DD];
    __shared__ float h2[DD / 2];
    __shared__ float lg[3];

    for (int d = tid; d < DD; d += 256) {
        float s = 0.f;
#pragma unroll
        for (int c = 0; c < 8; c++) s += g_pool_part[b * 8 + c][d];
        pooled[d] = s * (1.0f / LL);
    }
    __syncthreads();
    for (int i = warp; i < DD; i += 8) {
        const float* wr = w1 + (size_t)i * DD;
        float a = 0.f;
        for (int k = lane; k < DD; k += 32) a += pooled[k] * wr[k];
#pragma unroll
        for (int o = 16; o > 0; o >>= 1) a += __shfl_xor_sync(~0u, a, o);
        if (lane == 0) h1[i] = fmaxf(a + b1[i], 0.f);
    }
    __syncthreads();
    for (int i = warp; i < DD / 2; i += 8) {
        const float* wr = w2 + (size_t)i * DD;
        float a = 0.f;
        for (int k = lane; k < DD; k += 32) a += h1[k] * wr[k];
#pragma unroll
        for (int o = 16; o > 0; o >>= 1) a += __shfl_xor_sync(~0u, a, o);
        if (lane == 0) h2[i] = fmaxf(a + b2[i], 0.f);
    }
    __syncthreads();
    if (warp < 3) {
        const float* wr = w3 + (size_t)warp * (DD / 2);
        float a = 0.f;
        for (int k = lane; k < DD / 2; k += 32) a += h2[k] * wr[k];
#pragma unroll
        for (int o = 16; o > 0; o >>= 1) a += __shfl_xor_sync(~0u, a, o);
        if (lane == 0) lg[warp] = (a + b3[warp] + pbias[warp]) / 0.3f;
    }
    __syncthreads();
    if (tid == 0) {
        float m = fmaxf(lg[0], fmaxf(lg[1], lg[2]));
        float e0 = expf(lg[0] - m), e1 = expf(lg[1] - m), e2 = expf(lg[2] - m);
        float inv = 1.f / (e0 + e1 + e2);
        float p0 = e0 * inv, p1 = e1 * inv, p2 = e2 * inv;
        g_pw[b * 3 + 0] = p0;
        g_pw[b * 3 + 1] = p1;
        g_pw[b * 3 + 2] = p2;
        bool A00 = p1 > THRESH;
        bool A01 = (p1 + p2) > THRESH;
        bool A10 = (p0 + p1) > THRESH;
        bool A11 = ((p0 + p1) + p2) > THRESH;
        bool need_sparse = (A00 != A01) || (A10 != A11);
        int mode;
        if (need_sparse || A00) mode = 0;
        else if (A10)           mode = 1;
        else                    mode = 2;
        g_mode[b] = mode;
    }
}

// ---------------------------------------------------------------------------
__device__ __forceinline__ void write_split(int m, int col, float v)
{
    __nv_bfloat16 hi = __float2bfloat16(v);
    __nv_bfloat16 lo = __float2bfloat16(v - __bfloat162float(hi));
    __nv_bfloat16* d = g_ahl + (size_t)m * K3 + col;
    d[0] = hi; d[DD] = lo; d[2 * DD] = hi;
}

// ---------------------------------------------------------------------------
// Local-window fused attention (mode 1) + all-masked fallback (mode 2).
// b_off allows per-batch-range launches for overlap with the QKV GEMM tail.
// ---------------------------------------------------------------------------
__global__ __launch_bounds__(256)
void local_attn_kernel(int b_off)
{
    __shared__ float ksh[48][65];
    __shared__ float vsh[48][65];
    __shared__ float qsh[16][64];
    __shared__ float psh[16][33];

    int blk = blockIdx.x;
    int b = b_off + (blk >> 9);
    int h = (blk >> 6) & 7;
    int q0 = (blk & 63) * 16;
    int mode = g_mode[b];
    if (mode == 0) return;
    int tid = threadIdx.x;
    const float* base = g_qkv + (size_t)b * LL * QKVD + h * HD;

    if (mode == 2) {
        const float* v0 = base + 2 * DD;
#pragma unroll
        for (int i = 0; i < 4; i++) {
            int idx = tid + i * 256;
            int r = idx >> 6, d = idx & 63;
            write_split(b * LL + q0 + r, h * HD + d, v0[d]);
        }
        return;
    }

    int kb0 = max(q0 - 16, 0);
    int kend = min(q0 + 15 + 16, LL - 1);
    int klen = kend - kb0 + 1;

    for (int i = tid; i < klen * 64; i += 256) {
        int jj = i >> 6, d = i & 63;
        const float* src = base + (size_t)(kb0 + jj) * QKVD;
        ksh[jj][d] = src[DD + d];
        vsh[jj][d] = src[2 * DD + d];
    }
#pragma unroll
    for (int i = 0; i < 4; i++) {
        int idx = tid + i * 256;
        int r = idx >> 6, d = idx & 63;
        qsh[r][d] = base[(size_t)(q0 + r) * QKVD + d];
    }
    __syncthreads();

    int warp = tid >> 5, lane = tid & 31;
#pragma unroll
    for (int rr = 0; rr < 2; rr++) {
        int r = warp * 2 + rr;
        int q = q0 + r;
        int w0 = max(q - 16, 0), w1 = min(q + 16, LL - 1);
        int cnt = w1 - w0 + 1;
        int off = w0 - kb0;

        float s0 = NEG_INF, s1 = NEG_INF;
        if (lane < cnt) {
            float acc = 0.f;
#pragma unroll
            for (int d = 0; d < 64; d++) acc += qsh[r][d] * ksh[off + lane][d];
            s0 = acc * SCALE;
        }
        if (lane + 32 < cnt) {
            float acc = 0.f;
#pragma unroll
            for (int d = 0; d < 64; d++) acc += qsh[r][d] * ksh[off + lane + 32][d];
            s1 = acc * SCALE;
        }
        float m = fmaxf(s0, s1);
#pragma unroll
        for (int o = 16; o > 0; o >>= 1) m = fmaxf(m, __shfl_xor_sync(~0u, m, o));
        float e0 = (lane < cnt) ? __expf(s0 - m) : 0.f;
        float e1 = (lane + 32 < cnt) ? __expf(s1 - m) : 0.f;
        float sum = e0 + e1;
#pragma unroll
        for (int o = 16; o > 0; o >>= 1) sum += __shfl_xor_sync(~0u, sum, o);
        float inv = 1.f / sum;
        if (lane < cnt) psh[r][lane] = e0 * inv;
        if (lane + 32 < cnt) psh[r][lane + 32] = e1 * inv;
        __syncwarp();

        float o0 = 0.f, o1 = 0.f;
        for (int jj = 0; jj < cnt; jj++) {
            float p = psh[r][jj];
            o0 += p * vsh[off + jj][lane];
            o1 += p * vsh[off + jj][lane + 32];
        }
        int m_out = b * LL + q;
        write_split(m_out, h * HD + lane, o0);
        write_split(m_out, h * HD + lane + 32, o1);
    }
}

// ---------------------------------------------------------------------------
// Full-path mask + softmax (mode 0 only). 16 rows per block.
// ---------------------------------------------------------------------------
__device__ __forceinline__ unsigned fkey(float f) {
    unsigned u = __float_as_uint(f);
    return (u & 0x80000000u) ? ~u : (u | 0x80000000u);
}

__global__ __launch_bounds__(256)
void softmax_kernel(const float* __restrict__ sparse_w,
                    const float* __restrict__ sparse_b)
{
    __shared__ float s[LL];
    __shared__ float red[256];
    __shared__ unsigned hist[256];
    __shared__ unsigned sel_prefix, sel_k;
    __shared__ float mx_sh;

    int grp = blockIdx.x;
    int z = grp >> 6;
    int b = z >> 3, h = z & 7;
    if (g_mode[b] != 0) return;
    int q_base = (grp & 63) * 16;
    int tid = threadIdx.x;

    float p0 = g_pw[b * 3 + 0];
    float p1 = g_pw[b * 3 + 1];
    float p2 = g_pw[b * 3 + 2];
    bool A00 = p1 > THRESH;
    bool A01 = (p1 + p2) > THRESH;
    bool A10 = (p0 + p1) > THRESH;
    bool A11 = ((p0 + p1) + p2) > THRESH;
    bool need_sparse = (A00 != A01) || (A10 != A11);
    float w_h = sparse_w[h], b_h = sparse_b[h];

    for (int r = 0; r < 16; r++) {
        int q = q_base + r;
        float* srow = g_scores + ((size_t)z << 20) + ((size_t)q << 10);
        ((float4*)s)[tid] = ((const float4*)srow)[tid];
        __syncthreads();

        unsigned tu = 0u;
        if (need_sparse) {
            if (tid == 0) { sel_prefix = 0u; sel_k = KTOP; }
            __syncthreads();
            for (int shift = 24; shift >= 0; shift -= 8) {
                hist[tid] = 0u;
                __syncthreads();
                unsigned pref = sel_prefix;
                unsigned hm = (shift == 24) ? 0u : (0xFFFFFFFFu << (shift + 8));
                for (int j = tid; j < LL; j += 256) {
                    float v = __fadd_rn(__fmul_rn(s[j], w_h), b_h);
                    unsigned u = fkey(v);
                    if ((u & hm) == pref) atomicAdd(&hist[(u >> shift) & 255u], 1u);
                }
                __syncthreads();
                if (tid == 0) {
                    unsigned k = sel_k, cum = 0;
                    for (int dgt = 255; dgt >= 0; --dgt) {
                        unsigned c = hist[dgt];
                        if (cum + c >= k) {
                            sel_prefix = pref | ((unsigned)dgt << shift);
                            sel_k = k - cum;
                            break;
                        }
                        cum += c;
                    }
                }
                __syncthreads();
            }
            tu = sel_prefix;
            __syncthreads();
        }

        float v[4];
        float lm = NEG_INF;
#pragma unroll
        for (int i = 0; i < 4; i++) {
            int j = tid * 4 + i;
            float sv = s[j];
            bool lf = (abs(q - j) <= 16);
            bool allow;
            if (need_sparse) {
                float s2 = __fadd_rn(__fmul_rn(sv, w_h), b_h);
                float sf = (fkey(s2) >= tu) ? 1.f : 0.f;
                float comb = (p0 * (lf ? 1.f : 0.f) + p1) + p2 * sf;
                allow = comb > THRESH;
            } else {
                allow = lf ? A10 : A00;
            }
            v[i] = allow ? sv : NEG_INF;
            lm = fmaxf(lm, v[i]);
        }
        red[tid] = lm; __syncthreads();
        for (int o = 128; o > 0; o >>= 1) {
            if (tid < o) red[tid] = fmaxf(red[tid], red[tid + o]);
            __syncthreads();
        }
        if (tid == 0) mx_sh = red[0];
        __syncthreads();
        float mx = mx_sh;

        if (mx == NEG_INF) {
            float4 o;
            o.x = (tid == 0) ? 1.f : 0.f; o.y = 0.f; o.z = 0.f; o.w = 0.f;
            ((float4*)srow)[tid] = o;
            __syncthreads();
            continue;
        }

        float ls = 0.f;
#pragma unroll
        for (int i = 0; i < 4; i++) {
            v[i] = __expf(v[i] - mx);
            ls += v[i];
        }
        red[tid] = ls; __syncthreads();
        for (int o = 128; o > 0; o >>= 1) {
            if (tid < o) red[tid] += red[tid + o];
            __syncthreads();
        }
        if (tid == 0) mx_sh = 1.f / red[0];
        __syncthreads();
        float inv = mx_sh;
        float4 o;
        o.x = v[0] * inv; o.y = v[1] * inv; o.z = v[2] * inv; o.w = v[3] * inv;
        ((float4*)srow)[tid] = o;
        __syncthreads();
    }
}

// ---------------------------------------------------------------------------
extern "C" void kernel_launch(void* const* d_in, const int* in_sizes, int n_in,
                              void* d_out, int out_size)
{
    const float* x        = (const float*)d_in[0];
    const float* qkv_w    = (const float*)d_in[1];
    const float* proj_w   = (const float*)d_in[2];
    const float* proj_b   = (const float*)d_in[3];
    const float* ps_w1    = (const float*)d_in[4];
    const float* ps_b1    = (const float*)d_in[5];
    const float* ps_w2    = (const float*)d_in[6];
    const float* ps_b2    = (const float*)d_in[7];
    const float* ps_w3    = (const float*)d_in[8];
    const float* ps_b3    = (const float*)d_in[9];
    const float* pbias    = (const float*)d_in[10];
    const float* sparse_w = (const float*)d_in[11];
    const float* sparse_b = (const float*)d_in[12];
    float* out = (float*)d_out;

    float *qkv_p, *sc_p, *attn_p;
    int *mode_p;
    __nv_bfloat16 *xhl_p, *wqhl_p, *ahl_p, *pwhl_p;
    cudaGetSymbolAddress((void**)&qkv_p,  g_qkv);
    cudaGetSymbolAddress((void**)&sc_p,   g_scores);
    cudaGetSymbolAddress((void**)&attn_p, g_attn);
    cudaGetSymbolAddress((void**)&mode_p, g_mode);
    cudaGetSymbolAddress((void**)&xhl_p,  g_xhl);
    cudaGetSymbolAddress((void**)&wqhl_p, g_wqhl);
    cudaGetSymbolAddress((void**)&ahl_p,  g_ahl);
    cudaGetSymbolAddress((void**)&pwhl_p, g_pwhl);

    // One-time setup (first call is the uncaptured correctness run)
    static cudaStream_t s1 = nullptr, s2 = nullptr;
    static cudaEvent_t eFork = nullptr, eMode = nullptr, eWq = nullptr,
                       eWp = nullptr, eG1 = nullptr, eQkv = nullptr,
                       eFull = nullptr, eL123 = nullptr;
    if (!s1) {
        cudaStreamCreateWithFlags(&s1, cudaStreamNonBlocking);
        cudaStreamCreateWithFlags(&s2, cudaStreamNonBlocking);
        cudaEventCreateWithFlags(&eFork, cudaEventDisableTiming);
        cudaEventCreateWithFlags(&eMode, cudaEventDisableTiming);
        cudaEventCreateWithFlags(&eWq,   cudaEventDisableTiming);
        cudaEventCreateWithFlags(&eWp,   cudaEventDisableTiming);
        cudaEventCreateWithFlags(&eG1,   cudaEventDisableTiming);
        cudaEventCreateWithFlags(&eQkv,  cudaEventDisableTiming);
        cudaEventCreateWithFlags(&eFull, cudaEventDisableTiming);
        cudaEventCreateWithFlags(&eL123, cudaEventDisableTiming);
        cudaFuncSetAttribute(gemm_mma, cudaFuncAttributeMaxDynamicSharedMemorySize, GM_DSM);
    }

    // Fork side streams off the main (capture-origin) stream
    cudaEventRecord(eFork, 0);
    cudaStreamWaitEvent(s1, eFork, 0);
    cudaStreamWaitEvent(s2, eFork, 0);

    // s1: pattern-selector chain -> g_mode
    pool1_kernel<<<32, 256, 0, s1>>>(x);
    pattern_kernel<<<BB, 256, 0, s1>>>(ps_w1, ps_b1, ps_w2, ps_b2, ps_w3, ps_b3, pbias);
    cudaEventRecord(eMode, s1);

    // s2: weight conversions
    cvt_split<0><<<(QKVD * DD / 4 + 255) / 256, 256, 0, s2>>>(qkv_w, wqhl_p, QKVD, nullptr);
    cudaEventRecord(eWq, s2);
    cvt_split<0><<<(DD * DD / 4 + 255) / 256, 256, 0, s2>>>(proj_w, pwhl_p, DD, nullptr);
    cudaEventRecord(eWp, s2);

    // main: x conversion, then QKV GEMM split: G1 = batches 0-2 (288 CTAs ~ 1 wave),
    // G2 = batch 3 (96 CTAs). Local attention for batches 0-2 overlaps G2.
    cvt_split<1><<<(ML * DD / 4 + 255) / 256, 256>>>(x, xhl_p, ML, nullptr);
    cudaStreamWaitEvent(0, eWq, 0);
    gemm_mma<<<dim3(QKVD / 128, 24), 256, GM_DSM>>>(
        xhl_p, wqhl_p, qkv_p, QKVD, QKVD, nullptr, 0);
    cudaEventRecord(eG1, 0);
    gemm_mma<<<dim3(QKVD / 128, 8), 256, GM_DSM>>>(
        xhl_p, wqhl_p, qkv_p, QKVD, QKVD, nullptr, 3072);
    cudaEventRecord(eQkv, 0);

    // s2: local attention for batches 0-2 (needs G1 + mode), overlaps G2
    cudaStreamWaitEvent(s2, eG1, 0);
    cudaStreamWaitEvent(s2, eMode, 0);
    local_attn_kernel<<<3 * HH * (LL / 16), 256, 0, s2>>>(0);
    cudaEventRecord(eL123, s2);

    // s1: gated full path (needs full QKV; stubs when no batch is mode 0)
    cudaStreamWaitEvent(s1, eQkv, 0);
    gemm128<<<dim3(LL / 128, LL / 128, BB * HH), 256, 0, s1>>>(
        qkv_p, QKVD, (long)LL * QKVD, HD,
        qkv_p + DD, QKVD, (long)LL * QKVD, HD,
        sc_p, LL, (long)HH * LL * LL, (long)LL * LL,
        HD, SCALE, nullptr, HH, mode_p);
    softmax_kernel<<<BB * HH * (LL / 16), 256, 0, s1>>>(sparse_w, sparse_b);
    gemm_bt<<<dim3(HD / 64, LL / 64, BB * HH), 256, 0, s1>>>(
        sc_p, LL, (long)HH * LL * LL, (long)LL * LL,
        qkv_p + 2 * DD, QKVD, (long)LL * QKVD, HD,
        attn_p, DD, (long)LL * DD, HD,
        LL, HD, LL, 1.f, nullptr, HH, 0, mode_p);
    cvt_split<1><<<(ML * DD / 4 + 255) / 256, 256, 0, s1>>>(attn_p, ahl_p, ML, mode_p);
    cudaEventRecord(eFull, s1);

    // main: local attention for batch 3 (needs G2 [program order] + mode)
    cudaStreamWaitEvent(0, eMode, 0);
    local_attn_kernel<<<1 * HH * (LL / 16), 256>>>(3);

    // join: proj GEMM needs all of g_ahl (L123, L4, gated full) and proj weights
    cudaStreamWaitEvent(0, eL123, 0);
    cudaStreamWaitEvent(0, eFull, 0);
    cudaStreamWaitEvent(0, eWp, 0);
    gemm_mma<<<dim3(DD / 128, ML / 128), 256, GM_DSM>>>(
        ahl_p, pwhl_p, out, DD, DD, proj_b, 0);
}

// round 12
// speedup vs baseline: 10.8345x; 1.1474x over previous
#include <cuda_runtime.h>
#include <cuda_bf16.h>
#include <cuda_fp16.h>
#include <cstdint>
#include <math.h>

#define BB 4
#define LL 1024
#define DD 512
#define HH 8
#define HD 64
#define QKVD 1536
#define ML (BB*LL)
#define K2 1024              // 2 * 512 split-K for fp16 two-term GEMM
#define KTOP 716
#define THRESH 0.05f
#define SCALE 0.125f
#define NEG_INF __int_as_float(0xff800000)

#define NCHUNK (K2 / 64)             // 16 chunks of K=64
#define STAGE_BYTES 32768            // A(16KB) + B(16KB) per stage
#define GM_DSM (3 * STAGE_BYTES + 128)

// Scratch (device globals; no allocations allowed)
__device__ float g_qkv[ML * QKVD];
__device__ float g_scores[(size_t)BB * HH * LL * LL];
__device__ float g_attn[ML * DD];
__device__ float g_pw[BB * 3];
__device__ int   g_mode[BB];
__device__ float g_pool_part[32][DD];
// fp16 two-term split buffers
__device__ __half g_xhl[ML * K2];
__device__ __half g_wqhl[QKVD * K2];
__device__ __half g_ahl[ML * K2];
__device__ __half g_pwhl[DD * K2];

__device__ __forceinline__ uint32_t smem_u32(const void* p) {
    return (uint32_t)__cvta_generic_to_shared(p);
}
__device__ __forceinline__ void cp16(uint32_t dst, const void* src) {
    asm volatile("cp.async.cg.shared.global [%0], [%1], 16;\n" :: "r"(dst), "l"(src));
}
// row r (0..127), 16B unit u (0..7) inside a 128-row x 128B swizzled buffer
__device__ __forceinline__ uint32_t swz(uint32_t bufbase, int r, int u) {
    return bufbase + r * 128 + ((u ^ (r & 7)) << 4);
}

// ---------------------------------------------------------------------------
// fp32 -> fp16 two-term split. Astyle: [hi | lo]. Bstyle: [hi | hi].
// gate != nullptr: only process rows whose batch (m/LL) has mode 0.
// ---------------------------------------------------------------------------
template<int ASTYLE>
__global__ __launch_bounds__(256)
void cvt_split(const float* __restrict__ src, __half* __restrict__ dst,
               int M, const int* __restrict__ gate)
{
    int i = blockIdx.x * 256 + threadIdx.x;
    int total = M * (DD / 4);
    if (i >= total) return;
    int m = i / (DD / 4), c = i % (DD / 4);
    if (gate && gate[m / LL] != 0) return;
    float4 v = ((const float4*)(src + (size_t)m * DD))[c];
    __half hi[4], lo[4];
    float vv[4] = {v.x, v.y, v.z, v.w};
#pragma unroll
    for (int t = 0; t < 4; t++) {
        hi[t] = __float2half_rn(vv[t]);
        lo[t] = __float2half_rn(vv[t] - __half2float(hi[t]));
    }
    __half* d = dst + (size_t)m * K2 + c * 4;
    __half2* d0 = (__half2*)(d);
    __half2* d1 = (__half2*)(d + DD);
    __half2 hp0 = {hi[0], hi[1]}, hp1 = {hi[2], hi[3]};
    __half2 lp0 = {lo[0], lo[1]}, lp1 = {lo[2], lo[3]};
    d0[0] = hp0; d0[1] = hp1;
    if (ASTYLE) {
        d1[0] = lp0; d1[1] = lp1;      // A: [hi, lo]
    } else {
        d1[0] = hp0; d1[1] = hp1;      // B: [hi, hi]
    }
}

// ---------------------------------------------------------------------------
// fp16 NT GEMM via mma.sync m16n8k16, 3-stage cp.async pipeline,
// XOR-swizzled smem, one barrier per K-chunk. m_base allows row-split launches.
// ---------------------------------------------------------------------------
__global__ __launch_bounds__(256, 2)
void gemm_mma(const __half* __restrict__ A2,
              const __half* __restrict__ B2,
              float* __restrict__ C, int ldc, int N,
              const float* __restrict__ bias, int m_base)
{
    extern __shared__ char dsm[];
    uint32_t base = (smem_u32(dsm) + 127) & ~127u;
    int tid = threadIdx.x;
    int warp = tid >> 5, lane = tid & 31;
    int wm = warp >> 1, wn = warp & 1;
    int m0 = m_base + blockIdx.y * 128, n0 = blockIdx.x * 128;
    int m0w = wm * 32, n0w = wn * 64;

    float acc[2][8][4];
#pragma unroll
    for (int a = 0; a < 2; a++)
#pragma unroll
        for (int b = 0; b < 8; b++)
#pragma unroll
            for (int c = 0; c < 4; c++) acc[a][b][c] = 0.f;

    int u = tid & 7, row0 = tid >> 3;

    auto issue = [&](int chunk) {
        int s = chunk % 3;
        uint32_t bA = base + s * STAGE_BYTES;
        uint32_t bB = bA + 16384;
        int k0 = chunk * 64;
#pragma unroll
        for (int p = 0; p < 4; p++) {
            int r = row0 + p * 32;
            cp16(swz(bA, r, u), A2 + (size_t)(m0 + r) * K2 + k0 + u * 8);
            cp16(swz(bB, r, u), B2 + (size_t)(n0 + r) * K2 + k0 + u * 8);
        }
        asm volatile("cp.async.commit_group;\n");
    };

    issue(0);
    issue(1);

    for (int c = 0; c < NCHUNK; c++) {
        if (c + 2 < NCHUNK) {
            asm volatile("cp.async.wait_group 1;\n");
        } else {
            asm volatile("cp.async.wait_group 0;\n");
        }
        __syncthreads();
        if (c + 2 < NCHUNK) issue(c + 2);

        int s = c % 3;
        uint32_t bA = base + s * STAGE_BYTES;
        uint32_t bB = bA + 16384;
#pragma unroll
        for (int kk = 0; kk < 64; kk += 16) {
            int ub = kk >> 3;
            uint32_t a[2][4];
#pragma unroll
            for (int mt = 0; mt < 2; mt++) {
                int mrow = m0w + mt * 16 + (lane & 15);
                int un = ub + (lane >> 4);
                uint32_t ad = swz(bA, mrow, un);
                asm volatile("ldmatrix.sync.aligned.m8n8.x4.shared.b16 {%0,%1,%2,%3}, [%4];"
                    : "=r"(a[mt][0]), "=r"(a[mt][1]), "=r"(a[mt][2]), "=r"(a[mt][3])
                    : "r"(ad));
            }
            uint32_t bfr[4][4];
#pragma unroll
            for (int g = 0; g < 4; g++) {
                int nrow = n0w + g * 16 + ((lane >> 4) << 3) + (lane & 7);
                int un = ub + ((lane >> 3) & 1);
                uint32_t ad = swz(bB, nrow, un);
                asm volatile("ldmatrix.sync.aligned.m8n8.x4.shared.b16 {%0,%1,%2,%3}, [%4];"
                    : "=r"(bfr[g][0]), "=r"(bfr[g][1]), "=r"(bfr[g][2]), "=r"(bfr[g][3])
                    : "r"(ad));
            }
#pragma unroll
            for (int mt = 0; mt < 2; mt++)
#pragma unroll
                for (int nt = 0; nt < 8; nt++) {
                    int g = nt >> 1, pr = (nt & 1) * 2;
                    asm volatile(
                        "mma.sync.aligned.m16n8k16.row.col.f32.f16.f16.f32 "
                        "{%0,%1,%2,%3}, {%4,%5,%6,%7}, {%8,%9}, {%0,%1,%2,%3};"
                        : "+f"(acc[mt][nt][0]), "+f"(acc[mt][nt][1]),
                          "+f"(acc[mt][nt][2]), "+f"(acc[mt][nt][3])
                        : "r"(a[mt][0]), "r"(a[mt][1]), "r"(a[mt][2]), "r"(a[mt][3]),
                          "r"(bfr[g][pr]), "r"(bfr[g][pr + 1]));
                }
        }
    }

    // epilogue
#pragma unroll
    for (int mt = 0; mt < 2; mt++) {
        int mA = m0 + m0w + mt * 16 + (lane >> 2);
#pragma unroll
        for (int nt = 0; nt < 8; nt++) {
            int n = n0 + n0w + nt * 8 + (lane & 3) * 2;
            if (n >= N) continue;
            float b0 = bias ? bias[n] : 0.f;
            float b1 = bias ? bias[n + 1] : 0.f;
            *(float2*)&C[(size_t)mA * ldc + n] =
                make_float2(acc[mt][nt][0] + b0, acc[mt][nt][1] + b1);
            *(float2*)&C[(size_t)(mA + 8) * ldc + n] =
                make_float2(acc[mt][nt][2] + b0, acc[mt][nt][3] + b1);
        }
    }
}

// ---------------------------------------------------------------------------
// 128x128 fp32 SGEMM (NT) for the gated full-path scores.
// ---------------------------------------------------------------------------
__global__ __launch_bounds__(256)
void gemm128(const float* __restrict__ A, int lda, long sAb, long sAh,
             const float* __restrict__ B, int ldb, long sBb, long sBh,
             float* __restrict__ C, int ldc, long sCb, long sCh,
             int K, float alpha, const float* __restrict__ bias,
             int nh, const int* __restrict__ gate)
{
    __shared__ float As[16][132];
    __shared__ float Bs[16][132];
    int z = blockIdx.z;
    int b = z / nh, h = z % nh;
    if (gate && gate[b] != 0) return;
    A += (size_t)b * sAb + (size_t)h * sAh;
    B += (size_t)b * sBb + (size_t)h * sBh;
    C += (size_t)b * sCb + (size_t)h * sCh;

    int tid = threadIdx.x;
    int tx = tid & 15, ty = tid >> 4;
    int m0 = blockIdx.y * 128, n0 = blockIdx.x * 128;

    float acc[8][8];
#pragma unroll
    for (int i = 0; i < 8; i++)
#pragma unroll
        for (int j = 0; j < 8; j++) acc[i][j] = 0.f;

    for (int k0 = 0; k0 < K; k0 += 16) {
#pragma unroll
        for (int i = 0; i < 8; i++) {
            int idx = tid + i * 256;
            int m = idx >> 4, kk = idx & 15;
            As[kk][m] = A[(size_t)(m0 + m) * lda + k0 + kk];
            Bs[kk][m] = B[(size_t)(n0 + m) * ldb + k0 + kk];
        }
        __syncthreads();
#pragma unroll
        for (int kk = 0; kk < 16; kk++) {
            float4 a0 = *(const float4*)&As[kk][ty * 8];
            float4 a1 = *(const float4*)&As[kk][ty * 8 + 4];
            float4 b0 = *(const float4*)&Bs[kk][tx * 8];
            float4 b1 = *(const float4*)&Bs[kk][tx * 8 + 4];
            float av[8] = {a0.x, a0.y, a0.z, a0.w, a1.x, a1.y, a1.z, a1.w};
            float bv[8] = {b0.x, b0.y, b0.z, b0.w, b1.x, b1.y, b1.z, b1.w};
#pragma unroll
            for (int i = 0; i < 8; i++)
#pragma unroll
                for (int j = 0; j < 8; j++) acc[i][j] += av[i] * bv[j];
        }
        __syncthreads();
    }
#pragma unroll
    for (int i = 0; i < 8; i++) {
        int m = m0 + ty * 8 + i;
        float out[8];
#pragma unroll
        for (int j = 0; j < 8; j++) {
            out[j] = acc[i][j] * alpha;
            if (bias) out[j] += bias[n0 + tx * 8 + j];
        }
        float4* cp = (float4*)&C[(size_t)m * ldc + n0 + tx * 8];
        cp[0] = make_float4(out[0], out[1], out[2], out[3]);
        cp[1] = make_float4(out[4], out[5], out[6], out[7]);
    }
}

// ---------------------------------------------------------------------------
// 64x64 SGEMM (NT/NN) for the gated AV path.
// ---------------------------------------------------------------------------
__global__ __launch_bounds__(256)
void gemm_bt(const float* __restrict__ A, int lda, long sAb, long sAh,
             const float* __restrict__ B, int ldb, long sBb, long sBh,
             float* __restrict__ C, int ldc, long sCb, long sCh,
             int M, int N, int K, float alpha,
             const float* __restrict__ bias, int nh, int bTrans,
             const int* __restrict__ gate)
{
    __shared__ float As[16][65];
    __shared__ float Bs[16][65];
    int z = blockIdx.z;
    int b = z / nh, h = z % nh;
    if (gate && gate[b] != 0) return;
    A += (size_t)b * sAb + (size_t)h * sAh;
    B += (size_t)b * sBb + (size_t)h * sBh;
    C += (size_t)b * sCb + (size_t)h * sCh;

    int tid = threadIdx.x;
    int tx = tid & 15, ty = tid >> 4;
    int m0 = blockIdx.y * 64, n0 = blockIdx.x * 64;

    float acc[4][4];
#pragma unroll
    for (int i = 0; i < 4; i++)
#pragma unroll
        for (int j = 0; j < 4; j++) acc[i][j] = 0.f;

    for (int k0 = 0; k0 < K; k0 += 16) {
#pragma unroll
        for (int i = 0; i < 4; i++) {
            int idx = tid + i * 256;
            int m = idx >> 4, kk = idx & 15;
            As[kk][m] = A[(size_t)(m0 + m) * lda + k0 + kk];
        }
        if (bTrans) {
#pragma unroll
            for (int i = 0; i < 4; i++) {
                int idx = tid + i * 256;
                int n = idx >> 4, kk = idx & 15;
                Bs[kk][n] = B[(size_t)(n0 + n) * ldb + k0 + kk];
            }
        } else {
#pragma unroll
            for (int i = 0; i < 4; i++) {
                int idx = tid + i * 256;
                int n = idx & 63, kk = idx >> 6;
                Bs[kk][n] = B[(size_t)(k0 + kk) * ldb + n0 + n];
            }
        }
        __syncthreads();
#pragma unroll
        for (int kk = 0; kk < 16; kk++) {
            float a[4], bb[4];
#pragma unroll
            for (int i = 0; i < 4; i++) a[i] = As[kk][ty * 4 + i];
#pragma unroll
            for (int j = 0; j < 4; j++) bb[j] = Bs[kk][tx * 4 + j];
#pragma unroll
            for (int i = 0; i < 4; i++)
#pragma unroll
                for (int j = 0; j < 4; j++) acc[i][j] += a[i] * bb[j];
        }
        __syncthreads();
    }
#pragma unroll
    for (int i = 0; i < 4; i++) {
        int m = m0 + ty * 4 + i;
#pragma unroll
        for (int j = 0; j < 4; j++) {
            int n = n0 + tx * 4 + j;
            float v = acc[i][j] * alpha;
            if (bias) v += bias[n];
            C[(size_t)m * ldc + n] = v;
        }
    }
}

// ---------------------------------------------------------------------------
__global__ __launch_bounds__(256)
void pool1_kernel(const float* __restrict__ x)
{
    int blk = blockIdx.x;
    int b = blk >> 3, c = blk & 7;
    int tid = threadIdx.x;
    const float2* xp = (const float2*)(x + ((size_t)b * LL + c * 128) * DD) + tid;
    float s0 = 0.f, s1 = 0.f;
    for (int l = 0; l < 128; l++) {
        float2 v = xp[(size_t)l * (DD / 2)];
        s0 += v.x; s1 += v.y;
    }
    g_pool_part[blk][tid * 2]     = s0;
    g_pool_part[blk][tid * 2 + 1] = s1;
}

// ---------------------------------------------------------------------------
__global__ __launch_bounds__(256)
void pattern_kernel(const float* __restrict__ w1, const float* __restrict__ b1,
                    const float* __restrict__ w2, const float* __restrict__ b2,
                    const float* __restrict__ w3, const float* __restrict__ b3,
                    const float* __restrict__ pbias)
{
    int b = blockIdx.x, tid = threadIdx.x;
    int warp = tid >> 5, lane = tid & 31;
    __shared__ float pooled[DD];
    __shared__ float h1[DD];
    __shared__ float h2[DD / 2];
    __shared__ float lg[3];

    for (int d = tid; d < DD; d += 256) {
        float s = 0.f;
#pragma unroll
        for (int c = 0; c < 8; c++) s += g_pool_part[b * 8 + c][d];
        pooled[d] = s * (1.0f / LL);
    }
    __syncthreads();
    for (int i = warp; i < DD; i += 8) {
        const float* wr = w1 + (size_t)i * DD;
        float a = 0.f;
        for (int k = lane; k < DD; k += 32) a += pooled[k] * wr[k];
#pragma unroll
        for (int o = 16; o > 0; o >>= 1) a += __shfl_xor_sync(~0u, a, o);
        if (lane == 0) h1[i] = fmaxf(a + b1[i], 0.f);
    }
    __syncthreads();
    for (int i = warp; i < DD / 2; i += 8) {
        const float* wr = w2 + (size_t)i * DD;
        float a = 0.f;
        for (int k = lane; k < DD; k += 32) a += h1[k] * wr[k];
#pragma unroll
        for (int o = 16; o > 0; o >>= 1) a += __shfl_xor_sync(~0u, a, o);
        if (lane == 0) h2[i] = fmaxf(a + b2[i], 0.f);
    }
    __syncthreads();
    if (warp < 3) {
        const float* wr = w3 + (size_t)warp * (DD / 2);
        float a = 0.f;
        for (int k = lane; k < DD / 2; k += 32) a += h2[k] * wr[k];
#pragma unroll
        for (int o = 16; o > 0; o >>= 1) a += __shfl_xor_sync(~0u, a, o);
        if (lane == 0) lg[warp] = (a + b3[warp] + pbias[warp]) / 0.3f;
    }
    __syncthreads();
    if (tid == 0) {
        float m = fmaxf(lg[0], fmaxf(lg[1], lg[2]));
        float e0 = expf(lg[0] - m), e1 = expf(lg[1] - m), e2 = expf(lg[2] - m);
        float inv = 1.f / (e0 + e1 + e2);
        float p0 = e0 * inv, p1 = e1 * inv, p2 = e2 * inv;
        g_pw[b * 3 + 0] = p0;
        g_pw[b * 3 + 1] = p1;
        g_pw[b * 3 + 2] = p2;
        bool A00 = p1 > THRESH;
        bool A01 = (p1 + p2) > THRESH;
        bool A10 = (p0 + p1) > THRESH;
        bool A11 = ((p0 + p1) + p2) > THRESH;
        bool need_sparse = (A00 != A01) || (A10 != A11);
        int mode;
        if (need_sparse || A00) mode = 0;
        else if (A10)           mode = 1;
        else                    mode = 2;
        g_mode[b] = mode;
    }
}

// ---------------------------------------------------------------------------
__device__ __forceinline__ void write_split(int m, int col, float v)
{
    __half hi = __float2half_rn(v);
    __half lo = __float2half_rn(v - __half2float(hi));
    __half* d = g_ahl + (size_t)m * K2 + col;
    d[0] = hi; d[DD] = lo;
}

// ---------------------------------------------------------------------------
// Local-window fused attention (mode 1) + all-masked fallback (mode 2).
// b_off allows per-batch-range launches for overlap with the QKV GEMM tail.
// ---------------------------------------------------------------------------
__global__ __launch_bounds__(256)
void local_attn_kernel(int b_off)
{
    __shared__ float ksh[48][65];
    __shared__ float vsh[48][65];
    __shared__ float qsh[16][64];
    __shared__ float psh[16][33];

    int blk = blockIdx.x;
    int b = b_off + (blk >> 9);
    int h = (blk >> 6) & 7;
    int q0 = (blk & 63) * 16;
    int mode = g_mode[b];
    if (mode == 0) return;
    int tid = threadIdx.x;
    const float* base = g_qkv + (size_t)b * LL * QKVD + h * HD;

    if (mode == 2) {
        const float* v0 = base + 2 * DD;
#pragma unroll
        for (int i = 0; i < 4; i++) {
            int idx = tid + i * 256;
            int r = idx >> 6, d = idx & 63;
            write_split(b * LL + q0 + r, h * HD + d, v0[d]);
        }
        return;
    }

    int kb0 = max(q0 - 16, 0);
    int kend = min(q0 + 15 + 16, LL - 1);
    int klen = kend - kb0 + 1;

    for (int i = tid; i < klen * 64; i += 256) {
        int jj = i >> 6, d = i & 63;
        const float* src = base + (size_t)(kb0 + jj) * QKVD;
        ksh[jj][d] = src[DD + d];
        vsh[jj][d] = src[2 * DD + d];
    }
#pragma unroll
    for (int i = 0; i < 4; i++) {
        int idx = tid + i * 256;
        int r = idx >> 6, d = idx & 63;
        qsh[r][d] = base[(size_t)(q0 + r) * QKVD + d];
    }
    __syncthreads();

    int warp = tid >> 5, lane = tid & 31;
#pragma unroll
    for (int rr = 0; rr < 2; rr++) {
        int r = warp * 2 + rr;
        int q = q0 + r;
        int w0 = max(q - 16, 0), w1 = min(q + 16, LL - 1);
        int cnt = w1 - w0 + 1;
        int off = w0 - kb0;

        float s0 = NEG_INF, s1 = NEG_INF;
        if (lane < cnt) {
            float acc = 0.f;
#pragma unroll
            for (int d = 0; d < 64; d++) acc += qsh[r][d] * ksh[off + lane][d];
            s0 = acc * SCALE;
        }
        if (lane + 32 < cnt) {
            float acc = 0.f;
#pragma unroll
            for (int d = 0; d < 64; d++) acc += qsh[r][d] * ksh[off + lane + 32][d];
            s1 = acc * SCALE;
        }
        float m = fmaxf(s0, s1);
#pragma unroll
        for (int o = 16; o > 0; o >>= 1) m = fmaxf(m, __shfl_xor_sync(~0u, m, o));
        float e0 = (lane < cnt) ? __expf(s0 - m) : 0.f;
        float e1 = (lane + 32 < cnt) ? __expf(s1 - m) : 0.f;
        float sum = e0 + e1;
#pragma unroll
        for (int o = 16; o > 0; o >>= 1) sum += __shfl_xor_sync(~0u, sum, o);
        float inv = 1.f / sum;
        if (lane < cnt) psh[r][lane] = e0 * inv;
        if (lane + 32 < cnt) psh[r][lane + 32] = e1 * inv;
        __syncwarp();

        float o0 = 0.f, o1 = 0.f;
        for (int jj = 0; jj < cnt; jj++) {
            float p = psh[r][jj];
            o0 += p * vsh[off + jj][lane];
            o1 += p * vsh[off + jj][lane + 32];
        }
        int m_out = b * LL + q;
        write_split(m_out, h * HD + lane, o0);
        write_split(m_out, h * HD + lane + 32, o1);
    }
}

// ---------------------------------------------------------------------------
// Full-path mask + softmax (mode 0 only). 64 rows per block.
// ---------------------------------------------------------------------------
__device__ __forceinline__ unsigned fkey(float f) {
    unsigned u = __float_as_uint(f);
    return (u & 0x80000000u) ? ~u : (u | 0x80000000u);
}

__global__ __launch_bounds__(256)
void softmax_kernel(const float* __restrict__ sparse_w,
                    const float* __restrict__ sparse_b)
{
    __shared__ float s[LL];
    __shared__ float red[256];
    __shared__ unsigned hist[256];
    __shared__ unsigned sel_prefix, sel_k;
    __shared__ float mx_sh;

    int grp = blockIdx.x;               // 0..511, 64 rows each
    int z = grp >> 4;
    int b = z >> 3, h = z & 7;
    if (g_mode[b] != 0) return;
    int q_base = (grp & 15) * 64;
    int tid = threadIdx.x;

    float p0 = g_pw[b * 3 + 0];
    float p1 = g_pw[b * 3 + 1];
    float p2 = g_pw[b * 3 + 2];
    bool A00 = p1 > THRESH;
    bool A01 = (p1 + p2) > THRESH;
    bool A10 = (p0 + p1) > THRESH;
    bool A11 = ((p0 + p1) + p2) > THRESH;
    bool need_sparse = (A00 != A01) || (A10 != A11);
    float w_h = sparse_w[h], b_h = sparse_b[h];

    for (int r = 0; r < 64; r++) {
        int q = q_base + r;
        float* srow = g_scores + ((size_t)z << 20) + ((size_t)q << 10);
        ((float4*)s)[tid] = ((const float4*)srow)[tid];
        __syncthreads();

        unsigned tu = 0u;
        if (need_sparse) {
            if (tid == 0) { sel_prefix = 0u; sel_k = KTOP; }
            __syncthreads();
            for (int shift = 24; shift >= 0; shift -= 8) {
                hist[tid] = 0u;
                __syncthreads();
                unsigned pref = sel_prefix;
                unsigned hm = (shift == 24) ? 0u : (0xFFFFFFFFu << (shift + 8));
                for (int j = tid; j < LL; j += 256) {
                    float v = __fadd_rn(__fmul_rn(s[j], w_h), b_h);
                    unsigned u = fkey(v);
                    if ((u & hm) == pref) atomicAdd(&hist[(u >> shift) & 255u], 1u);
                }
                __syncthreads();
                if (tid == 0) {
                    unsigned k = sel_k, cum = 0;
                    for (int dgt = 255; dgt >= 0; --dgt) {
                        unsigned c = hist[dgt];
                        if (cum + c >= k) {
                            sel_prefix = pref | ((unsigned)dgt << shift);
                            sel_k = k - cum;
                            break;
                        }
                        cum += c;
                    }
                }
                __syncthreads();
            }
            tu = sel_prefix;
            __syncthreads();
        }

        float v[4];
        float lm = NEG_INF;
#pragma unroll
        for (int i = 0; i < 4; i++) {
            int j = tid * 4 + i;
            float sv = s[j];
            bool lf = (abs(q - j) <= 16);
            bool allow;
            if (need_sparse) {
                float s2 = __fadd_rn(__fmul_rn(sv, w_h), b_h);
                float sf = (fkey(s2) >= tu) ? 1.f : 0.f;
                float comb = (p0 * (lf ? 1.f : 0.f) + p1) + p2 * sf;
                allow = comb > THRESH;
            } else {
                allow = lf ? A10 : A00;
            }
            v[i] = allow ? sv : NEG_INF;
            lm = fmaxf(lm, v[i]);
        }
        red[tid] = lm; __syncthreads();
        for (int o = 128; o > 0; o >>= 1) {
            if (tid < o) red[tid] = fmaxf(red[tid], red[tid + o]);
            __syncthreads();
        }
        if (tid == 0) mx_sh = red[0];
        __syncthreads();
        float mx = mx_sh;

        if (mx == NEG_INF) {
            float4 o;
            o.x = (tid == 0) ? 1.f : 0.f; o.y = 0.f; o.z = 0.f; o.w = 0.f;
            ((float4*)srow)[tid] = o;
            __syncthreads();
            continue;
        }

        float ls = 0.f;
#pragma unroll
        for (int i = 0; i < 4; i++) {
            v[i] = __expf(v[i] - mx);
            ls += v[i];
        }
        red[tid] = ls; __syncthreads();
        for (int o = 128; o > 0; o >>= 1) {
            if (tid < o) red[tid] += red[tid + o];
            __syncthreads();
        }
        if (tid == 0) mx_sh = 1.f / red[0];
        __syncthreads();
        float inv = mx_sh;
        float4 o;
        o.x = v[0] * inv; o.y = v[1] * inv; o.z = v[2] * inv; o.w = v[3] * inv;
        ((float4*)srow)[tid] = o;
        __syncthreads();
    }
}

// ---------------------------------------------------------------------------
extern "C" void kernel_launch(void* const* d_in, const int* in_sizes, int n_in,
                              void* d_out, int out_size)
{
    const float* x        = (const float*)d_in[0];
    const float* qkv_w    = (const float*)d_in[1];
    const float* proj_w   = (const float*)d_in[2];
    const float* proj_b   = (const float*)d_in[3];
    const float* ps_w1    = (const float*)d_in[4];
    const float* ps_b1    = (const float*)d_in[5];
    const float* ps_w2    = (const float*)d_in[6];
    const float* ps_b2    = (const float*)d_in[7];
    const float* ps_w3    = (const float*)d_in[8];
    const float* ps_b3    = (const float*)d_in[9];
    const float* pbias    = (const float*)d_in[10];
    const float* sparse_w = (const float*)d_in[11];
    const float* sparse_b = (const float*)d_in[12];
    float* out = (float*)d_out;

    float *qkv_p, *sc_p, *attn_p;
    int *mode_p;
    __half *xhl_p, *wqhl_p, *ahl_p, *pwhl_p;
    cudaGetSymbolAddress((void**)&qkv_p,  g_qkv);
    cudaGetSymbolAddress((void**)&sc_p,   g_scores);
    cudaGetSymbolAddress((void**)&attn_p, g_attn);
    cudaGetSymbolAddress((void**)&mode_p, g_mode);
    cudaGetSymbolAddress((void**)&xhl_p,  g_xhl);
    cudaGetSymbolAddress((void**)&wqhl_p, g_wqhl);
    cudaGetSymbolAddress((void**)&ahl_p,  g_ahl);
    cudaGetSymbolAddress((void**)&pwhl_p, g_pwhl);

    // One-time setup (first call is the uncaptured correctness run)
    static cudaStream_t s1 = nullptr, s2 = nullptr;
    static cudaEvent_t eFork = nullptr, eMode = nullptr, eWq = nullptr,
                       eWp = nullptr, eG1 = nullptr, eQkv = nullptr,
                       eFull = nullptr, eL123 = nullptr, eX2 = nullptr;
    if (!s1) {
        cudaStreamCreateWithFlags(&s1, cudaStreamNonBlocking);
        cudaStreamCreateWithFlags(&s2, cudaStreamNonBlocking);
        cudaEventCreateWithFlags(&eFork, cudaEventDisableTiming);
        cudaEventCreateWithFlags(&eMode, cudaEventDisableTiming);
        cudaEventCreateWithFlags(&eWq,   cudaEventDisableTiming);
        cudaEventCreateWithFlags(&eWp,   cudaEventDisableTiming);
        cudaEventCreateWithFlags(&eG1,   cudaEventDisableTiming);
        cudaEventCreateWithFlags(&eQkv,  cudaEventDisableTiming);
        cudaEventCreateWithFlags(&eFull, cudaEventDisableTiming);
        cudaEventCreateWithFlags(&eL123, cudaEventDisableTiming);
        cudaEventCreateWithFlags(&eX2,   cudaEventDisableTiming);
        cudaFuncSetAttribute(gemm_mma, cudaFuncAttributeMaxDynamicSharedMemorySize, GM_DSM);
    }

    // Fork side streams off the main (capture-origin) stream
    cudaEventRecord(eFork, 0);
    cudaStreamWaitEvent(s1, eFork, 0);
    cudaStreamWaitEvent(s2, eFork, 0);

    // s1: pattern-selector chain -> g_mode, then x conversion for batch 3
    pool1_kernel<<<32, 256, 0, s1>>>(x);
    pattern_kernel<<<BB, 256, 0, s1>>>(ps_w1, ps_b1, ps_w2, ps_b2, ps_w3, ps_b3, pbias);
    cudaEventRecord(eMode, s1);
    cvt_split<1><<<(1024 * DD / 4 + 255) / 256, 256, 0, s1>>>(
        x + (size_t)3072 * DD, xhl_p + (size_t)3072 * K2, 1024, nullptr);
    cudaEventRecord(eX2, s1);

    // s2: weight conversions
    cvt_split<0><<<(QKVD * DD / 4 + 255) / 256, 256, 0, s2>>>(qkv_w, wqhl_p, QKVD, nullptr);
    cudaEventRecord(eWq, s2);
    cvt_split<0><<<(DD * DD / 4 + 255) / 256, 256, 0, s2>>>(proj_w, pwhl_p, DD, nullptr);
    cudaEventRecord(eWp, s2);

    // main: x conversion for batches 0-2, then QKV GEMM split:
    // G1 = batches 0-2 (288 CTAs ~ one wave), G2 = batch 3 (96 CTAs).
    cvt_split<1><<<(3072 * DD / 4 + 255) / 256, 256>>>(x, xhl_p, 3072, nullptr);
    cudaStreamWaitEvent(0, eWq, 0);
    gemm_mma<<<dim3(QKVD / 128, 24), 256, GM_DSM>>>(
        xhl_p, wqhl_p, qkv_p, QKVD, QKVD, nullptr, 0);
    cudaEventRecord(eG1, 0);
    cudaStreamWaitEvent(0, eX2, 0);
    gemm_mma<<<dim3(QKVD / 128, 8), 256, GM_DSM>>>(
        xhl_p, wqhl_p, qkv_p, QKVD, QKVD, nullptr, 3072);
    cudaEventRecord(eQkv, 0);

    // s2: local attention for batches 0-2 (needs G1 + mode), overlaps G2
    cudaStreamWaitEvent(s2, eG1, 0);
    cudaStreamWaitEvent(s2, eMode, 0);
    local_attn_kernel<<<3 * HH * (LL / 16), 256, 0, s2>>>(0);
    cudaEventRecord(eL123, s2);

    // s1: gated full path (needs full QKV; stubs when no batch is mode 0)
    cudaStreamWaitEvent(s1, eQkv, 0);
    gemm128<<<dim3(LL / 128, LL / 128, BB * HH), 256, 0, s1>>>(
        qkv_p, QKVD, (long)LL * QKVD, HD,
        qkv_p + DD, QKVD, (long)LL * QKVD, HD,
        sc_p, LL, (long)HH * LL * LL, (long)LL * LL,
        HD, SCALE, nullptr, HH, mode_p);
    softmax_kernel<<<BB * HH * (LL / 64), 256, 0, s1>>>(sparse_w, sparse_b);
    gemm_bt<<<dim3(HD / 64, LL / 64, BB * HH), 256, 0, s1>>>(
        sc_p, LL, (long)HH * LL * LL, (long)LL * LL,
        qkv_p + 2 * DD, QKVD, (long)LL * QKVD, HD,
        attn_p, DD, (long)LL * DD, HD,
        LL, HD, LL, 1.f, nullptr, HH, 0, mode_p);
    cvt_split<1><<<(ML * DD / 4 + 255) / 256, 256, 0, s1>>>(attn_p, ahl_p, ML, mode_p);
    cudaEventRecord(eFull, s1);

    // main: local attention for batch 3 (needs G2 [program order] + mode)
    cudaStreamWaitEvent(0, eMode, 0);
    local_attn_kernel<<<1 * HH * (LL / 16), 256>>>(3);

    // join: proj GEMM needs all of g_ahl (L123, L4, gated full) and proj weights
    cudaStreamWaitEvent(0, eL123, 0);
    cudaStreamWaitEvent(0, eFull, 0);
    cudaStreamWaitEvent(0, eWp, 0);
    gemm_mma<<<dim3(DD / 128, ML / 128), 256, GM_DSM>>>(
        ahl_p, pwhl_p, out, DD, DD, proj_b, 0);
}

// round 13
// speedup vs baseline: 12.0051x; 1.1081x over previous
#include <cuda_runtime.h>
#include <cuda_bf16.h>
#include <cuda_fp16.h>
#include <cstdint>
#include <math.h>

#define BB 4
#define LL 1024
#define DD 512
#define HH 8
#define HD 64
#define QKVD 1536
#define ML (BB*LL)
#define K2 1024              // 2 * 512 split-K for fp16 two-term GEMM
#define KTOP 716
#define THRESH 0.05f
#define SCALE 0.125f
#define NEG_INF __int_as_float(0xff800000)

#define NCHUNK (K2 / 64)             // 16 chunks of K=64
#define STAGE_BYTES 32768            // A(16KB) + B(16KB) per stage
#define GM_DSM (3 * STAGE_BYTES + 128)

// Scratch (device globals; no allocations allowed)
__device__ float g_qkv[ML * QKVD];
__device__ float g_scores[(size_t)BB * HH * LL * LL];
__device__ float g_attn[ML * DD];
__device__ float g_pw[BB * 3];
__device__ int   g_mode[BB];
__device__ float g_pool_part[32][DD];
// fp16 two-term split buffers
__device__ __half g_xhl[ML * K2];
__device__ __half g_wqhl[QKVD * K2];
__device__ __half g_ahl[ML * K2];
__device__ __half g_pwhl[DD * K2];

__device__ __forceinline__ uint32_t smem_u32(const void* p) {
    return (uint32_t)__cvta_generic_to_shared(p);
}
__device__ __forceinline__ void cp16(uint32_t dst, const void* src) {
    asm volatile("cp.async.cg.shared.global [%0], [%1], 16;\n" :: "r"(dst), "l"(src));
}
// row r (0..127), 16B unit u (0..7) inside a 128-row x 128B swizzled buffer
__device__ __forceinline__ uint32_t swz(uint32_t bufbase, int r, int u) {
    return bufbase + r * 128 + ((u ^ (r & 7)) << 4);
}

// ---------------------------------------------------------------------------
// fp32 -> fp16 two-term split. Astyle: [hi | lo]. Bstyle: [hi | hi].
// gate != nullptr: only process rows whose batch (m/LL) has mode 0.
// ---------------------------------------------------------------------------
template<int ASTYLE>
__global__ __launch_bounds__(256)
void cvt_split(const float* __restrict__ src, __half* __restrict__ dst,
               int M, const int* __restrict__ gate)
{
    int i = blockIdx.x * 256 + threadIdx.x;
    int total = M * (DD / 4);
    if (i >= total) return;
    int m = i / (DD / 4), c = i % (DD / 4);
    if (gate && gate[m / LL] != 0) return;
    float4 v = ((const float4*)(src + (size_t)m * DD))[c];
    __half hi[4], lo[4];
    float vv[4] = {v.x, v.y, v.z, v.w};
#pragma unroll
    for (int t = 0; t < 4; t++) {
        hi[t] = __float2half_rn(vv[t]);
        lo[t] = __float2half_rn(vv[t] - __half2float(hi[t]));
    }
    __half* d = dst + (size_t)m * K2 + c * 4;
    __half2* d0 = (__half2*)(d);
    __half2* d1 = (__half2*)(d + DD);
    __half2 hp0 = {hi[0], hi[1]}, hp1 = {hi[2], hi[3]};
    __half2 lp0 = {lo[0], lo[1]}, lp1 = {lo[2], lo[3]};
    d0[0] = hp0; d0[1] = hp1;
    if (ASTYLE) {
        d1[0] = lp0; d1[1] = lp1;      // A: [hi, lo]
    } else {
        d1[0] = hp0; d1[1] = hp1;      // B: [hi, hi]
    }
}

// ---------------------------------------------------------------------------
// fp16 NT GEMM via mma.sync m16n8k16, 3-stage cp.async pipeline,
// XOR-swizzled smem, one barrier per K-chunk. m_base allows row-split launches.
// ---------------------------------------------------------------------------
__global__ __launch_bounds__(256, 2)
void gemm_mma(const __half* __restrict__ A2,
              const __half* __restrict__ B2,
              float* __restrict__ C, int ldc, int N,
              const float* __restrict__ bias, int m_base)
{
    extern __shared__ char dsm[];
    uint32_t base = (smem_u32(dsm) + 127) & ~127u;
    int tid = threadIdx.x;
    int warp = tid >> 5, lane = tid & 31;
    int wm = warp >> 1, wn = warp & 1;
    int m0 = m_base + blockIdx.y * 128, n0 = blockIdx.x * 128;
    int m0w = wm * 32, n0w = wn * 64;

    float acc[2][8][4];
#pragma unroll
    for (int a = 0; a < 2; a++)
#pragma unroll
        for (int b = 0; b < 8; b++)
#pragma unroll
            for (int c = 0; c < 4; c++) acc[a][b][c] = 0.f;

    int u = tid & 7, row0 = tid >> 3;

    auto issue = [&](int chunk) {
        int s = chunk % 3;
        uint32_t bA = base + s * STAGE_BYTES;
        uint32_t bB = bA + 16384;
        int k0 = chunk * 64;
#pragma unroll
        for (int p = 0; p < 4; p++) {
            int r = row0 + p * 32;
            cp16(swz(bA, r, u), A2 + (size_t)(m0 + r) * K2 + k0 + u * 8);
            cp16(swz(bB, r, u), B2 + (size_t)(n0 + r) * K2 + k0 + u * 8);
        }
        asm volatile("cp.async.commit_group;\n");
    };

    issue(0);
    issue(1);

    for (int c = 0; c < NCHUNK; c++) {
        if (c + 2 < NCHUNK) {
            asm volatile("cp.async.wait_group 1;\n");
        } else {
            asm volatile("cp.async.wait_group 0;\n");
        }
        __syncthreads();
        if (c + 2 < NCHUNK) issue(c + 2);

        int s = c % 3;
        uint32_t bA = base + s * STAGE_BYTES;
        uint32_t bB = bA + 16384;
#pragma unroll
        for (int kk = 0; kk < 64; kk += 16) {
            int ub = kk >> 3;
            uint32_t a[2][4];
#pragma unroll
            for (int mt = 0; mt < 2; mt++) {
                int mrow = m0w + mt * 16 + (lane & 15);
                int un = ub + (lane >> 4);
                uint32_t ad = swz(bA, mrow, un);
                asm volatile("ldmatrix.sync.aligned.m8n8.x4.shared.b16 {%0,%1,%2,%3}, [%4];"
                    : "=r"(a[mt][0]), "=r"(a[mt][1]), "=r"(a[mt][2]), "=r"(a[mt][3])
                    : "r"(ad));
            }
            uint32_t bfr[4][4];
#pragma unroll
            for (int g = 0; g < 4; g++) {
                int nrow = n0w + g * 16 + ((lane >> 4) << 3) + (lane & 7);
                int un = ub + ((lane >> 3) & 1);
                uint32_t ad = swz(bB, nrow, un);
                asm volatile("ldmatrix.sync.aligned.m8n8.x4.shared.b16 {%0,%1,%2,%3}, [%4];"
                    : "=r"(bfr[g][0]), "=r"(bfr[g][1]), "=r"(bfr[g][2]), "=r"(bfr[g][3])
                    : "r"(ad));
            }
#pragma unroll
            for (int mt = 0; mt < 2; mt++)
#pragma unroll
                for (int nt = 0; nt < 8; nt++) {
                    int g = nt >> 1, pr = (nt & 1) * 2;
                    asm volatile(
                        "mma.sync.aligned.m16n8k16.row.col.f32.f16.f16.f32 "
                        "{%0,%1,%2,%3}, {%4,%5,%6,%7}, {%8,%9}, {%0,%1,%2,%3};"
                        : "+f"(acc[mt][nt][0]), "+f"(acc[mt][nt][1]),
                          "+f"(acc[mt][nt][2]), "+f"(acc[mt][nt][3])
                        : "r"(a[mt][0]), "r"(a[mt][1]), "r"(a[mt][2]), "r"(a[mt][3]),
                          "r"(bfr[g][pr]), "r"(bfr[g][pr + 1]));
                }
        }
    }

    // epilogue
#pragma unroll
    for (int mt = 0; mt < 2; mt++) {
        int mA = m0 + m0w + mt * 16 + (lane >> 2);
#pragma unroll
        for (int nt = 0; nt < 8; nt++) {
            int n = n0 + n0w + nt * 8 + (lane & 3) * 2;
            if (n >= N) continue;
            float b0 = bias ? bias[n] : 0.f;
            float b1 = bias ? bias[n + 1] : 0.f;
            *(float2*)&C[(size_t)mA * ldc + n] =
                make_float2(acc[mt][nt][0] + b0, acc[mt][nt][1] + b1);
            *(float2*)&C[(size_t)(mA + 8) * ldc + n] =
                make_float2(acc[mt][nt][2] + b0, acc[mt][nt][3] + b1);
        }
    }
}

// ---------------------------------------------------------------------------
// 128x128 fp32 SGEMM (NT) for the gated full-path scores.
// ---------------------------------------------------------------------------
__global__ __launch_bounds__(256)
void gemm128(const float* __restrict__ A, int lda, long sAb, long sAh,
             const float* __restrict__ B, int ldb, long sBb, long sBh,
             float* __restrict__ C, int ldc, long sCb, long sCh,
             int K, float alpha, const float* __restrict__ bias,
             int nh, const int* __restrict__ gate)
{
    __shared__ float As[16][132];
    __shared__ float Bs[16][132];
    int z = blockIdx.z;
    int b = z / nh, h = z % nh;
    if (gate && gate[b] != 0) return;
    A += (size_t)b * sAb + (size_t)h * sAh;
    B += (size_t)b * sBb + (size_t)h * sBh;
    C += (size_t)b * sCb + (size_t)h * sCh;

    int tid = threadIdx.x;
    int tx = tid & 15, ty = tid >> 4;
    int m0 = blockIdx.y * 128, n0 = blockIdx.x * 128;

    float acc[8][8];
#pragma unroll
    for (int i = 0; i < 8; i++)
#pragma unroll
        for (int j = 0; j < 8; j++) acc[i][j] = 0.f;

    for (int k0 = 0; k0 < K; k0 += 16) {
#pragma unroll
        for (int i = 0; i < 8; i++) {
            int idx = tid + i * 256;
            int m = idx >> 4, kk = idx & 15;
            As[kk][m] = A[(size_t)(m0 + m) * lda + k0 + kk];
            Bs[kk][m] = B[(size_t)(n0 + m) * ldb + k0 + kk];
        }
        __syncthreads();
#pragma unroll
        for (int kk = 0; kk < 16; kk++) {
            float4 a0 = *(const float4*)&As[kk][ty * 8];
            float4 a1 = *(const float4*)&As[kk][ty * 8 + 4];
            float4 b0 = *(const float4*)&Bs[kk][tx * 8];
            float4 b1 = *(const float4*)&Bs[kk][tx * 8 + 4];
            float av[8] = {a0.x, a0.y, a0.z, a0.w, a1.x, a1.y, a1.z, a1.w};
            float bv[8] = {b0.x, b0.y, b0.z, b0.w, b1.x, b1.y, b1.z, b1.w};
#pragma unroll
            for (int i = 0; i < 8; i++)
#pragma unroll
                for (int j = 0; j < 8; j++) acc[i][j] += av[i] * bv[j];
        }
        __syncthreads();
    }
#pragma unroll
    for (int i = 0; i < 8; i++) {
        int m = m0 + ty * 8 + i;
        float out[8];
#pragma unroll
        for (int j = 0; j < 8; j++) {
            out[j] = acc[i][j] * alpha;
            if (bias) out[j] += bias[n0 + tx * 8 + j];
        }
        float4* cp = (float4*)&C[(size_t)m * ldc + n0 + tx * 8];
        cp[0] = make_float4(out[0], out[1], out[2], out[3]);
        cp[1] = make_float4(out[4], out[5], out[6], out[7]);
    }
}

// ---------------------------------------------------------------------------
// 64x64 SGEMM (NT/NN) for the gated AV path.
// ---------------------------------------------------------------------------
__global__ __launch_bounds__(256)
void gemm_bt(const float* __restrict__ A, int lda, long sAb, long sAh,
             const float* __restrict__ B, int ldb, long sBb, long sBh,
             float* __restrict__ C, int ldc, long sCb, long sCh,
             int M, int N, int K, float alpha,
             const float* __restrict__ bias, int nh, int bTrans,
             const int* __restrict__ gate)
{
    __shared__ float As[16][65];
    __shared__ float Bs[16][65];
    int z = blockIdx.z;
    int b = z / nh, h = z % nh;
    if (gate && gate[b] != 0) return;
    A += (size_t)b * sAb + (size_t)h * sAh;
    B += (size_t)b * sBb + (size_t)h * sBh;
    C += (size_t)b * sCb + (size_t)h * sCh;

    int tid = threadIdx.x;
    int tx = tid & 15, ty = tid >> 4;
    int m0 = blockIdx.y * 64, n0 = blockIdx.x * 64;

    float acc[4][4];
#pragma unroll
    for (int i = 0; i < 4; i++)
#pragma unroll
        for (int j = 0; j < 4; j++) acc[i][j] = 0.f;

    for (int k0 = 0; k0 < K; k0 += 16) {
#pragma unroll
        for (int i = 0; i < 4; i++) {
            int idx = tid + i * 256;
            int m = idx >> 4, kk = idx & 15;
            As[kk][m] = A[(size_t)(m0 + m) * lda + k0 + kk];
        }
        if (bTrans) {
#pragma unroll
            for (int i = 0; i < 4; i++) {
                int idx = tid + i * 256;
                int n = idx >> 4, kk = idx & 15;
                Bs[kk][n] = B[(size_t)(n0 + n) * ldb + k0 + kk];
            }
        } else {
#pragma unroll
            for (int i = 0; i < 4; i++) {
                int idx = tid + i * 256;
                int n = idx & 63, kk = idx >> 6;
                Bs[kk][n] = B[(size_t)(k0 + kk) * ldb + n0 + n];
            }
        }
        __syncthreads();
#pragma unroll
        for (int kk = 0; kk < 16; kk++) {
            float a[4], bb[4];
#pragma unroll
            for (int i = 0; i < 4; i++) a[i] = As[kk][ty * 4 + i];
#pragma unroll
            for (int j = 0; j < 4; j++) bb[j] = Bs[kk][tx * 4 + j];
#pragma unroll
            for (int i = 0; i < 4; i++)
#pragma unroll
                for (int j = 0; j < 4; j++) acc[i][j] += a[i] * bb[j];
        }
        __syncthreads();
    }
#pragma unroll
    for (int i = 0; i < 4; i++) {
        int m = m0 + ty * 4 + i;
#pragma unroll
        for (int j = 0; j < 4; j++) {
            int n = n0 + tx * 4 + j;
            float v = acc[i][j] * alpha;
            if (bias) v += bias[n];
            C[(size_t)m * ldc + n] = v;
        }
    }
}

// ---------------------------------------------------------------------------
__global__ __launch_bounds__(256)
void pool1_kernel(const float* __restrict__ x)
{
    int blk = blockIdx.x;
    int b = blk >> 3, c = blk & 7;
    int tid = threadIdx.x;
    const float2* xp = (const float2*)(x + ((size_t)b * LL + c * 128) * DD) + tid;
    float s0 = 0.f, s1 = 0.f;
    for (int l = 0; l < 128; l++) {
        float2 v = xp[(size_t)l * (DD / 2)];
        s0 += v.x; s1 += v.y;
    }
    g_pool_part[blk][tid * 2]     = s0;
    g_pool_part[blk][tid * 2 + 1] = s1;
}

// ---------------------------------------------------------------------------
__global__ __launch_bounds__(256)
void pattern_kernel(const float* __restrict__ w1, const float* __restrict__ b1,
                    const float* __restrict__ w2, const float* __restrict__ b2,
                    const float* __restrict__ w3, const float* __restrict__ b3,
                    const float* __restrict__ pbias)
{
    int b = blockIdx.x, tid = threadIdx.x;
    int warp = tid >> 5, lane = tid & 31;
    __shared__ float pooled[DD];
    __shared__ float h1[DD];
    __shared__ float h2[DD / 2];
    __shared__ float lg[3];

    for (int d = tid; d < DD; d += 256) {
        float s = 0.f;
#pragma unroll
        for (int c = 0; c < 8; c++) s += g_pool_part[b * 8 + c][d];
        pooled[d] = s * (1.0f / LL);
    }
    __syncthreads();
    for (int i = warp; i < DD; i += 8) {
        const float* wr = w1 + (size_t)i * DD;
        float a = 0.f;
        for (int k = lane; k < DD; k += 32) a += pooled[k] * wr[k];
#pragma unroll
        for (int o = 16; o > 0; o >>= 1) a += __shfl_xor_sync(~0u, a, o);
        if (lane == 0) h1[i] = fmaxf(a + b1[i], 0.f);
    }
    __syncthreads();
    for (int i = warp; i < DD / 2; i += 8) {
        const float* wr = w2 + (size_t)i * DD;
        float a = 0.f;
        for (int k = lane; k < DD; k += 32) a += h1[k] * wr[k];
#pragma unroll
        for (int o = 16; o > 0; o >>= 1) a += __shfl_xor_sync(~0u, a, o);
        if (lane == 0) h2[i] = fmaxf(a + b2[i], 0.f);
    }
    __syncthreads();
    if (warp < 3) {
        const float* wr = w3 + (size_t)warp * (DD / 2);
        float a = 0.f;
        for (int k = lane; k < DD / 2; k += 32) a += h2[k] * wr[k];
#pragma unroll
        for (int o = 16; o > 0; o >>= 1) a += __shfl_xor_sync(~0u, a, o);
        if (lane == 0) lg[warp] = (a + b3[warp] + pbias[warp]) / 0.3f;
    }
    __syncthreads();
    if (tid == 0) {
        float m = fmaxf(lg[0], fmaxf(lg[1], lg[2]));
        float e0 = expf(lg[0] - m), e1 = expf(lg[1] - m), e2 = expf(lg[2] - m);
        float inv = 1.f / (e0 + e1 + e2);
        float p0 = e0 * inv, p1 = e1 * inv, p2 = e2 * inv;
        g_pw[b * 3 + 0] = p0;
        g_pw[b * 3 + 1] = p1;
        g_pw[b * 3 + 2] = p2;
        bool A00 = p1 > THRESH;
        bool A01 = (p1 + p2) > THRESH;
        bool A10 = (p0 + p1) > THRESH;
        bool A11 = ((p0 + p1) + p2) > THRESH;
        bool need_sparse = (A00 != A01) || (A10 != A11);
        int mode;
        if (need_sparse || A00) mode = 0;
        else if (A10)           mode = 1;
        else                    mode = 2;
        g_mode[b] = mode;
    }
}

// ---------------------------------------------------------------------------
__device__ __forceinline__ void write_split(int m, int col, float v)
{
    __half hi = __float2half_rn(v);
    __half lo = __float2half_rn(v - __half2float(hi));
    __half* d = g_ahl + (size_t)m * K2 + col;
    d[0] = hi; d[DD] = lo;
}

// ---------------------------------------------------------------------------
// Local-window fused attention (mode 1) + all-masked fallback (mode 2).
// b_off allows per-batch-range launches for overlap with the QKV GEMM tail.
// ---------------------------------------------------------------------------
__global__ __launch_bounds__(256)
void local_attn_kernel(int b_off)
{
    __shared__ float ksh[48][65];
    __shared__ float vsh[48][65];
    __shared__ float qsh[16][64];
    __shared__ float psh[16][33];

    int blk = blockIdx.x;
    int b = b_off + (blk >> 9);
    int h = (blk >> 6) & 7;
    int q0 = (blk & 63) * 16;
    int mode = g_mode[b];
    if (mode == 0) return;
    int tid = threadIdx.x;
    const float* base = g_qkv + (size_t)b * LL * QKVD + h * HD;

    if (mode == 2) {
        const float* v0 = base + 2 * DD;
#pragma unroll
        for (int i = 0; i < 4; i++) {
            int idx = tid + i * 256;
            int r = idx >> 6, d = idx & 63;
            write_split(b * LL + q0 + r, h * HD + d, v0[d]);
        }
        return;
    }

    int kb0 = max(q0 - 16, 0);
    int kend = min(q0 + 15 + 16, LL - 1);
    int klen = kend - kb0 + 1;

    for (int i = tid; i < klen * 64; i += 256) {
        int jj = i >> 6, d = i & 63;
        const float* src = base + (size_t)(kb0 + jj) * QKVD;
        ksh[jj][d] = src[DD + d];
        vsh[jj][d] = src[2 * DD + d];
    }
#pragma unroll
    for (int i = 0; i < 4; i++) {
        int idx = tid + i * 256;
        int r = idx >> 6, d = idx & 63;
        qsh[r][d] = base[(size_t)(q0 + r) * QKVD + d];
    }
    __syncthreads();

    int warp = tid >> 5, lane = tid & 31;
#pragma unroll
    for (int rr = 0; rr < 2; rr++) {
        int r = warp * 2 + rr;
        int q = q0 + r;
        int w0 = max(q - 16, 0), w1 = min(q + 16, LL - 1);
        int cnt = w1 - w0 + 1;
        int off = w0 - kb0;

        float s0 = NEG_INF, s1 = NEG_INF;
        if (lane < cnt) {
            float acc = 0.f;
#pragma unroll
            for (int d = 0; d < 64; d++) acc += qsh[r][d] * ksh[off + lane][d];
            s0 = acc * SCALE;
        }
        if (lane + 32 < cnt) {
            float acc = 0.f;
#pragma unroll
            for (int d = 0; d < 64; d++) acc += qsh[r][d] * ksh[off + lane + 32][d];
            s1 = acc * SCALE;
        }
        float m = fmaxf(s0, s1);
#pragma unroll
        for (int o = 16; o > 0; o >>= 1) m = fmaxf(m, __shfl_xor_sync(~0u, m, o));
        float e0 = (lane < cnt) ? __expf(s0 - m) : 0.f;
        float e1 = (lane + 32 < cnt) ? __expf(s1 - m) : 0.f;
        float sum = e0 + e1;
#pragma unroll
        for (int o = 16; o > 0; o >>= 1) sum += __shfl_xor_sync(~0u, sum, o);
        float inv = 1.f / sum;
        if (lane < cnt) psh[r][lane] = e0 * inv;
        if (lane + 32 < cnt) psh[r][lane + 32] = e1 * inv;
        __syncwarp();

        float o0 = 0.f, o1 = 0.f;
        for (int jj = 0; jj < cnt; jj++) {
            float p = psh[r][jj];
            o0 += p * vsh[off + jj][lane];
            o1 += p * vsh[off + jj][lane + 32];
        }
        int m_out = b * LL + q;
        write_split(m_out, h * HD + lane, o0);
        write_split(m_out, h * HD + lane + 32, o1);
    }
}

// ---------------------------------------------------------------------------
// Full-path mask + softmax (mode 0 only). 64 rows per block.
// ---------------------------------------------------------------------------
__device__ __forceinline__ unsigned fkey(float f) {
    unsigned u = __float_as_uint(f);
    return (u & 0x80000000u) ? ~u : (u | 0x80000000u);
}

__global__ __launch_bounds__(256)
void softmax_kernel(const float* __restrict__ sparse_w,
                    const float* __restrict__ sparse_b)
{
    __shared__ float s[LL];
    __shared__ float red[256];
    __shared__ unsigned hist[256];
    __shared__ unsigned sel_prefix, sel_k;
    __shared__ float mx_sh;

    int grp = blockIdx.x;               // 0..511, 64 rows each
    int z = grp >> 4;
    int b = z >> 3, h = z & 7;
    if (g_mode[b] != 0) return;
    int q_base = (grp & 15) * 64;
    int tid = threadIdx.x;

    float p0 = g_pw[b * 3 + 0];
    float p1 = g_pw[b * 3 + 1];
    float p2 = g_pw[b * 3 + 2];
    bool A00 = p1 > THRESH;
    bool A01 = (p1 + p2) > THRESH;
    bool A10 = (p0 + p1) > THRESH;
    bool A11 = ((p0 + p1) + p2) > THRESH;
    bool need_sparse = (A00 != A01) || (A10 != A11);
    float w_h = sparse_w[h], b_h = sparse_b[h];

    for (int r = 0; r < 64; r++) {
        int q = q_base + r;
        float* srow = g_scores + ((size_t)z << 20) + ((size_t)q << 10);
        ((float4*)s)[tid] = ((const float4*)srow)[tid];
        __syncthreads();

        unsigned tu = 0u;
        if (need_sparse) {
            if (tid == 0) { sel_prefix = 0u; sel_k = KTOP; }
            __syncthreads();
            for (int shift = 24; shift >= 0; shift -= 8) {
                hist[tid] = 0u;
                __syncthreads();
                unsigned pref = sel_prefix;
                unsigned hm = (shift == 24) ? 0u : (0xFFFFFFFFu << (shift + 8));
                for (int j = tid; j < LL; j += 256) {
                    float v = __fadd_rn(__fmul_rn(s[j], w_h), b_h);
                    unsigned u = fkey(v);
                    if ((u & hm) == pref) atomicAdd(&hist[(u >> shift) & 255u], 1u);
                }
                __syncthreads();
                if (tid == 0) {
                    unsigned k = sel_k, cum = 0;
                    for (int dgt = 255; dgt >= 0; --dgt) {
                        unsigned c = hist[dgt];
                        if (cum + c >= k) {
                            sel_prefix = pref | ((unsigned)dgt << shift);
                            sel_k = k - cum;
                            break;
                        }
                        cum += c;
                    }
                }
                __syncthreads();
            }
            tu = sel_prefix;
            __syncthreads();
        }

        float v[4];
        float lm = NEG_INF;
#pragma unroll
        for (int i = 0; i < 4; i++) {
            int j = tid * 4 + i;
            float sv = s[j];
            bool lf = (abs(q - j) <= 16);
            bool allow;
            if (need_sparse) {
                float s2 = __fadd_rn(__fmul_rn(sv, w_h), b_h);
                float sf = (fkey(s2) >= tu) ? 1.f : 0.f;
                float comb = (p0 * (lf ? 1.f : 0.f) + p1) + p2 * sf;
                allow = comb > THRESH;
            } else {
                allow = lf ? A10 : A00;
            }
            v[i] = allow ? sv : NEG_INF;
            lm = fmaxf(lm, v[i]);
        }
        red[tid] = lm; __syncthreads();
        for (int o = 128; o > 0; o >>= 1) {
            if (tid < o) red[tid] = fmaxf(red[tid], red[tid + o]);
            __syncthreads();
        }
        if (tid == 0) mx_sh = red[0];
        __syncthreads();
        float mx = mx_sh;

        if (mx == NEG_INF) {
            float4 o;
            o.x = (tid == 0) ? 1.f : 0.f; o.y = 0.f; o.z = 0.f; o.w = 0.f;
            ((float4*)srow)[tid] = o;
            __syncthreads();
            continue;
        }

        float ls = 0.f;
#pragma unroll
        for (int i = 0; i < 4; i++) {
            v[i] = __expf(v[i] - mx);
            ls += v[i];
        }
        red[tid] = ls; __syncthreads();
        for (int o = 128; o > 0; o >>= 1) {
            if (tid < o) red[tid] += red[tid + o];
            __syncthreads();
        }
        if (tid == 0) mx_sh = 1.f / red[0];
        __syncthreads();
        float inv = mx_sh;
        float4 o;
        o.x = v[0] * inv; o.y = v[1] * inv; o.z = v[2] * inv; o.w = v[3] * inv;
        ((float4*)srow)[tid] = o;
        __syncthreads();
    }
}

// ---------------------------------------------------------------------------
extern "C" void kernel_launch(void* const* d_in, const int* in_sizes, int n_in,
                              void* d_out, int out_size)
{
    const float* x        = (const float*)d_in[0];
    const float* qkv_w    = (const float*)d_in[1];
    const float* proj_w   = (const float*)d_in[2];
    const float* proj_b   = (const float*)d_in[3];
    const float* ps_w1    = (const float*)d_in[4];
    const float* ps_b1    = (const float*)d_in[5];
    const float* ps_w2    = (const float*)d_in[6];
    const float* ps_b2    = (const float*)d_in[7];
    const float* ps_w3    = (const float*)d_in[8];
    const float* ps_b3    = (const float*)d_in[9];
    const float* pbias    = (const float*)d_in[10];
    const float* sparse_w = (const float*)d_in[11];
    const float* sparse_b = (const float*)d_in[12];
    float* out = (float*)d_out;

    float *qkv_p, *sc_p, *attn_p;
    int *mode_p;
    __half *xhl_p, *wqhl_p, *ahl_p, *pwhl_p;
    cudaGetSymbolAddress((void**)&qkv_p,  g_qkv);
    cudaGetSymbolAddress((void**)&sc_p,   g_scores);
    cudaGetSymbolAddress((void**)&attn_p, g_attn);
    cudaGetSymbolAddress((void**)&mode_p, g_mode);
    cudaGetSymbolAddress((void**)&xhl_p,  g_xhl);
    cudaGetSymbolAddress((void**)&wqhl_p, g_wqhl);
    cudaGetSymbolAddress((void**)&ahl_p,  g_ahl);
    cudaGetSymbolAddress((void**)&pwhl_p, g_pwhl);

    // One-time setup (first call is the uncaptured correctness run)
    static cudaStream_t s1 = nullptr, s2 = nullptr;
    static cudaEvent_t eFork = nullptr, eMode = nullptr, eWq = nullptr,
                       eWp = nullptr, eG1 = nullptr, eQkv = nullptr,
                       eFull = nullptr, eL123 = nullptr, eP02 = nullptr;
    if (!s1) {
        cudaStreamCreateWithFlags(&s1, cudaStreamNonBlocking);
        cudaStreamCreateWithFlags(&s2, cudaStreamNonBlocking);
        cudaEventCreateWithFlags(&eFork, cudaEventDisableTiming);
        cudaEventCreateWithFlags(&eMode, cudaEventDisableTiming);
        cudaEventCreateWithFlags(&eWq,   cudaEventDisableTiming);
        cudaEventCreateWithFlags(&eWp,   cudaEventDisableTiming);
        cudaEventCreateWithFlags(&eG1,   cudaEventDisableTiming);
        cudaEventCreateWithFlags(&eQkv,  cudaEventDisableTiming);
        cudaEventCreateWithFlags(&eFull, cudaEventDisableTiming);
        cudaEventCreateWithFlags(&eL123, cudaEventDisableTiming);
        cudaEventCreateWithFlags(&eP02,  cudaEventDisableTiming);
        cudaFuncSetAttribute(gemm_mma, cudaFuncAttributeMaxDynamicSharedMemorySize, GM_DSM);
    }

    // Fork side streams off the main (capture-origin) stream
    cudaEventRecord(eFork, 0);
    cudaStreamWaitEvent(s1, eFork, 0);
    cudaStreamWaitEvent(s2, eFork, 0);

    // s1: pattern-selector chain -> g_mode                  [launches 1,2]
    pool1_kernel<<<32, 256, 0, s1>>>(x);
    pattern_kernel<<<BB, 256, 0, s1>>>(ps_w1, ps_b1, ps_w2, ps_b2, ps_w3, ps_b3, pbias);
    cudaEventRecord(eMode, s1);

    // s2: weight conversions                                [launches 3,4]
    cvt_split<0><<<(QKVD * DD / 4 + 255) / 256, 256, 0, s2>>>(qkv_w, wqhl_p, QKVD, nullptr);
    cudaEventRecord(eWq, s2);
    cvt_split<0><<<(DD * DD / 4 + 255) / 256, 256, 0, s2>>>(proj_w, pwhl_p, DD, nullptr);
    cudaEventRecord(eWp, s2);

    // main: full x conversion, then QKV GEMM split          [launches 5,6,7]
    // (gemm_mma G1 is the 6th launch -> ncu -s 5 -c 1 captures it)
    cvt_split<1><<<(ML * DD / 4 + 255) / 256, 256>>>(x, xhl_p, ML, nullptr);
    cudaStreamWaitEvent(0, eWq, 0);
    gemm_mma<<<dim3(QKVD / 128, 24), 256, GM_DSM>>>(
        xhl_p, wqhl_p, qkv_p, QKVD, QKVD, nullptr, 0);
    cudaEventRecord(eG1, 0);
    gemm_mma<<<dim3(QKVD / 128, 8), 256, GM_DSM>>>(
        xhl_p, wqhl_p, qkv_p, QKVD, QKVD, nullptr, 3072);
    cudaEventRecord(eQkv, 0);

    // s2: local attention for batches 0-2 (needs G1 + mode), overlaps G2
    cudaStreamWaitEvent(s2, eG1, 0);
    cudaStreamWaitEvent(s2, eMode, 0);
    local_attn_kernel<<<3 * HH * (LL / 16), 256, 0, s2>>>(0);
    cudaEventRecord(eL123, s2);

    // s1: gated full path (needs full QKV; stubs when no batch is mode 0)
    cudaStreamWaitEvent(s1, eQkv, 0);
    gemm128<<<dim3(LL / 128, LL / 128, BB * HH), 256, 0, s1>>>(
        qkv_p, QKVD, (long)LL * QKVD, HD,
        qkv_p + DD, QKVD, (long)LL * QKVD, HD,
        sc_p, LL, (long)HH * LL * LL, (long)LL * LL,
        HD, SCALE, nullptr, HH, mode_p);
    softmax_kernel<<<BB * HH * (LL / 64), 256, 0, s1>>>(sparse_w, sparse_b);
    gemm_bt<<<dim3(HD / 64, LL / 64, BB * HH), 256, 0, s1>>>(
        sc_p, LL, (long)HH * LL * LL, (long)LL * LL,
        qkv_p + 2 * DD, QKVD, (long)LL * QKVD, HD,
        attn_p, DD, (long)LL * DD, HD,
        LL, HD, LL, 1.f, nullptr, HH, 0, mode_p);
    cvt_split<1><<<(ML * DD / 4 + 255) / 256, 256, 0, s1>>>(attn_p, ahl_p, ML, mode_p);
    cudaEventRecord(eFull, s1);

    // s2: proj for batches 0-2 (needs L123 [program order] + gated cvt + weights)
    cudaStreamWaitEvent(s2, eFull, 0);
    gemm_mma<<<dim3(DD / 128, 24), 256, GM_DSM, s2>>>(
        ahl_p, pwhl_p, out, DD, DD, proj_b, 0);
    cudaEventRecord(eP02, s2);

    // main: local attention for batch 3 (needs G2 [program order] + mode)
    cudaStreamWaitEvent(0, eMode, 0);
    local_attn_kernel<<<1 * HH * (LL / 16), 256>>>(3);

    // main: proj for batch 3 (needs L4 [program order] + gated cvt + weights)
    cudaStreamWaitEvent(0, eFull, 0);
    cudaStreamWaitEvent(0, eWp, 0);
    gemm_mma<<<dim3(DD / 128, 8), 256, GM_DSM>>>(
        ahl_p, pwhl_p, out, DD, DD, proj_b, 3072);

    // join s2 (proj 0-2) back into the capture-origin stream
    cudaStreamWaitEvent(0, eP02, 0);
}

// round 14
// speedup vs baseline: 12.0257x; 1.0017x over previous
#include <cuda_runtime.h>
#include <cuda_bf16.h>
#include <cuda_fp16.h>
#include <cstdint>
#include <math.h>

#define BB 4
#define LL 1024
#define DD 512
#define HH 8
#define HD 64
#define QKVD 1536
#define ML (BB*LL)
#define KH 512               // pure fp16 GEMM: K = 512, no split expansion
#define KTOP 716
#define THRESH 0.05f
#define SCALE 0.125f
#define NEG_INF __int_as_float(0xff800000)

#define NCHUNK (KH / 64)             // 8 chunks of K=64
#define STAGE_BYTES 32768            // A(16KB) + B(16KB) per stage
#define GM_DSM (3 * STAGE_BYTES + 128)

// Scratch (device globals; no allocations allowed)
__device__ float g_qkv[ML * QKVD];
__device__ float g_scores[(size_t)BB * HH * LL * LL];
__device__ float g_attn[ML * DD];
__device__ float g_pw[BB * 3];
__device__ int   g_mode[BB];
__device__ float g_pool_part[32][DD];
// fp16 buffers
__device__ __half g_xh[ML * KH];
__device__ __half g_wqh[QKVD * KH];
__device__ __half g_ah[ML * KH];
__device__ __half g_pwh[DD * KH];

__device__ __forceinline__ uint32_t smem_u32(const void* p) {
    return (uint32_t)__cvta_generic_to_shared(p);
}
__device__ __forceinline__ void cp16(uint32_t dst, const void* src) {
    asm volatile("cp.async.cg.shared.global [%0], [%1], 16;\n" :: "r"(dst), "l"(src));
}
// row r (0..127), 16B unit u (0..7) inside a 128-row x 128B swizzled buffer
__device__ __forceinline__ uint32_t swz(uint32_t bufbase, int r, int u) {
    return bufbase + r * 128 + ((u ^ (r & 7)) << 4);
}

// ---------------------------------------------------------------------------
// fp32 -> fp16 convert, row-major [M][512]. gate: skip non-mode-0 batches.
// ---------------------------------------------------------------------------
__global__ __launch_bounds__(256)
void cvt_h(const float* __restrict__ src, __half* __restrict__ dst,
           int M, const int* __restrict__ gate)
{
    int i = blockIdx.x * 256 + threadIdx.x;
    int total = M * (DD / 4);
    if (i >= total) return;
    int m = i / (DD / 4), c = i % (DD / 4);
    if (gate && gate[m / LL] != 0) return;
    float4 v = ((const float4*)(src + (size_t)m * DD))[c];
    __half2 h0 = {__float2half_rn(v.x), __float2half_rn(v.y)};
    __half2 h1 = {__float2half_rn(v.z), __float2half_rn(v.w)};
    __half2* d = (__half2*)(dst + (size_t)m * KH + c * 4);
    d[0] = h0; d[1] = h1;
}

// ---------------------------------------------------------------------------
// fp16 NT GEMM via mma.sync m16n8k16, 3-stage cp.async pipeline,
// XOR-swizzled smem, one barrier per K-chunk. m_base allows row-split launches.
// ---------------------------------------------------------------------------
__global__ __launch_bounds__(256, 2)
void gemm_mma(const __half* __restrict__ A2,
              const __half* __restrict__ B2,
              float* __restrict__ C, int ldc, int N,
              const float* __restrict__ bias, int m_base)
{
    extern __shared__ char dsm[];
    uint32_t base = (smem_u32(dsm) + 127) & ~127u;
    int tid = threadIdx.x;
    int warp = tid >> 5, lane = tid & 31;
    int wm = warp >> 1, wn = warp & 1;
    int m0 = m_base + blockIdx.y * 128, n0 = blockIdx.x * 128;
    int m0w = wm * 32, n0w = wn * 64;

    float acc[2][8][4];
#pragma unroll
    for (int a = 0; a < 2; a++)
#pragma unroll
        for (int b = 0; b < 8; b++)
#pragma unroll
            for (int c = 0; c < 4; c++) acc[a][b][c] = 0.f;

    int u = tid & 7, row0 = tid >> 3;

    auto issue = [&](int chunk) {
        int s = chunk % 3;
        uint32_t bA = base + s * STAGE_BYTES;
        uint32_t bB = bA + 16384;
        int k0 = chunk * 64;
#pragma unroll
        for (int p = 0; p < 4; p++) {
            int r = row0 + p * 32;
            cp16(swz(bA, r, u), A2 + (size_t)(m0 + r) * KH + k0 + u * 8);
            cp16(swz(bB, r, u), B2 + (size_t)(n0 + r) * KH + k0 + u * 8);
        }
        asm volatile("cp.async.commit_group;\n");
    };

    issue(0);
    issue(1);

    for (int c = 0; c < NCHUNK; c++) {
        if (c + 2 < NCHUNK) {
            asm volatile("cp.async.wait_group 1;\n");
        } else {
            asm volatile("cp.async.wait_group 0;\n");
        }
        __syncthreads();
        if (c + 2 < NCHUNK) issue(c + 2);

        int s = c % 3;
        uint32_t bA = base + s * STAGE_BYTES;
        uint32_t bB = bA + 16384;
#pragma unroll
        for (int kk = 0; kk < 64; kk += 16) {
            int ub = kk >> 3;
            uint32_t a[2][4];
#pragma unroll
            for (int mt = 0; mt < 2; mt++) {
                int mrow = m0w + mt * 16 + (lane & 15);
                int un = ub + (lane >> 4);
                uint32_t ad = swz(bA, mrow, un);
                asm volatile("ldmatrix.sync.aligned.m8n8.x4.shared.b16 {%0,%1,%2,%3}, [%4];"
                    : "=r"(a[mt][0]), "=r"(a[mt][1]), "=r"(a[mt][2]), "=r"(a[mt][3])
                    : "r"(ad));
            }
            uint32_t bfr[4][4];
#pragma unroll
            for (int g = 0; g < 4; g++) {
                int nrow = n0w + g * 16 + ((lane >> 4) << 3) + (lane & 7);
                int un = ub + ((lane >> 3) & 1);
                uint32_t ad = swz(bB, nrow, un);
                asm volatile("ldmatrix.sync.aligned.m8n8.x4.shared.b16 {%0,%1,%2,%3}, [%4];"
                    : "=r"(bfr[g][0]), "=r"(bfr[g][1]), "=r"(bfr[g][2]), "=r"(bfr[g][3])
                    : "r"(ad));
            }
#pragma unroll
            for (int mt = 0; mt < 2; mt++)
#pragma unroll
                for (int nt = 0; nt < 8; nt++) {
                    int g = nt >> 1, pr = (nt & 1) * 2;
                    asm volatile(
                        "mma.sync.aligned.m16n8k16.row.col.f32.f16.f16.f32 "
                        "{%0,%1,%2,%3}, {%4,%5,%6,%7}, {%8,%9}, {%0,%1,%2,%3};"
                        : "+f"(acc[mt][nt][0]), "+f"(acc[mt][nt][1]),
                          "+f"(acc[mt][nt][2]), "+f"(acc[mt][nt][3])
                        : "r"(a[mt][0]), "r"(a[mt][1]), "r"(a[mt][2]), "r"(a[mt][3]),
                          "r"(bfr[g][pr]), "r"(bfr[g][pr + 1]));
                }
        }
    }

    // epilogue
#pragma unroll
    for (int mt = 0; mt < 2; mt++) {
        int mA = m0 + m0w + mt * 16 + (lane >> 2);
#pragma unroll
        for (int nt = 0; nt < 8; nt++) {
            int n = n0 + n0w + nt * 8 + (lane & 3) * 2;
            if (n >= N) continue;
            float b0 = bias ? bias[n] : 0.f;
            float b1 = bias ? bias[n + 1] : 0.f;
            *(float2*)&C[(size_t)mA * ldc + n] =
                make_float2(acc[mt][nt][0] + b0, acc[mt][nt][1] + b1);
            *(float2*)&C[(size_t)(mA + 8) * ldc + n] =
                make_float2(acc[mt][nt][2] + b0, acc[mt][nt][3] + b1);
        }
    }
}

// ---------------------------------------------------------------------------
// 128x128 fp32 SGEMM (NT) for the gated full-path scores.
// ---------------------------------------------------------------------------
__global__ __launch_bounds__(256)
void gemm128(const float* __restrict__ A, int lda, long sAb, long sAh,
             const float* __restrict__ B, int ldb, long sBb, long sBh,
             float* __restrict__ C, int ldc, long sCb, long sCh,
             int K, float alpha, const float* __restrict__ bias,
             int nh, const int* __restrict__ gate)
{
    __shared__ float As[16][132];
    __shared__ float Bs[16][132];
    int z = blockIdx.z;
    int b = z / nh, h = z % nh;
    if (gate && gate[b] != 0) return;
    A += (size_t)b * sAb + (size_t)h * sAh;
    B += (size_t)b * sBb + (size_t)h * sBh;
    C += (size_t)b * sCb + (size_t)h * sCh;

    int tid = threadIdx.x;
    int tx = tid & 15, ty = tid >> 4;
    int m0 = blockIdx.y * 128, n0 = blockIdx.x * 128;

    float acc[8][8];
#pragma unroll
    for (int i = 0; i < 8; i++)
#pragma unroll
        for (int j = 0; j < 8; j++) acc[i][j] = 0.f;

    for (int k0 = 0; k0 < K; k0 += 16) {
#pragma unroll
        for (int i = 0; i < 8; i++) {
            int idx = tid + i * 256;
            int m = idx >> 4, kk = idx & 15;
            As[kk][m] = A[(size_t)(m0 + m) * lda + k0 + kk];
            Bs[kk][m] = B[(size_t)(n0 + m) * ldb + k0 + kk];
        }
        __syncthreads();
#pragma unroll
        for (int kk = 0; kk < 16; kk++) {
            float4 a0 = *(const float4*)&As[kk][ty * 8];
            float4 a1 = *(const float4*)&As[kk][ty * 8 + 4];
            float4 b0 = *(const float4*)&Bs[kk][tx * 8];
            float4 b1 = *(const float4*)&Bs[kk][tx * 8 + 4];
            float av[8] = {a0.x, a0.y, a0.z, a0.w, a1.x, a1.y, a1.z, a1.w};
            float bv[8] = {b0.x, b0.y, b0.z, b0.w, b1.x, b1.y, b1.z, b1.w};
#pragma unroll
            for (int i = 0; i < 8; i++)
#pragma unroll
                for (int j = 0; j < 8; j++) acc[i][j] += av[i] * bv[j];
        }
        __syncthreads();
    }
#pragma unroll
    for (int i = 0; i < 8; i++) {
        int m = m0 + ty * 8 + i;
        float out[8];
#pragma unroll
        for (int j = 0; j < 8; j++) {
            out[j] = acc[i][j] * alpha;
            if (bias) out[j] += bias[n0 + tx * 8 + j];
        }
        float4* cp = (float4*)&C[(size_t)m * ldc + n0 + tx * 8];
        cp[0] = make_float4(out[0], out[1], out[2], out[3]);
        cp[1] = make_float4(out[4], out[5], out[6], out[7]);
    }
}

// ---------------------------------------------------------------------------
// 64x64 SGEMM (NT/NN) for the gated AV path.
// ---------------------------------------------------------------------------
__global__ __launch_bounds__(256)
void gemm_bt(const float* __restrict__ A, int lda, long sAb, long sAh,
             const float* __restrict__ B, int ldb, long sBb, long sBh,
             float* __restrict__ C, int ldc, long sCb, long sCh,
             int M, int N, int K, float alpha,
             const float* __restrict__ bias, int nh, int bTrans,
             const int* __restrict__ gate)
{
    __shared__ float As[16][65];
    __shared__ float Bs[16][65];
    int z = blockIdx.z;
    int b = z / nh, h = z % nh;
    if (gate && gate[b] != 0) return;
    A += (size_t)b * sAb + (size_t)h * sAh;
    B += (size_t)b * sBb + (size_t)h * sBh;
    C += (size_t)b * sCb + (size_t)h * sCh;

    int tid = threadIdx.x;
    int tx = tid & 15, ty = tid >> 4;
    int m0 = blockIdx.y * 64, n0 = blockIdx.x * 64;

    float acc[4][4];
#pragma unroll
    for (int i = 0; i < 4; i++)
#pragma unroll
        for (int j = 0; j < 4; j++) acc[i][j] = 0.f;

    for (int k0 = 0; k0 < K; k0 += 16) {
#pragma unroll
        for (int i = 0; i < 4; i++) {
            int idx = tid + i * 256;
            int m = idx >> 4, kk = idx & 15;
            As[kk][m] = A[(size_t)(m0 + m) * lda + k0 + kk];
        }
        if (bTrans) {
#pragma unroll
            for (int i = 0; i < 4; i++) {
                int idx = tid + i * 256;
                int n = idx >> 4, kk = idx & 15;
                Bs[kk][n] = B[(size_t)(n0 + n) * ldb + k0 + kk];
            }
        } else {
#pragma unroll
            for (int i = 0; i < 4; i++) {
                int idx = tid + i * 256;
                int n = idx & 63, kk = idx >> 6;
                Bs[kk][n] = B[(size_t)(k0 + kk) * ldb + n0 + n];
            }
        }
        __syncthreads();
#pragma unroll
        for (int kk = 0; kk < 16; kk++) {
            float a[4], bb[4];
#pragma unroll
            for (int i = 0; i < 4; i++) a[i] = As[kk][ty * 4 + i];
#pragma unroll
            for (int j = 0; j < 4; j++) bb[j] = Bs[kk][tx * 4 + j];
#pragma unroll
            for (int i = 0; i < 4; i++)
#pragma unroll
                for (int j = 0; j < 4; j++) acc[i][j] += a[i] * bb[j];
        }
        __syncthreads();
    }
#pragma unroll
    for (int i = 0; i < 4; i++) {
        int m = m0 + ty * 4 + i;
#pragma unroll
        for (int j = 0; j < 4; j++) {
            int n = n0 + tx * 4 + j;
            float v = acc[i][j] * alpha;
            if (bias) v += bias[n];
            C[(size_t)m * ldc + n] = v;
        }
    }
}

// ---------------------------------------------------------------------------
__global__ __launch_bounds__(256)
void pool1_kernel(const float* __restrict__ x)
{
    int blk = blockIdx.x;
    int b = blk >> 3, c = blk & 7;
    int tid = threadIdx.x;
    const float2* xp = (const float2*)(x + ((size_t)b * LL + c * 128) * DD) + tid;
    float s0 = 0.f, s1 = 0.f;
    for (int l = 0; l < 128; l++) {
        float2 v = xp[(size_t)l * (DD / 2)];
        s0 += v.x; s1 += v.y;
    }
    g_pool_part[blk][tid * 2]     = s0;
    g_pool_part[blk][tid * 2 + 1] = s1;
}

// ---------------------------------------------------------------------------
__global__ __launch_bounds__(256)
void pattern_kernel(const float* __restrict__ w1, const float* __restrict__ b1,
                    const float* __restrict__ w2, const float* __restrict__ b2,
                    const float* __restrict__ w3, const float* __restrict__ b3,
                    const float* __restrict__ pbias)
{
    int b = blockIdx.x, tid = threadIdx.x;
    int warp = tid >> 5, lane = tid & 31;
    __shared__ float pooled[DD];
    __shared__ float h1[DD];
    __shared__ float h2[DD / 2];
    __shared__ float lg[3];

    for (int d = tid; d < DD; d += 256) {
        float s = 0.f;
#pragma unroll
        for (int c = 0; c < 8; c++) s += g_pool_part[b * 8 + c][d];
        pooled[d] = s * (1.0f / LL);
    }
    __syncthreads();
    for (int i = warp; i < DD; i += 8) {
        const float* wr = w1 + (size_t)i * DD;
        float a = 0.f;
        for (int k = lane; k < DD; k += 32) a += pooled[k] * wr[k];
#pragma unroll
        for (int o = 16; o > 0; o >>= 1) a += __shfl_xor_sync(~0u, a, o);
        if (lane == 0) h1[i] = fmaxf(a + b1[i], 0.f);
    }
    __syncthreads();
    for (int i = warp; i < DD / 2; i += 8) {
        const float* wr = w2 + (size_t)i * DD;
        float a = 0.f;
        for (int k = lane; k < DD; k += 32) a += h1[k] * wr[k];
#pragma unroll
        for (int o = 16; o > 0; o >>= 1) a += __shfl_xor_sync(~0u, a, o);
        if (lane == 0) h2[i] = fmaxf(a + b2[i], 0.f);
    }
    __syncthreads();
    if (warp < 3) {
        const float* wr = w3 + (size_t)warp * (DD / 2);
        float a = 0.f;
        for (int k = lane; k < DD / 2; k += 32) a += h2[k] * wr[k];
#pragma unroll
        for (int o = 16; o > 0; o >>= 1) a += __shfl_xor_sync(~0u, a, o);
        if (lane == 0) lg[warp] = (a + b3[warp] + pbias[warp]) / 0.3f;
    }
    __syncthreads();
    if (tid == 0) {
        float m = fmaxf(lg[0], fmaxf(lg[1], lg[2]));
        float e0 = expf(lg[0] - m), e1 = expf(lg[1] - m), e2 = expf(lg[2] - m);
        float inv = 1.f / (e0 + e1 + e2);
        float p0 = e0 * inv, p1 = e1 * inv, p2 = e2 * inv;
        g_pw[b * 3 + 0] = p0;
        g_pw[b * 3 + 1] = p1;
        g_pw[b * 3 + 2] = p2;
        bool A00 = p1 > THRESH;
        bool A01 = (p1 + p2) > THRESH;
        bool A10 = (p0 + p1) > THRESH;
        bool A11 = ((p0 + p1) + p2) > THRESH;
        bool need_sparse = (A00 != A01) || (A10 != A11);
        int mode;
        if (need_sparse || A00) mode = 0;
        else if (A10)           mode = 1;
        else                    mode = 2;
        g_mode[b] = mode;
    }
}

// ---------------------------------------------------------------------------
__device__ __forceinline__ void write_h(int m, int col, float v)
{
    g_ah[(size_t)m * KH + col] = __float2half_rn(v);
}

// ---------------------------------------------------------------------------
// Local-window fused attention (mode 1) + all-masked fallback (mode 2).
// b_off allows per-batch-range launches for overlap with the QKV GEMM tail.
// ---------------------------------------------------------------------------
__global__ __launch_bounds__(256)
void local_attn_kernel(int b_off)
{
    __shared__ float ksh[48][65];
    __shared__ float vsh[48][65];
    __shared__ float qsh[16][64];
    __shared__ float psh[16][33];

    int blk = blockIdx.x;
    int b = b_off + (blk >> 9);
    int h = (blk >> 6) & 7;
    int q0 = (blk & 63) * 16;
    int mode = g_mode[b];
    if (mode == 0) return;
    int tid = threadIdx.x;
    const float* base = g_qkv + (size_t)b * LL * QKVD + h * HD;

    if (mode == 2) {
        const float* v0 = base + 2 * DD;
#pragma unroll
        for (int i = 0; i < 4; i++) {
            int idx = tid + i * 256;
            int r = idx >> 6, d = idx & 63;
            write_h(b * LL + q0 + r, h * HD + d, v0[d]);
        }
        return;
    }

    int kb0 = max(q0 - 16, 0);
    int kend = min(q0 + 15 + 16, LL - 1);
    int klen = kend - kb0 + 1;

    for (int i = tid; i < klen * 64; i += 256) {
        int jj = i >> 6, d = i & 63;
        const float* src = base + (size_t)(kb0 + jj) * QKVD;
        ksh[jj][d] = src[DD + d];
        vsh[jj][d] = src[2 * DD + d];
    }
#pragma unroll
    for (int i = 0; i < 4; i++) {
        int idx = tid + i * 256;
        int r = idx >> 6, d = idx & 63;
        qsh[r][d] = base[(size_t)(q0 + r) * QKVD + d];
    }
    __syncthreads();

    int warp = tid >> 5, lane = tid & 31;
#pragma unroll
    for (int rr = 0; rr < 2; rr++) {
        int r = warp * 2 + rr;
        int q = q0 + r;
        int w0 = max(q - 16, 0), w1 = min(q + 16, LL - 1);
        int cnt = w1 - w0 + 1;
        int off = w0 - kb0;

        float s0 = NEG_INF, s1 = NEG_INF;
        if (lane < cnt) {
            float acc = 0.f;
#pragma unroll
            for (int d = 0; d < 64; d++) acc += qsh[r][d] * ksh[off + lane][d];
            s0 = acc * SCALE;
        }
        if (lane + 32 < cnt) {
            float acc = 0.f;
#pragma unroll
            for (int d = 0; d < 64; d++) acc += qsh[r][d] * ksh[off + lane + 32][d];
            s1 = acc * SCALE;
        }
        float m = fmaxf(s0, s1);
#pragma unroll
        for (int o = 16; o > 0; o >>= 1) m = fmaxf(m, __shfl_xor_sync(~0u, m, o));
        float e0 = (lane < cnt) ? __expf(s0 - m) : 0.f;
        float e1 = (lane + 32 < cnt) ? __expf(s1 - m) : 0.f;
        float sum = e0 + e1;
#pragma unroll
        for (int o = 16; o > 0; o >>= 1) sum += __shfl_xor_sync(~0u, sum, o);
        float inv = 1.f / sum;
        if (lane < cnt) psh[r][lane] = e0 * inv;
        if (lane + 32 < cnt) psh[r][lane + 32] = e1 * inv;
        __syncwarp();

        float o0 = 0.f, o1 = 0.f;
        for (int jj = 0; jj < cnt; jj++) {
            float p = psh[r][jj];
            o0 += p * vsh[off + jj][lane];
            o1 += p * vsh[off + jj][lane + 32];
        }
        int m_out = b * LL + q;
        write_h(m_out, h * HD + lane, o0);
        write_h(m_out, h * HD + lane + 32, o1);
    }
}

// ---------------------------------------------------------------------------
// Full-path mask + softmax (mode 0 only). 64 rows per block.
// ---------------------------------------------------------------------------
__device__ __forceinline__ unsigned fkey(float f) {
    unsigned u = __float_as_uint(f);
    return (u & 0x80000000u) ? ~u : (u | 0x80000000u);
}

__global__ __launch_bounds__(256)
void softmax_kernel(const float* __restrict__ sparse_w,
                    const float* __restrict__ sparse_b)
{
    __shared__ float s[LL];
    __shared__ float red[256];
    __shared__ unsigned hist[256];
    __shared__ unsigned sel_prefix, sel_k;
    __shared__ float mx_sh;

    int grp = blockIdx.x;               // 0..511, 64 rows each
    int z = grp >> 4;
    int b = z >> 3, h = z & 7;
    if (g_mode[b] != 0) return;
    int q_base = (grp & 15) * 64;
    int tid = threadIdx.x;

    float p0 = g_pw[b * 3 + 0];
    float p1 = g_pw[b * 3 + 1];
    float p2 = g_pw[b * 3 + 2];
    bool A00 = p1 > THRESH;
    bool A01 = (p1 + p2) > THRESH;
    bool A10 = (p0 + p1) > THRESH;
    bool A11 = ((p0 + p1) + p2) > THRESH;
    bool need_sparse = (A00 != A01) || (A10 != A11);
    float w_h = sparse_w[h], b_h = sparse_b[h];

    for (int r = 0; r < 64; r++) {
        int q = q_base + r;
        float* srow = g_scores + ((size_t)z << 20) + ((size_t)q << 10);
        ((float4*)s)[tid] = ((const float4*)srow)[tid];
        __syncthreads();

        unsigned tu = 0u;
        if (need_sparse) {
            if (tid == 0) { sel_prefix = 0u; sel_k = KTOP; }
            __syncthreads();
            for (int shift = 24; shift >= 0; shift -= 8) {
                hist[tid] = 0u;
                __syncthreads();
                unsigned pref = sel_prefix;
                unsigned hm = (shift == 24) ? 0u : (0xFFFFFFFFu << (shift + 8));
                for (int j = tid; j < LL; j += 256) {
                    float v = __fadd_rn(__fmul_rn(s[j], w_h), b_h);
                    unsigned u = fkey(v);
                    if ((u & hm) == pref) atomicAdd(&hist[(u >> shift) & 255u], 1u);
                }
                __syncthreads();
                if (tid == 0) {
                    unsigned k = sel_k, cum = 0;
                    for (int dgt = 255; dgt >= 0; --dgt) {
                        unsigned c = hist[dgt];
                        if (cum + c >= k) {
                            sel_prefix = pref | ((unsigned)dgt << shift);
                            sel_k = k - cum;
                            break;
                        }
                        cum += c;
                    }
                }
                __syncthreads();
            }
            tu = sel_prefix;
            __syncthreads();
        }

        float v[4];
        float lm = NEG_INF;
#pragma unroll
        for (int i = 0; i < 4; i++) {
            int j = tid * 4 + i;
            float sv = s[j];
            bool lf = (abs(q - j) <= 16);
            bool allow;
            if (need_sparse) {
                float s2 = __fadd_rn(__fmul_rn(sv, w_h), b_h);
                float sf = (fkey(s2) >= tu) ? 1.f : 0.f;
                float comb = (p0 * (lf ? 1.f : 0.f) + p1) + p2 * sf;
                allow = comb > THRESH;
            } else {
                allow = lf ? A10 : A00;
            }
            v[i] = allow ? sv : NEG_INF;
            lm = fmaxf(lm, v[i]);
        }
        red[tid] = lm; __syncthreads();
        for (int o = 128; o > 0; o >>= 1) {
            if (tid < o) red[tid] = fmaxf(red[tid], red[tid + o]);
            __syncthreads();
        }
        if (tid == 0) mx_sh = red[0];
        __syncthreads();
        float mx = mx_sh;

        if (mx == NEG_INF) {
            float4 o;
            o.x = (tid == 0) ? 1.f : 0.f; o.y = 0.f; o.z = 0.f; o.w = 0.f;
            ((float4*)srow)[tid] = o;
            __syncthreads();
            continue;
        }

        float ls = 0.f;
#pragma unroll
        for (int i = 0; i < 4; i++) {
            v[i] = __expf(v[i] - mx);
            ls += v[i];
        }
        red[tid] = ls; __syncthreads();
        for (int o = 128; o > 0; o >>= 1) {
            if (tid < o) red[tid] += red[tid + o];
            __syncthreads();
        }
        if (tid == 0) mx_sh = 1.f / red[0];
        __syncthreads();
        float inv = mx_sh;
        float4 o;
        o.x = v[0] * inv; o.y = v[1] * inv; o.z = v[2] * inv; o.w = v[3] * inv;
        ((float4*)srow)[tid] = o;
        __syncthreads();
    }
}

// ---------------------------------------------------------------------------
extern "C" void kernel_launch(void* const* d_in, const int* in_sizes, int n_in,
                              void* d_out, int out_size)
{
    const float* x        = (const float*)d_in[0];
    const float* qkv_w    = (const float*)d_in[1];
    const float* proj_w   = (const float*)d_in[2];
    const float* proj_b   = (const float*)d_in[3];
    const float* ps_w1    = (const float*)d_in[4];
    const float* ps_b1    = (const float*)d_in[5];
    const float* ps_w2    = (const float*)d_in[6];
    const float* ps_b2    = (const float*)d_in[7];
    const float* ps_w3    = (const float*)d_in[8];
    const float* ps_b3    = (const float*)d_in[9];
    const float* pbias    = (const float*)d_in[10];
    const float* sparse_w = (const float*)d_in[11];
    const float* sparse_b = (const float*)d_in[12];
    float* out = (float*)d_out;

    float *qkv_p, *sc_p, *attn_p;
    int *mode_p;
    __half *xh_p, *wqh_p, *ah_p, *pwh_p;
    cudaGetSymbolAddress((void**)&qkv_p,  g_qkv);
    cudaGetSymbolAddress((void**)&sc_p,   g_scores);
    cudaGetSymbolAddress((void**)&attn_p, g_attn);
    cudaGetSymbolAddress((void**)&mode_p, g_mode);
    cudaGetSymbolAddress((void**)&xh_p,   g_xh);
    cudaGetSymbolAddress((void**)&wqh_p,  g_wqh);
    cudaGetSymbolAddress((void**)&ah_p,   g_ah);
    cudaGetSymbolAddress((void**)&pwh_p,  g_pwh);

    // One-time setup (first call is the uncaptured correctness run)
    static cudaStream_t s1 = nullptr, s2 = nullptr;
    static cudaEvent_t eFork = nullptr, eMode = nullptr, eWq = nullptr,
                       eWp = nullptr, eG1 = nullptr, eQkv = nullptr,
                       eFull = nullptr, eL123 = nullptr, eP02 = nullptr,
                       eX2 = nullptr;
    if (!s1) {
        cudaStreamCreateWithFlags(&s1, cudaStreamNonBlocking);
        cudaStreamCreateWithFlags(&s2, cudaStreamNonBlocking);
        cudaEventCreateWithFlags(&eFork, cudaEventDisableTiming);
        cudaEventCreateWithFlags(&eMode, cudaEventDisableTiming);
        cudaEventCreateWithFlags(&eWq,   cudaEventDisableTiming);
        cudaEventCreateWithFlags(&eWp,   cudaEventDisableTiming);
        cudaEventCreateWithFlags(&eG1,   cudaEventDisableTiming);
        cudaEventCreateWithFlags(&eQkv,  cudaEventDisableTiming);
        cudaEventCreateWithFlags(&eFull, cudaEventDisableTiming);
        cudaEventCreateWithFlags(&eL123, cudaEventDisableTiming);
        cudaEventCreateWithFlags(&eP02,  cudaEventDisableTiming);
        cudaEventCreateWithFlags(&eX2,   cudaEventDisableTiming);
        cudaFuncSetAttribute(gemm_mma, cudaFuncAttributeMaxDynamicSharedMemorySize, GM_DSM);
    }

    // Fork side streams off the main (capture-origin) stream
    cudaEventRecord(eFork, 0);
    cudaStreamWaitEvent(s1, eFork, 0);
    cudaStreamWaitEvent(s2, eFork, 0);

    // s1: pattern-selector chain -> g_mode, then x conversion for batch 3
    pool1_kernel<<<32, 256, 0, s1>>>(x);
    pattern_kernel<<<BB, 256, 0, s1>>>(ps_w1, ps_b1, ps_w2, ps_b2, ps_w3, ps_b3, pbias);
    cudaEventRecord(eMode, s1);
    cvt_h<<<(1024 * DD / 4 + 255) / 256, 256, 0, s1>>>(
        x + (size_t)3072 * DD, xh_p + (size_t)3072 * KH, 1024, nullptr);
    cudaEventRecord(eX2, s1);

    // s2: weight conversions
    cvt_h<<<(QKVD * DD / 4 + 255) / 256, 256, 0, s2>>>(qkv_w, wqh_p, QKVD, nullptr);
    cudaEventRecord(eWq, s2);
    cvt_h<<<(DD * DD / 4 + 255) / 256, 256, 0, s2>>>(proj_w, pwh_p, DD, nullptr);
    cudaEventRecord(eWp, s2);

    // main: x conversion for batches 0-2, then QKV GEMM split:
    // G1 = batches 0-2 (288 CTAs ~ one wave), G2 = batch 3 (96 CTAs).
    cvt_h<<<(3072 * DD / 4 + 255) / 256, 256>>>(x, xh_p, 3072, nullptr);
    cudaStreamWaitEvent(0, eWq, 0);
    gemm_mma<<<dim3(QKVD / 128, 24), 256, GM_DSM>>>(
        xh_p, wqh_p, qkv_p, QKVD, QKVD, nullptr, 0);
    cudaEventRecord(eG1, 0);
    cudaStreamWaitEvent(0, eX2, 0);
    gemm_mma<<<dim3(QKVD / 128, 8), 256, GM_DSM>>>(
        xh_p, wqh_p, qkv_p, QKVD, QKVD, nullptr, 3072);
    cudaEventRecord(eQkv, 0);

    // s2: local attention for batches 0-2 (needs G1 + mode), overlaps G2
    cudaStreamWaitEvent(s2, eG1, 0);
    cudaStreamWaitEvent(s2, eMode, 0);
    local_attn_kernel<<<3 * HH * (LL / 16), 256, 0, s2>>>(0);
    cudaEventRecord(eL123, s2);

    // s1: gated full path (needs full QKV; stubs when no batch is mode 0)
    cudaStreamWaitEvent(s1, eQkv, 0);
    gemm128<<<dim3(LL / 128, LL / 128, BB * HH), 256, 0, s1>>>(
        qkv_p, QKVD, (long)LL * QKVD, HD,
        qkv_p + DD, QKVD, (long)LL * QKVD, HD,
        sc_p, LL, (long)HH * LL * LL, (long)LL * LL,
        HD, SCALE, nullptr, HH, mode_p);
    softmax_kernel<<<BB * HH * (LL / 64), 256, 0, s1>>>(sparse_w, sparse_b);
    gemm_bt<<<dim3(HD / 64, LL / 64, BB * HH), 256, 0, s1>>>(
        sc_p, LL, (long)HH * LL * LL, (long)LL * LL,
        qkv_p + 2 * DD, QKVD, (long)LL * QKVD, HD,
        attn_p, DD, (long)LL * DD, HD,
        LL, HD, LL, 1.f, nullptr, HH, 0, mode_p);
    cvt_h<<<(ML * DD / 4 + 255) / 256, 256, 0, s1>>>(attn_p, ah_p, ML, mode_p);
    cudaEventRecord(eFull, s1);

    // s2: proj for batches 0-2 (needs L123 [program order] + gated cvt + weights)
    cudaStreamWaitEvent(s2, eFull, 0);
    gemm_mma<<<dim3(DD / 128, 24), 256, GM_DSM, s2>>>(
        ah_p, pwh_p, out, DD, DD, proj_b, 0);
    cudaEventRecord(eP02, s2);

    // main: local attention for batch 3 (needs G2 [program order] + mode)
    cudaStreamWaitEvent(0, eMode, 0);
    local_attn_kernel<<<1 * HH * (LL / 16), 256>>>(3);

    // main: proj for batch 3 (needs L4 [program order] + gated cvt + weights)
    cudaStreamWaitEvent(0, eFull, 0);
    cudaStreamWaitEvent(0, eWp, 0);
    gemm_mma<<<dim3(DD / 128, 8), 256, GM_DSM>>>(
        ah_p, pwh_p, out, DD, DD, proj_b, 3072);

    // join s2 (proj 0-2) back into the capture-origin stream
    cudaStreamWaitEvent(0, eP02, 0);
}

// round 15
// speedup vs baseline: 13.6922x; 1.1386x over previous
#include <cuda_runtime.h>
#include <cuda_bf16.h>
#include <cuda_fp16.h>
#include <cstdint>
#include <math.h>

#define BB 4
#define LL 1024
#define DD 512
#define HH 8
#define HD 64
#define QKVD 1536
#define ML (BB*LL)
#define KH 512               // pure fp16 GEMM: K = 512
#define KTOP 716
#define THRESH 0.05f
#define SCALE 0.125f
#define NEG_INF __int_as_float(0xff800000)

#define NCHUNK (KH / 64)             // 8 chunks of K=64
#define STAGE_BYTES 32768            // A(16KB) + B(16KB) per stage
#define GM_DSM (3 * STAGE_BYTES + 128)

// Scratch (device globals; no allocations allowed)
__device__ float g_qkv[ML * QKVD];
__device__ float g_scores[(size_t)BB * HH * LL * LL];
__device__ float g_attn[ML * DD];
__device__ float g_pw[BB * 3];
__device__ int   g_mode[BB];
__device__ float g_pool_part[128][DD];
// fp16 buffers
__device__ __half g_xh[ML * KH];
__device__ __half g_wqh[QKVD * KH];
__device__ __half g_ah[ML * KH];
__device__ __half g_pwh[DD * KH];

__device__ __forceinline__ uint32_t smem_u32(const void* p) {
    return (uint32_t)__cvta_generic_to_shared(p);
}
__device__ __forceinline__ void cp16(uint32_t dst, const void* src) {
    asm volatile("cp.async.cg.shared.global [%0], [%1], 16;\n" :: "r"(dst), "l"(src));
}
__device__ __forceinline__ uint32_t swz(uint32_t bufbase, int r, int u) {
    return bufbase + r * 128 + ((u ^ (r & 7)) << 4);
}

// ---------------------------------------------------------------------------
// fp32 -> fp16 convert, row-major [M][512]. gate: skip non-mode-0 batches.
// ---------------------------------------------------------------------------
__device__ __forceinline__ void cvt_row4(const float* src, __half* dst, int m, int c)
{
    float4 v = ((const float4*)(src + (size_t)m * DD))[c];
    __half2 h0 = {__float2half_rn(v.x), __float2half_rn(v.y)};
    __half2 h1 = {__float2half_rn(v.z), __float2half_rn(v.w)};
    __half2* d = (__half2*)(dst + (size_t)m * KH + c * 4);
    d[0] = h0; d[1] = h1;
}

__global__ __launch_bounds__(256)
void cvt_h(const float* __restrict__ src, __half* __restrict__ dst,
           int M, const int* __restrict__ gate)
{
    int i = blockIdx.x * 256 + threadIdx.x;
    int total = M * (DD / 4);
    if (i >= total) return;
    int m = i / (DD / 4), c = i % (DD / 4);
    if (gate && gate[m / LL] != 0) return;
    cvt_row4(src, dst, m, c);
}

// Both weight matrices in one launch: qkv_w (QKVD rows) then proj_w (DD rows).
__global__ __launch_bounds__(256)
void cvt_w(const float* __restrict__ wq, const float* __restrict__ wp,
           __half* __restrict__ dwq, __half* __restrict__ dwp)
{
    int i = blockIdx.x * 256 + threadIdx.x;
    int totq = QKVD * (DD / 4);
    int totp = DD * (DD / 4);
    if (i < totq) {
        cvt_row4(wq, dwq, i / (DD / 4), i % (DD / 4));
    } else if (i < totq + totp) {
        int j = i - totq;
        cvt_row4(wp, dwp, j / (DD / 4), j % (DD / 4));
    }
}

// ---------------------------------------------------------------------------
// fp16 NT GEMM via mma.sync m16n8k16, 3-stage cp.async pipeline,
// XOR-swizzled smem, one barrier per K-chunk. m_base allows row-split launches.
// ---------------------------------------------------------------------------
__global__ __launch_bounds__(256, 2)
void gemm_mma(const __half* __restrict__ A2,
              const __half* __restrict__ B2,
              float* __restrict__ C, int ldc, int N,
              const float* __restrict__ bias, int m_base)
{
    extern __shared__ char dsm[];
    uint32_t base = (smem_u32(dsm) + 127) & ~127u;
    int tid = threadIdx.x;
    int warp = tid >> 5, lane = tid & 31;
    int wm = warp >> 1, wn = warp & 1;
    int m0 = m_base + blockIdx.y * 128, n0 = blockIdx.x * 128;
    int m0w = wm * 32, n0w = wn * 64;

    float acc[2][8][4];
#pragma unroll
    for (int a = 0; a < 2; a++)
#pragma unroll
        for (int b = 0; b < 8; b++)
#pragma unroll
            for (int c = 0; c < 4; c++) acc[a][b][c] = 0.f;

    int u = tid & 7, row0 = tid >> 3;

    auto issue = [&](int chunk) {
        int s = chunk % 3;
        uint32_t bA = base + s * STAGE_BYTES;
        uint32_t bB = bA + 16384;
        int k0 = chunk * 64;
#pragma unroll
        for (int p = 0; p < 4; p++) {
            int r = row0 + p * 32;
            cp16(swz(bA, r, u), A2 + (size_t)(m0 + r) * KH + k0 + u * 8);
            cp16(swz(bB, r, u), B2 + (size_t)(n0 + r) * KH + k0 + u * 8);
        }
        asm volatile("cp.async.commit_group;\n");
    };

    issue(0);
    issue(1);

    for (int c = 0; c < NCHUNK; c++) {
        if (c + 2 < NCHUNK) {
            asm volatile("cp.async.wait_group 1;\n");
        } else {
            asm volatile("cp.async.wait_group 0;\n");
        }
        __syncthreads();
        if (c + 2 < NCHUNK) issue(c + 2);

        int s = c % 3;
        uint32_t bA = base + s * STAGE_BYTES;
        uint32_t bB = bA + 16384;
#pragma unroll
        for (int kk = 0; kk < 64; kk += 16) {
            int ub = kk >> 3;
            uint32_t a[2][4];
#pragma unroll
            for (int mt = 0; mt < 2; mt++) {
                int mrow = m0w + mt * 16 + (lane & 15);
                int un = ub + (lane >> 4);
                uint32_t ad = swz(bA, mrow, un);
                asm volatile("ldmatrix.sync.aligned.m8n8.x4.shared.b16 {%0,%1,%2,%3}, [%4];"
                    : "=r"(a[mt][0]), "=r"(a[mt][1]), "=r"(a[mt][2]), "=r"(a[mt][3])
                    : "r"(ad));
            }
            uint32_t bfr[4][4];
#pragma unroll
            for (int g = 0; g < 4; g++) {
                int nrow = n0w + g * 16 + ((lane >> 4) << 3) + (lane & 7);
                int un = ub + ((lane >> 3) & 1);
                uint32_t ad = swz(bB, nrow, un);
                asm volatile("ldmatrix.sync.aligned.m8n8.x4.shared.b16 {%0,%1,%2,%3}, [%4];"
                    : "=r"(bfr[g][0]), "=r"(bfr[g][1]), "=r"(bfr[g][2]), "=r"(bfr[g][3])
                    : "r"(ad));
            }
#pragma unroll
            for (int mt = 0; mt < 2; mt++)
#pragma unroll
                for (int nt = 0; nt < 8; nt++) {
                    int g = nt >> 1, pr = (nt & 1) * 2;
                    asm volatile(
                        "mma.sync.aligned.m16n8k16.row.col.f32.f16.f16.f32 "
                        "{%0,%1,%2,%3}, {%4,%5,%6,%7}, {%8,%9}, {%0,%1,%2,%3};"
                        : "+f"(acc[mt][nt][0]), "+f"(acc[mt][nt][1]),
                          "+f"(acc[mt][nt][2]), "+f"(acc[mt][nt][3])
                        : "r"(a[mt][0]), "r"(a[mt][1]), "r"(a[mt][2]), "r"(a[mt][3]),
                          "r"(bfr[g][pr]), "r"(bfr[g][pr + 1]));
                }
        }
    }

    // epilogue
#pragma unroll
    for (int mt = 0; mt < 2; mt++) {
        int mA = m0 + m0w + mt * 16 + (lane >> 2);
#pragma unroll
        for (int nt = 0; nt < 8; nt++) {
            int n = n0 + n0w + nt * 8 + (lane & 3) * 2;
            if (n >= N) continue;
            float b0 = bias ? bias[n] : 0.f;
            float b1 = bias ? bias[n + 1] : 0.f;
            *(float2*)&C[(size_t)mA * ldc + n] =
                make_float2(acc[mt][nt][0] + b0, acc[mt][nt][1] + b1);
            *(float2*)&C[(size_t)(mA + 8) * ldc + n] =
                make_float2(acc[mt][nt][2] + b0, acc[mt][nt][3] + b1);
        }
    }
}

// ---------------------------------------------------------------------------
// 128x128 fp32 SGEMM (NT) for the gated full-path scores.
// ---------------------------------------------------------------------------
__global__ __launch_bounds__(256)
void gemm128(const float* __restrict__ A, int lda, long sAb, long sAh,
             const float* __restrict__ B, int ldb, long sBb, long sBh,
             float* __restrict__ C, int ldc, long sCb, long sCh,
             int K, float alpha, const float* __restrict__ bias,
             int nh, const int* __restrict__ gate)
{
    __shared__ float As[16][132];
    __shared__ float Bs[16][132];
    int z = blockIdx.z;
    int b = z / nh, h = z % nh;
    if (gate && gate[b] != 0) return;
    A += (size_t)b * sAb + (size_t)h * sAh;
    B += (size_t)b * sBb + (size_t)h * sBh;
    C += (size_t)b * sCb + (size_t)h * sCh;

    int tid = threadIdx.x;
    int tx = tid & 15, ty = tid >> 4;
    int m0 = blockIdx.y * 128, n0 = blockIdx.x * 128;

    float acc[8][8];
#pragma unroll
    for (int i = 0; i < 8; i++)
#pragma unroll
        for (int j = 0; j < 8; j++) acc[i][j] = 0.f;

    for (int k0 = 0; k0 < K; k0 += 16) {
#pragma unroll
        for (int i = 0; i < 8; i++) {
            int idx = tid + i * 256;
            int m = idx >> 4, kk = idx & 15;
            As[kk][m] = A[(size_t)(m0 + m) * lda + k0 + kk];
            Bs[kk][m] = B[(size_t)(n0 + m) * ldb + k0 + kk];
        }
        __syncthreads();
#pragma unroll
        for (int kk = 0; kk < 16; kk++) {
            float4 a0 = *(const float4*)&As[kk][ty * 8];
            float4 a1 = *(const float4*)&As[kk][ty * 8 + 4];
            float4 b0 = *(const float4*)&Bs[kk][tx * 8];
            float4 b1 = *(const float4*)&Bs[kk][tx * 8 + 4];
            float av[8] = {a0.x, a0.y, a0.z, a0.w, a1.x, a1.y, a1.z, a1.w};
            float bv[8] = {b0.x, b0.y, b0.z, b0.w, b1.x, b1.y, b1.z, b1.w};
#pragma unroll
            for (int i = 0; i < 8; i++)
#pragma unroll
                for (int j = 0; j < 8; j++) acc[i][j] += av[i] * bv[j];
        }
        __syncthreads();
    }
#pragma unroll
    for (int i = 0; i < 8; i++) {
        int m = m0 + ty * 8 + i;
        float out[8];
#pragma unroll
        for (int j = 0; j < 8; j++) {
            out[j] = acc[i][j] * alpha;
            if (bias) out[j] += bias[n0 + tx * 8 + j];
        }
        float4* cp = (float4*)&C[(size_t)m * ldc + n0 + tx * 8];
        cp[0] = make_float4(out[0], out[1], out[2], out[3]);
        cp[1] = make_float4(out[4], out[5], out[6], out[7]);
    }
}

// ---------------------------------------------------------------------------
// 64x64 SGEMM (NT/NN) for the gated AV path.
// ---------------------------------------------------------------------------
__global__ __launch_bounds__(256)
void gemm_bt(const float* __restrict__ A, int lda, long sAb, long sAh,
             const float* __restrict__ B, int ldb, long sBb, long sBh,
             float* __restrict__ C, int ldc, long sCb, long sCh,
             int M, int N, int K, float alpha,
             const float* __restrict__ bias, int nh, int bTrans,
             const int* __restrict__ gate)
{
    __shared__ float As[16][65];
    __shared__ float Bs[16][65];
    int z = blockIdx.z;
    int b = z / nh, h = z % nh;
    if (gate && gate[b] != 0) return;
    A += (size_t)b * sAb + (size_t)h * sAh;
    B += (size_t)b * sBb + (size_t)h * sBh;
    C += (size_t)b * sCb + (size_t)h * sCh;

    int tid = threadIdx.x;
    int tx = tid & 15, ty = tid >> 4;
    int m0 = blockIdx.y * 64, n0 = blockIdx.x * 64;

    float acc[4][4];
#pragma unroll
    for (int i = 0; i < 4; i++)
#pragma unroll
        for (int j = 0; j < 4; j++) acc[i][j] = 0.f;

    for (int k0 = 0; k0 < K; k0 += 16) {
#pragma unroll
        for (int i = 0; i < 4; i++) {
            int idx = tid + i * 256;
            int m = idx >> 4, kk = idx & 15;
            As[kk][m] = A[(size_t)(m0 + m) * lda + k0 + kk];
        }
        if (bTrans) {
#pragma unroll
            for (int i = 0; i < 4; i++) {
                int idx = tid + i * 256;
                int n = idx >> 4, kk = idx & 15;
                Bs[kk][n] = B[(size_t)(n0 + n) * ldb + k0 + kk];
            }
        } else {
#pragma unroll
            for (int i = 0; i < 4; i++) {
                int idx = tid + i * 256;
                int n = idx & 63, kk = idx >> 6;
                Bs[kk][n] = B[(size_t)(k0 + kk) * ldb + n0 + n];
            }
        }
        __syncthreads();
#pragma unroll
        for (int kk = 0; kk < 16; kk++) {
            float a[4], bb[4];
#pragma unroll
            for (int i = 0; i < 4; i++) a[i] = As[kk][ty * 4 + i];
#pragma unroll
            for (int j = 0; j < 4; j++) bb[j] = Bs[kk][tx * 4 + j];
#pragma unroll
            for (int i = 0; i < 4; i++)
#pragma unroll
                for (int j = 0; j < 4; j++) acc[i][j] += a[i] * bb[j];
        }
        __syncthreads();
    }
#pragma unroll
    for (int i = 0; i < 4; i++) {
        int m = m0 + ty * 4 + i;
#pragma unroll
        for (int j = 0; j < 4; j++) {
            int n = n0 + tx * 4 + j;
            float v = acc[i][j] * alpha;
            if (bias) v += bias[n];
            C[(size_t)m * ldc + n] = v;
        }
    }
}

// ---------------------------------------------------------------------------
// Pooling stage 1: 128 blocks, each sums 32 rows of one batch.
// ---------------------------------------------------------------------------
__global__ __launch_bounds__(256)
void pool1_kernel(const float* __restrict__ x)
{
    int blk = blockIdx.x;               // 0..127
    int b = blk >> 5, c = blk & 31;
    int tid = threadIdx.x;
    const float2* xp = (const float2*)(x + ((size_t)b * LL + c * 32) * DD) + tid;
    float s0 = 0.f, s1 = 0.f;
    for (int l = 0; l < 32; l++) {
        float2 v = xp[(size_t)l * (DD / 2)];
        s0 += v.x; s1 += v.y;
    }
    g_pool_part[blk][tid * 2]     = s0;
    g_pool_part[blk][tid * 2 + 1] = s1;
}

// ---------------------------------------------------------------------------
__global__ __launch_bounds__(256)
void pattern_kernel(const float* __restrict__ w1, const float* __restrict__ b1,
                    const float* __restrict__ w2, const float* __restrict__ b2,
                    const float* __restrict__ w3, const float* __restrict__ b3,
                    const float* __restrict__ pbias)
{
    int b = blockIdx.x, tid = threadIdx.x;
    int warp = tid >> 5, lane = tid & 31;
    __shared__ float pooled[DD];
    __shared__ float h1[DD];
    __shared__ float h2[DD / 2];
    __shared__ float lg[3];

    for (int d = tid; d < DD; d += 256) {
        float s = 0.f;
#pragma unroll
        for (int c = 0; c < 32; c++) s += g_pool_part[b * 32 + c][d];
        pooled[d] = s * (1.0f / LL);
    }
    __syncthreads();
    for (int i = warp; i < DD; i += 8) {
        const float* wr = w1 + (size_t)i * DD;
        float a = 0.f;
        for (int k = lane; k < DD; k += 32) a += pooled[k] * wr[k];
#pragma unroll
        for (int o = 16; o > 0; o >>= 1) a += __shfl_xor_sync(~0u, a, o);
        if (lane == 0) h1[i] = fmaxf(a + b1[i], 0.f);
    }
    __syncthreads();
    for (int i = warp; i < DD / 2; i += 8) {
        const float* wr = w2 + (size_t)i * DD;
        float a = 0.f;
        for (int k = lane; k < DD; k += 32) a += h1[k] * wr[k];
#pragma unroll
        for (int o = 16; o > 0; o >>= 1) a += __shfl_xor_sync(~0u, a, o);
        if (lane == 0) h2[i] = fmaxf(a + b2[i], 0.f);
    }
    __syncthreads();
    if (warp < 3) {
        const float* wr = w3 + (size_t)warp * (DD / 2);
        float a = 0.f;
        for (int k = lane; k < DD / 2; k += 32) a += h2[k] * wr[k];
#pragma unroll
        for (int o = 16; o > 0; o >>= 1) a += __shfl_xor_sync(~0u, a, o);
        if (lane == 0) lg[warp] = (a + b3[warp] + pbias[warp]) / 0.3f;
    }
    __syncthreads();
    if (tid == 0) {
        float m = fmaxf(lg[0], fmaxf(lg[1], lg[2]));
        float e0 = expf(lg[0] - m), e1 = expf(lg[1] - m), e2 = expf(lg[2] - m);
        float inv = 1.f / (e0 + e1 + e2);
        float p0 = e0 * inv, p1 = e1 * inv, p2 = e2 * inv;
        g_pw[b * 3 + 0] = p0;
        g_pw[b * 3 + 1] = p1;
        g_pw[b * 3 + 2] = p2;
        bool A00 = p1 > THRESH;
        bool A01 = (p1 + p2) > THRESH;
        bool A10 = (p0 + p1) > THRESH;
        bool A11 = ((p0 + p1) + p2) > THRESH;
        bool need_sparse = (A00 != A01) || (A10 != A11);
        int mode;
        if (need_sparse || A00) mode = 0;
        else if (A10)           mode = 1;
        else                    mode = 2;
        g_mode[b] = mode;
    }
}

// ---------------------------------------------------------------------------
__device__ __forceinline__ void write_h(int m, int col, float v)
{
    g_ah[(size_t)m * KH + col] = __float2half_rn(v);
}

// ---------------------------------------------------------------------------
// Local-window fused attention (mode 1) + all-masked fallback (mode 2).
// ---------------------------------------------------------------------------
__global__ __launch_bounds__(256)
void local_attn_kernel(int b_off)
{
    __shared__ float ksh[48][65];
    __shared__ float vsh[48][65];
    __shared__ float qsh[16][64];
    __shared__ float psh[16][33];

    int blk = blockIdx.x;
    int b = b_off + (blk >> 9);
    int h = (blk >> 6) & 7;
    int q0 = (blk & 63) * 16;
    int mode = g_mode[b];
    if (mode == 0) return;
    int tid = threadIdx.x;
    const float* base = g_qkv + (size_t)b * LL * QKVD + h * HD;

    if (mode == 2) {
        const float* v0 = base + 2 * DD;
#pragma unroll
        for (int i = 0; i < 4; i++) {
            int idx = tid + i * 256;
            int r = idx >> 6, d = idx & 63;
            write_h(b * LL + q0 + r, h * HD + d, v0[d]);
        }
        return;
    }

    int kb0 = max(q0 - 16, 0);
    int kend = min(q0 + 15 + 16, LL - 1);
    int klen = kend - kb0 + 1;

    for (int i = tid; i < klen * 64; i += 256) {
        int jj = i >> 6, d = i & 63;
        const float* src = base + (size_t)(kb0 + jj) * QKVD;
        ksh[jj][d] = src[DD + d];
        vsh[jj][d] = src[2 * DD + d];
    }
#pragma unroll
    for (int i = 0; i < 4; i++) {
        int idx = tid + i * 256;
        int r = idx >> 6, d = idx & 63;
        qsh[r][d] = base[(size_t)(q0 + r) * QKVD + d];
    }
    __syncthreads();

    int warp = tid >> 5, lane = tid & 31;
#pragma unroll
    for (int rr = 0; rr < 2; rr++) {
        int r = warp * 2 + rr;
        int q = q0 + r;
        int w0 = max(q - 16, 0), w1 = min(q + 16, LL - 1);
        int cnt = w1 - w0 + 1;
        int off = w0 - kb0;

        float s0 = NEG_INF, s1 = NEG_INF;
        if (lane < cnt) {
            float acc = 0.f;
#pragma unroll
            for (int d = 0; d < 64; d++) acc += qsh[r][d] * ksh[off + lane][d];
            s0 = acc * SCALE;
        }
        if (lane + 32 < cnt) {
            float acc = 0.f;
#pragma unroll
            for (int d = 0; d < 64; d++) acc += qsh[r][d] * ksh[off + lane + 32][d];
            s1 = acc * SCALE;
        }
        float m = fmaxf(s0, s1);
#pragma unroll
        for (int o = 16; o > 0; o >>= 1) m = fmaxf(m, __shfl_xor_sync(~0u, m, o));
        float e0 = (lane < cnt) ? __expf(s0 - m) : 0.f;
        float e1 = (lane + 32 < cnt) ? __expf(s1 - m) : 0.f;
        float sum = e0 + e1;
#pragma unroll
        for (int o = 16; o > 0; o >>= 1) sum += __shfl_xor_sync(~0u, sum, o);
        float inv = 1.f / sum;
        if (lane < cnt) psh[r][lane] = e0 * inv;
        if (lane + 32 < cnt) psh[r][lane + 32] = e1 * inv;
        __syncwarp();

        float o0 = 0.f, o1 = 0.f;
        for (int jj = 0; jj < cnt; jj++) {
            float p = psh[r][jj];
            o0 += p * vsh[off + jj][lane];
            o1 += p * vsh[off + jj][lane + 32];
        }
        int m_out = b * LL + q;
        write_h(m_out, h * HD + lane, o0);
        write_h(m_out, h * HD + lane + 32, o1);
    }
}

// ---------------------------------------------------------------------------
// Full-path mask + softmax (mode 0 only). 64 rows per block.
// ---------------------------------------------------------------------------
__device__ __forceinline__ unsigned fkey(float f) {
    unsigned u = __float_as_uint(f);
    return (u & 0x80000000u) ? ~u : (u | 0x80000000u);
}

__global__ __launch_bounds__(256)
void softmax_kernel(const float* __restrict__ sparse_w,
                    const float* __restrict__ sparse_b)
{
    __shared__ float s[LL];
    __shared__ float red[256];
    __shared__ unsigned hist[256];
    __shared__ unsigned sel_prefix, sel_k;
    __shared__ float mx_sh;

    int grp = blockIdx.x;
    int z = grp >> 4;
    int b = z >> 3, h = z & 7;
    if (g_mode[b] != 0) return;
    int q_base = (grp & 15) * 64;
    int tid = threadIdx.x;

    float p0 = g_pw[b * 3 + 0];
    float p1 = g_pw[b * 3 + 1];
    float p2 = g_pw[b * 3 + 2];
    bool A00 = p1 > THRESH;
    bool A01 = (p1 + p2) > THRESH;
    bool A10 = (p0 + p1) > THRESH;
    bool A11 = ((p0 + p1) + p2) > THRESH;
    bool need_sparse = (A00 != A01) || (A10 != A11);
    float w_h = sparse_w[h], b_h = sparse_b[h];

    for (int r = 0; r < 64; r++) {
        int q = q_base + r;
        float* srow = g_scores + ((size_t)z << 20) + ((size_t)q << 10);
        ((float4*)s)[tid] = ((const float4*)srow)[tid];
        __syncthreads();

        unsigned tu = 0u;
        if (need_sparse) {
            if (tid == 0) { sel_prefix = 0u; sel_k = KTOP; }
            __syncthreads();
            for (int shift = 24; shift >= 0; shift -= 8) {
                hist[tid] = 0u;
                __syncthreads();
                unsigned pref = sel_prefix;
                unsigned hm = (shift == 24) ? 0u : (0xFFFFFFFFu << (shift + 8));
                for (int j = tid; j < LL; j += 256) {
                    float v = __fadd_rn(__fmul_rn(s[j], w_h), b_h);
                    unsigned u = fkey(v);
                    if ((u & hm) == pref) atomicAdd(&hist[(u >> shift) & 255u], 1u);
                }
                __syncthreads();
                if (tid == 0) {
                    unsigned k = sel_k, cum = 0;
                    for (int dgt = 255; dgt >= 0; --dgt) {
                        unsigned c = hist[dgt];
                        if (cum + c >= k) {
                            sel_prefix = pref | ((unsigned)dgt << shift);
                            sel_k = k - cum;
                            break;
                        }
                        cum += c;
                    }
                }
                __syncthreads();
            }
            tu = sel_prefix;
            __syncthreads();
        }

        float v[4];
        float lm = NEG_INF;
#pragma unroll
        for (int i = 0; i < 4; i++) {
            int j = tid * 4 + i;
            float sv = s[j];
            bool lf = (abs(q - j) <= 16);
            bool allow;
            if (need_sparse) {
                float s2 = __fadd_rn(__fmul_rn(sv, w_h), b_h);
                float sf = (fkey(s2) >= tu) ? 1.f : 0.f;
                float comb = (p0 * (lf ? 1.f : 0.f) + p1) + p2 * sf;
                allow = comb > THRESH;
            } else {
                allow = lf ? A10 : A00;
            }
            v[i] = allow ? sv : NEG_INF;
            lm = fmaxf(lm, v[i]);
        }
        red[tid] = lm; __syncthreads();
        for (int o = 128; o > 0; o >>= 1) {
            if (tid < o) red[tid] = fmaxf(red[tid], red[tid + o]);
            __syncthreads();
        }
        if (tid == 0) mx_sh = red[0];
        __syncthreads();
        float mx = mx_sh;

        if (mx == NEG_INF) {
            float4 o;
            o.x = (tid == 0) ? 1.f : 0.f; o.y = 0.f; o.z = 0.f; o.w = 0.f;
            ((float4*)srow)[tid] = o;
            __syncthreads();
            continue;
        }

        float ls = 0.f;
#pragma unroll
        for (int i = 0; i < 4; i++) {
            v[i] = __expf(v[i] - mx);
            ls += v[i];
        }
        red[tid] = ls; __syncthreads();
        for (int o = 128; o > 0; o >>= 1) {
            if (tid < o) red[tid] += red[tid + o];
            __syncthreads();
        }
        if (tid == 0) mx_sh = 1.f / red[0];
        __syncthreads();
        float inv = mx_sh;
        float4 o;
        o.x = v[0] * inv; o.y = v[1] * inv; o.z = v[2] * inv; o.w = v[3] * inv;
        ((float4*)srow)[tid] = o;
        __syncthreads();
    }
}

// ---------------------------------------------------------------------------
extern "C" void kernel_launch(void* const* d_in, const int* in_sizes, int n_in,
                              void* d_out, int out_size)
{
    const float* x        = (const float*)d_in[0];
    const float* qkv_w    = (const float*)d_in[1];
    const float* proj_w   = (const float*)d_in[2];
    const float* proj_b   = (const float*)d_in[3];
    const float* ps_w1    = (const float*)d_in[4];
    const float* ps_b1    = (const float*)d_in[5];
    const float* ps_w2    = (const float*)d_in[6];
    const float* ps_b2    = (const float*)d_in[7];
    const float* ps_w3    = (const float*)d_in[8];
    const float* ps_b3    = (const float*)d_in[9];
    const float* pbias    = (const float*)d_in[10];
    const float* sparse_w = (const float*)d_in[11];
    const float* sparse_b = (const float*)d_in[12];
    float* out = (float*)d_out;

    float *qkv_p, *sc_p, *attn_p;
    int *mode_p;
    __half *xh_p, *wqh_p, *ah_p, *pwh_p;
    cudaGetSymbolAddress((void**)&qkv_p,  g_qkv);
    cudaGetSymbolAddress((void**)&sc_p,   g_scores);
    cudaGetSymbolAddress((void**)&attn_p, g_attn);
    cudaGetSymbolAddress((void**)&mode_p, g_mode);
    cudaGetSymbolAddress((void**)&xh_p,   g_xh);
    cudaGetSymbolAddress((void**)&wqh_p,  g_wqh);
    cudaGetSymbolAddress((void**)&ah_p,   g_ah);
    cudaGetSymbolAddress((void**)&pwh_p,  g_pwh);

    // One-time setup (first call is the uncaptured correctness run)
    static cudaStream_t s1 = nullptr, s2 = nullptr;
    static cudaEvent_t eFork = nullptr, eMode = nullptr, eW = nullptr,
                       eG1 = nullptr, eQkv = nullptr, eFull = nullptr,
                       eL123 = nullptr, eP02 = nullptr;
    if (!s1) {
        cudaStreamCreateWithFlags(&s1, cudaStreamNonBlocking);
        cudaStreamCreateWithFlags(&s2, cudaStreamNonBlocking);
        cudaEventCreateWithFlags(&eFork, cudaEventDisableTiming);
        cudaEventCreateWithFlags(&eMode, cudaEventDisableTiming);
        cudaEventCreateWithFlags(&eW,    cudaEventDisableTiming);
        cudaEventCreateWithFlags(&eG1,   cudaEventDisableTiming);
        cudaEventCreateWithFlags(&eQkv,  cudaEventDisableTiming);
        cudaEventCreateWithFlags(&eFull, cudaEventDisableTiming);
        cudaEventCreateWithFlags(&eL123, cudaEventDisableTiming);
        cudaEventCreateWithFlags(&eP02,  cudaEventDisableTiming);
        cudaFuncSetAttribute(gemm_mma, cudaFuncAttributeMaxDynamicSharedMemorySize, GM_DSM);
    }

    // Fork side streams off the main (capture-origin) stream
    cudaEventRecord(eFork, 0);
    cudaStreamWaitEvent(s1, eFork, 0);
    cudaStreamWaitEvent(s2, eFork, 0);

    // s1: pattern-selector chain -> g_mode
    pool1_kernel<<<128, 256, 0, s1>>>(x);
    pattern_kernel<<<BB, 256, 0, s1>>>(ps_w1, ps_b1, ps_w2, ps_b2, ps_w3, ps_b3, pbias);
    cudaEventRecord(eMode, s1);

    // s2: both weight conversions in one launch
    cvt_w<<<((QKVD + DD) * (DD / 4) + 255) / 256, 256, 0, s2>>>(
        qkv_w, proj_w, wqh_p, pwh_p);
    cudaEventRecord(eW, s2);

    // main: x conversion, then QKV GEMM split:
    // G1 = batches 0-2 (288 CTAs ~ one wave), G2 = batch 3 (96 CTAs).
    cvt_h<<<(ML * DD / 4 + 255) / 256, 256>>>(x, xh_p, ML, nullptr);
    cudaStreamWaitEvent(0, eW, 0);
    gemm_mma<<<dim3(QKVD / 128, 24), 256, GM_DSM>>>(
        xh_p, wqh_p, qkv_p, QKVD, QKVD, nullptr, 0);
    cudaEventRecord(eG1, 0);
    gemm_mma<<<dim3(QKVD / 128, 8), 256, GM_DSM>>>(
        xh_p, wqh_p, qkv_p, QKVD, QKVD, nullptr, 3072);
    cudaEventRecord(eQkv, 0);

    // s2: local attention for batches 0-2 (needs G1 + mode), overlaps G2
    cudaStreamWaitEvent(s2, eG1, 0);
    cudaStreamWaitEvent(s2, eMode, 0);
    local_attn_kernel<<<3 * HH * (LL / 16), 256, 0, s2>>>(0);
    cudaEventRecord(eL123, s2);

    // s1: gated full path (needs full QKV; stubs when no batch is mode 0)
    cudaStreamWaitEvent(s1, eQkv, 0);
    gemm128<<<dim3(LL / 128, LL / 128, BB * HH), 256, 0, s1>>>(
        qkv_p, QKVD, (long)LL * QKVD, HD,
        qkv_p + DD, QKVD, (long)LL * QKVD, HD,
        sc_p, LL, (long)HH * LL * LL, (long)LL * LL,
        HD, SCALE, nullptr, HH, mode_p);
    softmax_kernel<<<BB * HH * (LL / 64), 256, 0, s1>>>(sparse_w, sparse_b);
    gemm_bt<<<dim3(HD / 64, LL / 64, BB * HH), 256, 0, s1>>>(
        sc_p, LL, (long)HH * LL * LL, (long)LL * LL,
        qkv_p + 2 * DD, QKVD, (long)LL * QKVD, HD,
        attn_p, DD, (long)LL * DD, HD,
        LL, HD, LL, 1.f, nullptr, HH, 0, mode_p);
    cvt_h<<<(ML * DD / 4 + 255) / 256, 256, 0, s1>>>(attn_p, ah_p, ML, mode_p);
    cudaEventRecord(eFull, s1);

    // s2: proj for batches 0-2 (needs L123 [program order] + gated cvt + weights)
    cudaStreamWaitEvent(s2, eFull, 0);
    gemm_mma<<<dim3(DD / 128, 24), 256, GM_DSM, s2>>>(
        ah_p, pwh_p, out, DD, DD, proj_b, 0);
    cudaEventRecord(eP02, s2);

    // main: local attention for batch 3 (needs G2 [program order] + mode)
    cudaStreamWaitEvent(0, eMode, 0);
    local_attn_kernel<<<1 * HH * (LL / 16), 256>>>(3);

    // main: proj for batch 3 (needs L4 [program order] + gated cvt + weights)
    cudaStreamWaitEvent(0, eFull, 0);
    gemm_mma<<<dim3(DD / 128, 8), 256, GM_DSM>>>(
        ah_p, pwh_p, out, DD, DD, proj_b, 3072);

    // join s2 (proj 0-2) back into the capture-origin stream
    cudaStreamWaitEvent(0, eP02, 0);
}